// round 1
// baseline (speedup 1.0000x reference)
#include <cuda_runtime.h>
#include <math.h>

#define AA 400
#define BB 64
#define II 50
#define HH 192
#define OO 3
#define AD 128
#define NHD 8
#define HDD 16
#define EPSF 1e-5f

// ---------------- scratch (device globals; no allocation allowed) ----------------
__device__ float g_xhat[BB * II];
__device__ float g_h1[AA * BB * HH];
__device__ float g_h2[AA * BB * HH];
__device__ float g_h3[AA * BB * HH];
__device__ float g_y [AA * BB * HH];
__device__ float g_q[BB * NHD * AA * HDD];   // [b, h, a, d]
__device__ float g_k[BB * NHD * AA * HDD];
__device__ float g_v[BB * NHD * AA * HDD];
__device__ float g_o[BB * NHD * AA * HDD];

__device__ __forceinline__ float gelu_exact(float v) {
    return 0.5f * v * (1.0f + erff(v * 0.70710678118654752440f));
}

__device__ __forceinline__ float warp_sum(float v) {
    #pragma unroll
    for (int o = 16; o > 0; o >>= 1) v += __shfl_xor_sync(0xffffffffu, v, o);
    return v;
}

// ---------------- K0: shared input LayerNorm stats (per batch row) ----------------
__global__ void k0_xhat(const float* __restrict__ x) {
    int b = threadIdx.x;
    if (b >= BB) return;
    float s = 0.f;
    #pragma unroll
    for (int i = 0; i < II; i++) s += x[b * II + i];
    float mu = s * (1.0f / II);
    float vv = 0.f;
    #pragma unroll
    for (int i = 0; i < II; i++) { float d = x[b * II + i] - mu; vv += d * d; }
    float rinv = rsqrtf(vv * (1.0f / II) + EPSF);
    #pragma unroll
    for (int i = 0; i < II; i++) g_xhat[b * II + i] = (x[b * II + i] - mu) * rinv;
}

// ---------------- K1: per-agent layer 1 (gelu path + skip path) ----------------
// h1 = gelu(xn@W1 + b1) + xn@Ws1 + bs1,  xn[b,i] = xhat[b,i]*g[a,i] + beta[a,i]
__global__ void k1_layer1(const float* __restrict__ ling, const float* __restrict__ linb,
                          const float* __restrict__ W1,  const float* __restrict__ b1,
                          const float* __restrict__ Ws1, const float* __restrict__ bs1) {
    int a = blockIdx.x;
    extern __shared__ float sm[];
    float* xn  = sm;                 // BB*II
    float* w1s = sm + BB * II;       // II*HH
    float* w2s = w1s + II * HH;      // II*HH
    int tid = threadIdx.x;           // 512

    for (int idx = tid; idx < BB * II; idx += 512) {
        int i = idx % II;
        xn[idx] = g_xhat[idx] * ling[a * II + i] + linb[a * II + i];
    }
    for (int idx = tid; idx < II * HH; idx += 512) {
        w1s[idx] = W1 [a * II * HH + idx];
        w2s[idx] = Ws1[a * II * HH + idx];
    }
    __syncthreads();

    int hg = tid & 31, bg = tid >> 5;
    int b0 = bg * 4;
    float accA[4][6] = {}, accB[4][6] = {};

    #pragma unroll 2
    for (int k = 0; k < II; k++) {
        float xv[4];
        #pragma unroll
        for (int tb = 0; tb < 4; tb++) xv[tb] = xn[(b0 + tb) * II + k];
        float w1v[6], w2v[6];
        #pragma unroll
        for (int th = 0; th < 6; th++) {
            w1v[th] = w1s[k * HH + hg + 32 * th];
            w2v[th] = w2s[k * HH + hg + 32 * th];
        }
        #pragma unroll
        for (int tb = 0; tb < 4; tb++)
            #pragma unroll
            for (int th = 0; th < 6; th++) {
                accA[tb][th] = fmaf(xv[tb], w1v[th], accA[tb][th]);
                accB[tb][th] = fmaf(xv[tb], w2v[th], accB[tb][th]);
            }
    }

    #pragma unroll
    for (int tb = 0; tb < 4; tb++)
        #pragma unroll
        for (int th = 0; th < 6; th++) {
            int h = hg + 32 * th, b = b0 + tb;
            float va = accA[tb][th] + b1 [a * HH + h];
            float vb = accB[tb][th] + bs1[a * HH + h];
            g_h1[(a * BB + b) * HH + h] = gelu_exact(va) + vb;
        }
}

// ---------------- K2: per-agent layer 2 ----------------
__global__ void k2_layer2(const float* __restrict__ W2,  const float* __restrict__ b2,
                          const float* __restrict__ Ws2, const float* __restrict__ bs2) {
    int a = blockIdx.x;
    extern __shared__ float sm[];
    float* hin = sm;               // BB*HH
    float* wc1 = sm + BB * HH;     // 32*HH
    float* wc2 = wc1 + 32 * HH;    // 32*HH
    int tid = threadIdx.x;

    const float* src = g_h1 + a * BB * HH;
    for (int idx = tid; idx < BB * HH; idx += 512) hin[idx] = src[idx];

    int hg = tid & 31, bg = tid >> 5;
    int b0 = bg * 4;
    float accA[4][6] = {}, accB[4][6] = {};

    for (int kc = 0; kc < HH; kc += 32) {
        __syncthreads();
        const float* wp  = W2  + a * HH * HH + kc * HH;
        const float* wsp = Ws2 + a * HH * HH + kc * HH;
        for (int idx = tid; idx < 32 * HH; idx += 512) { wc1[idx] = wp[idx]; wc2[idx] = wsp[idx]; }
        __syncthreads();
        #pragma unroll 4
        for (int k = 0; k < 32; k++) {
            float xv[4];
            #pragma unroll
            for (int tb = 0; tb < 4; tb++) xv[tb] = hin[(b0 + tb) * HH + kc + k];
            float w1v[6], w2v[6];
            #pragma unroll
            for (int th = 0; th < 6; th++) {
                w1v[th] = wc1[k * HH + hg + 32 * th];
                w2v[th] = wc2[k * HH + hg + 32 * th];
            }
            #pragma unroll
            for (int tb = 0; tb < 4; tb++)
                #pragma unroll
                for (int th = 0; th < 6; th++) {
                    accA[tb][th] = fmaf(xv[tb], w1v[th], accA[tb][th]);
                    accB[tb][th] = fmaf(xv[tb], w2v[th], accB[tb][th]);
                }
        }
    }

    #pragma unroll
    for (int tb = 0; tb < 4; tb++)
        #pragma unroll
        for (int th = 0; th < 6; th++) {
            int h = hg + 32 * th, b = b0 + tb;
            float va = accA[tb][th] + b2 [a * HH + h];
            float vb = accB[tb][th] + bs2[a * HH + h];
            g_h2[(a * BB + b) * HH + h] = gelu_exact(va) + vb;
        }
}

// ---------------- K3: per-agent layer 3 + LN(h3) + LN(y) ----------------
__global__ void k3_layer3(const float* __restrict__ W3,   const float* __restrict__ b3v,
                          const float* __restrict__ lhg,  const float* __restrict__ lhb,
                          const float* __restrict__ alng, const float* __restrict__ alnb) {
    int a = blockIdx.x;
    extern __shared__ float sm[];
    float* hin = sm;               // BB*HH
    float* wch = sm + BB * HH;     // 32*HH
    float* tbf = wch + 32 * HH;    // BB*HH
    int tid = threadIdx.x;

    const float* src = g_h2 + a * BB * HH;
    for (int idx = tid; idx < BB * HH; idx += 512) hin[idx] = src[idx];

    int hg = tid & 31, bg = tid >> 5;
    int b0 = bg * 4;
    float acc[4][6] = {};

    for (int kc = 0; kc < HH; kc += 32) {
        __syncthreads();
        const float* wp = W3 + a * HH * HH + kc * HH;
        for (int idx = tid; idx < 32 * HH; idx += 512) wch[idx] = wp[idx];
        __syncthreads();
        #pragma unroll 4
        for (int k = 0; k < 32; k++) {
            float xv[4];
            #pragma unroll
            for (int tb = 0; tb < 4; tb++) xv[tb] = hin[(b0 + tb) * HH + kc + k];
            float wv[6];
            #pragma unroll
            for (int th = 0; th < 6; th++) wv[th] = wch[k * HH + hg + 32 * th];
            #pragma unroll
            for (int tb = 0; tb < 4; tb++)
                #pragma unroll
                for (int th = 0; th < 6; th++)
                    acc[tb][th] = fmaf(xv[tb], wv[th], acc[tb][th]);
        }
    }

    // t = h2 + h2@W3 + b3
    #pragma unroll
    for (int tb = 0; tb < 4; tb++)
        #pragma unroll
        for (int th = 0; th < 6; th++) {
            int h = hg + 32 * th, b = b0 + tb;
            tbf[b * HH + h] = hin[b * HH + h] + acc[tb][th] + b3v[a * HH + h];
        }
    __syncthreads();

    // chained LayerNorms, one warp per row group
    int wid = tid >> 5, lane = tid & 31;
    for (int r = wid; r < BB; r += 16) {
        float v[6];
        #pragma unroll
        for (int u = 0; u < 6; u++) v[u] = tbf[r * HH + u * 32 + lane];
        float s = 0.f;
        #pragma unroll
        for (int u = 0; u < 6; u++) s += v[u];
        s = warp_sum(s);
        float mu = s * (1.0f / HH);
        float ss = 0.f;
        #pragma unroll
        for (int u = 0; u < 6; u++) { float d = v[u] - mu; ss += d * d; }
        ss = warp_sum(ss);
        float rinv = rsqrtf(ss * (1.0f / HH) + EPSF);

        float h3v[6];
        float s2 = 0.f;
        #pragma unroll
        for (int u = 0; u < 6; u++) {
            int i = u * 32 + lane;
            h3v[u] = (v[u] - mu) * rinv * lhg[a * HH + i] + lhb[a * HH + i];
            g_h3[(a * BB + r) * HH + i] = h3v[u];
            s2 += h3v[u];
        }
        s2 = warp_sum(s2);
        float mu2 = s2 * (1.0f / HH);
        float ss2 = 0.f;
        #pragma unroll
        for (int u = 0; u < 6; u++) { float d = h3v[u] - mu2; ss2 += d * d; }
        ss2 = warp_sum(ss2);
        float rinv2 = rsqrtf(ss2 * (1.0f / HH) + EPSF);
        #pragma unroll
        for (int u = 0; u < 6; u++) {
            int i = u * 32 + lane;
            g_y[(a * BB + r) * HH + i] = (h3v[u] - mu2) * rinv2 * alng[i] + alnb[i];
        }
    }
}

// ---------------- K4: fused QKV projection (N=384) + transpose to [b,h,a,d] ----------------
__global__ void k4_qkv(const float* __restrict__ Wq, const float* __restrict__ bq,
                       const float* __restrict__ Wk, const float* __restrict__ bk,
                       const float* __restrict__ Wv, const float* __restrict__ bv) {
    int a = blockIdx.x;
    extern __shared__ float sm[];
    float* ys  = sm;              // BB*HH
    float* wch = sm + BB * HH;    // 16*384
    int tid = threadIdx.x;

    const float* src = g_y + a * BB * HH;
    for (int idx = tid; idx < BB * HH; idx += 512) ys[idx] = src[idx];

    int ng = tid & 31, bg = tid >> 5;
    int b0 = bg * 4;
    float acc[4][12] = {};

    for (int kc = 0; kc < HH; kc += 16) {
        __syncthreads();
        for (int idx = tid; idx < 16 * 384; idx += 512) {
            int k = idx / 384, n = idx % 384;
            int kk = kc + k;
            float w;
            if (n < 128)      w = Wq[kk * AD + n];
            else if (n < 256) w = Wk[kk * AD + n - 128];
            else              w = Wv[kk * AD + n - 256];
            wch[idx] = w;
        }
        __syncthreads();
        #pragma unroll 4
        for (int k = 0; k < 16; k++) {
            float xv[4];
            #pragma unroll
            for (int tb = 0; tb < 4; tb++) xv[tb] = ys[(b0 + tb) * HH + kc + k];
            float wv[12];
            #pragma unroll
            for (int tn = 0; tn < 12; tn++) wv[tn] = wch[k * 384 + ng + 32 * tn];
            #pragma unroll
            for (int tb = 0; tb < 4; tb++)
                #pragma unroll
                for (int tn = 0; tn < 12; tn++)
                    acc[tb][tn] = fmaf(xv[tb], wv[tn], acc[tb][tn]);
        }
    }

    #pragma unroll
    for (int tb = 0; tb < 4; tb++)
        #pragma unroll
        for (int tn = 0; tn < 12; tn++) {
            int n = ng + 32 * tn, b = b0 + tb;
            float val = acc[tb][tn];
            float* dst;
            int c;
            if (n < 128)      { val += bq[n];       c = n;       dst = g_q; }
            else if (n < 256) { val += bk[n - 128]; c = n - 128; dst = g_k; }
            else              { val += bv[n - 256]; c = n - 256; dst = g_v; }
            dst[(((b * NHD) + (c >> 4)) * AA + a) * HDD + (c & 15)] = val;
        }
}

// ---------------- K5: cross-agent attention, one block per (b, head) ----------------
__global__ void k5_attn() {
    int bh = blockIdx.x;                 // b*NHD + h
    extern __shared__ float sm[];
    float* ks = sm;                      // AA*HDD
    float* vs = sm + AA * HDD;           // AA*HDD
    int tid = threadIdx.x;               // 416

    const float* kg = g_k + bh * AA * HDD;
    const float* vg = g_v + bh * AA * HDD;
    for (int idx = tid; idx < AA * HDD; idx += blockDim.x) { ks[idx] = kg[idx]; vs[idx] = vg[idx]; }
    __syncthreads();

    if (tid < AA) {
        const float4* qp = (const float4*)(g_q + (bh * AA + tid) * HDD);
        float4 q0 = qp[0], q1 = qp[1], q2 = qp[2], q3 = qp[3];
        const float4* kp = (const float4*)ks;
        const float4* vp = (const float4*)vs;

        float m = -3.0e38f, l = 0.f;
        float4 a0 = make_float4(0,0,0,0), a1 = a0, a2 = a0, a3 = a0;

        for (int j = 0; j < AA; j++) {
            float4 kk0 = kp[j*4+0], kk1 = kp[j*4+1], kk2 = kp[j*4+2], kk3 = kp[j*4+3];
            float s = q0.x*kk0.x + q0.y*kk0.y + q0.z*kk0.z + q0.w*kk0.w
                    + q1.x*kk1.x + q1.y*kk1.y + q1.z*kk1.z + q1.w*kk1.w
                    + q2.x*kk2.x + q2.y*kk2.y + q2.z*kk2.z + q2.w*kk2.w
                    + q3.x*kk3.x + q3.y*kk3.y + q3.z*kk3.z + q3.w*kk3.w;
            s *= 0.25f;
            if (s > m) {
                float c = __expf(m - s);
                l *= c;
                a0.x *= c; a0.y *= c; a0.z *= c; a0.w *= c;
                a1.x *= c; a1.y *= c; a1.z *= c; a1.w *= c;
                a2.x *= c; a2.y *= c; a2.z *= c; a2.w *= c;
                a3.x *= c; a3.y *= c; a3.z *= c; a3.w *= c;
                m = s;
            }
            float p = __expf(s - m);
            l += p;
            float4 vv0 = vp[j*4+0], vv1 = vp[j*4+1], vv2 = vp[j*4+2], vv3 = vp[j*4+3];
            a0.x = fmaf(p, vv0.x, a0.x); a0.y = fmaf(p, vv0.y, a0.y); a0.z = fmaf(p, vv0.z, a0.z); a0.w = fmaf(p, vv0.w, a0.w);
            a1.x = fmaf(p, vv1.x, a1.x); a1.y = fmaf(p, vv1.y, a1.y); a1.z = fmaf(p, vv1.z, a1.z); a1.w = fmaf(p, vv1.w, a1.w);
            a2.x = fmaf(p, vv2.x, a2.x); a2.y = fmaf(p, vv2.y, a2.y); a2.z = fmaf(p, vv2.z, a2.z); a2.w = fmaf(p, vv2.w, a2.w);
            a3.x = fmaf(p, vv3.x, a3.x); a3.y = fmaf(p, vv3.y, a3.y); a3.z = fmaf(p, vv3.z, a3.z); a3.w = fmaf(p, vv3.w, a3.w);
        }
        float inv = 1.0f / l;
        float4* op = (float4*)(g_o + (bh * AA + tid) * HDD);
        op[0] = make_float4(a0.x*inv, a0.y*inv, a0.z*inv, a0.w*inv);
        op[1] = make_float4(a1.x*inv, a1.y*inv, a1.z*inv, a1.w*inv);
        op[2] = make_float4(a2.x*inv, a2.y*inv, a2.z*inv, a2.w*inv);
        op[3] = make_float4(a3.x*inv, a3.y*inv, a3.z*inv, a3.w*inv);
    }
}

// ---------------- K6: O-proj + residual + per-agent output head ----------------
__global__ void k6_out(const float* __restrict__ Wo,   const float* __restrict__ bo,
                       const float* __restrict__ Wout, const float* __restrict__ bout,
                       float* __restrict__ out) {
    int a = blockIdx.x;
    extern __shared__ float sm[];
    float* os  = sm;               // BB*AD
    float* wch = sm + BB * AD;     // 32*HH
    float* att = wch + 32 * HH;    // BB*HH
    int tid = threadIdx.x;

    for (int idx = tid; idx < BB * AD; idx += 512) {
        int b = idx >> 7, c = idx & 127;
        os[idx] = g_o[(((b * NHD) + (c >> 4)) * AA + a) * HDD + (c & 15)];
    }

    int hg = tid & 31, bg = tid >> 5;
    int b0 = bg * 4;
    float acc[4][6] = {};

    for (int kc = 0; kc < AD; kc += 32) {
        __syncthreads();
        const float* wp = Wo + kc * HH;
        for (int idx = tid; idx < 32 * HH; idx += 512) wch[idx] = wp[idx];
        __syncthreads();
        #pragma unroll 4
        for (int k = 0; k < 32; k++) {
            float xv[4];
            #pragma unroll
            for (int tb = 0; tb < 4; tb++) xv[tb] = os[(b0 + tb) * AD + kc + k];
            float wv[6];
            #pragma unroll
            for (int th = 0; th < 6; th++) wv[th] = wch[k * HH + hg + 32 * th];
            #pragma unroll
            for (int tb = 0; tb < 4; tb++)
                #pragma unroll
                for (int th = 0; th < 6; th++)
                    acc[tb][th] = fmaf(xv[tb], wv[th], acc[tb][th]);
        }
    }

    #pragma unroll
    for (int tb = 0; tb < 4; tb++)
        #pragma unroll
        for (int th = 0; th < 6; th++) {
            int h = hg + 32 * th, b = b0 + tb;
            att[b * HH + h] = g_h3[(a * BB + b) * HH + h] + acc[tb][th] + bo[h];
        }
    __syncthreads();

    if (tid < BB * OO) {
        int b = tid / OO, oo = tid % OO;
        float s = bout[a * OO + oo];
        #pragma unroll 4
        for (int k = 0; k < HH; k++)
            s = fmaf(att[b * HH + k], Wout[(a * HH + k) * OO + oo], s);
        out[(a * BB + b) * OO + oo] = s;
    }
}

// ---------------- host launcher ----------------
extern "C" void kernel_launch(void* const* d_in, const int* in_sizes, int n_in,
                              void* d_out, int out_size) {
    const float* x      = (const float*)d_in[0];
    const float* ln_in_g = (const float*)d_in[1];
    const float* ln_in_b = (const float*)d_in[2];
    const float* W1   = (const float*)d_in[3];
    const float* b1   = (const float*)d_in[4];
    const float* Ws1  = (const float*)d_in[5];
    const float* bs1  = (const float*)d_in[6];
    const float* W2   = (const float*)d_in[7];
    const float* b2   = (const float*)d_in[8];
    const float* Ws2  = (const float*)d_in[9];
    const float* bs2  = (const float*)d_in[10];
    const float* W3   = (const float*)d_in[11];
    const float* b3   = (const float*)d_in[12];
    const float* ln_h_g = (const float*)d_in[13];
    const float* ln_h_b = (const float*)d_in[14];
    const float* Wout = (const float*)d_in[15];
    const float* bout = (const float*)d_in[16];
    const float* aln_g = (const float*)d_in[17];
    const float* aln_b = (const float*)d_in[18];
    const float* Wq = (const float*)d_in[19];
    const float* bq = (const float*)d_in[20];
    const float* Wk = (const float*)d_in[21];
    const float* bk = (const float*)d_in[22];
    const float* Wv = (const float*)d_in[23];
    const float* bv = (const float*)d_in[24];
    const float* Wo = (const float*)d_in[25];
    const float* bo = (const float*)d_in[26];
    float* out = (float*)d_out;

    const int SM1 = (BB * II + 2 * II * HH) * 4;          // 89600
    const int SM2 = (BB * HH + 2 * 32 * HH) * 4;          // 98304
    const int SM3 = (BB * HH + 32 * HH + BB * HH) * 4;    // 122880
    const int SM4 = (BB * HH + 16 * 384) * 4;             // 73728
    const int SM5 = (2 * AA * HDD) * 4;                   // 51200
    const int SM6 = (BB * AD + 32 * HH + BB * HH) * 4;    // 106496

    cudaFuncSetAttribute(k1_layer1, cudaFuncAttributeMaxDynamicSharedMemorySize, SM1);
    cudaFuncSetAttribute(k2_layer2, cudaFuncAttributeMaxDynamicSharedMemorySize, SM2);
    cudaFuncSetAttribute(k3_layer3, cudaFuncAttributeMaxDynamicSharedMemorySize, SM3);
    cudaFuncSetAttribute(k4_qkv,    cudaFuncAttributeMaxDynamicSharedMemorySize, SM4);
    cudaFuncSetAttribute(k5_attn,   cudaFuncAttributeMaxDynamicSharedMemorySize, SM5);
    cudaFuncSetAttribute(k6_out,    cudaFuncAttributeMaxDynamicSharedMemorySize, SM6);

    k0_xhat<<<1, 64>>>(x);
    k1_layer1<<<AA, 512, SM1>>>(ln_in_g, ln_in_b, W1, b1, Ws1, bs1);
    k2_layer2<<<AA, 512, SM2>>>(W2, b2, Ws2, bs2);
    k3_layer3<<<AA, 512, SM3>>>(W3, b3, ln_h_g, ln_h_b, aln_g, aln_b);
    k4_qkv   <<<AA, 512, SM4>>>(Wq, bq, Wk, bk, Wv, bv);
    k5_attn  <<<BB * NHD, 416, SM5>>>();
    k6_out   <<<AA, 512, SM6>>>(Wo, bo, Wout, bout, out);
}

// round 5
// speedup vs baseline: 1.4568x; 1.4568x over previous
#include <cuda_runtime.h>
#include <cuda_fp16.h>
#include <math.h>
#include <stdint.h>

#define AA 400
#define BB 64
#define II 50
#define HH 192
#define OO 3
#define AD 128
#define NHD 8
#define HDD 16
#define EPSF 1e-5f

// ---------------- scratch (device globals) ----------------
__device__ float g_xhat[BB * II];
__device__ float g_h1[AA * BB * HH];
__device__ float g_h2[AA * BB * HH];
__device__ float g_h3[AA * BB * HH];
__device__ float g_y [AA * BB * HH];
__device__ __half g_qh[BB * NHD * AA * HDD];   // [b, h, a, d], pre-scaled by 0.25
__device__ __half g_kh[BB * NHD * AA * HDD];
__device__ __half g_vh[BB * NHD * AA * HDD];
__device__ float  g_o [BB * NHD * AA * HDD];

__device__ __forceinline__ float gelu_exact(float v) {
    return 0.5f * v * (1.0f + erff(v * 0.70710678118654752440f));
}
__device__ __forceinline__ float warp_sum(float v) {
    #pragma unroll
    for (int o = 16; o > 0; o >>= 1) v += __shfl_xor_sync(0xffffffffu, v, o);
    return v;
}
__device__ __forceinline__ float f2tf(float f) {   // round to tf32, return as float bits
    uint32_t r;
    asm("cvt.rna.tf32.f32 %0, %1;" : "=r"(r) : "f"(f));
    return __uint_as_float(r);
}
__device__ __forceinline__ void mma_tf32(float* c, uint32_t a0, uint32_t a1, uint32_t a2, uint32_t a3,
                                         uint32_t b0, uint32_t b1) {
    asm volatile("mma.sync.aligned.m16n8k8.row.col.f32.tf32.tf32.f32 "
                 "{%0,%1,%2,%3},{%4,%5,%6,%7},{%8,%9},{%0,%1,%2,%3};"
                 : "+f"(c[0]), "+f"(c[1]), "+f"(c[2]), "+f"(c[3])
                 : "r"(a0), "r"(a1), "r"(a2), "r"(a3), "r"(b0), "r"(b1));
}
__device__ __forceinline__ void mma_f16(float* c, uint32_t a0, uint32_t a1, uint32_t a2, uint32_t a3,
                                        uint32_t b0, uint32_t b1) {
    asm volatile("mma.sync.aligned.m16n8k16.row.col.f32.f16.f16.f32 "
                 "{%0,%1,%2,%3},{%4,%5,%6,%7},{%8,%9},{%0,%1,%2,%3};"
                 : "+f"(c[0]), "+f"(c[1]), "+f"(c[2]), "+f"(c[3])
                 : "r"(a0), "r"(a1), "r"(a2), "r"(a3), "r"(b0), "r"(b1));
}
__device__ __forceinline__ uint32_t pack2h(float x, float y) {
    __half2 h = __floats2half2_rn(x, y);
    return *reinterpret_cast<uint32_t*>(&h);
}

// ---------------- K0: shared input LN stats ----------------
__global__ void __launch_bounds__(64) k0_xhat(const float* __restrict__ x) {
    int b = threadIdx.x;
    if (b >= BB) return;
    float s = 0.f;
    #pragma unroll
    for (int i = 0; i < II; i++) s += x[b * II + i];
    float mu = s * (1.0f / II);
    float vv = 0.f;
    #pragma unroll
    for (int i = 0; i < II; i++) { float d = x[b * II + i] - mu; vv += d * d; }
    float rinv = rsqrtf(vv * (1.0f / II) + EPSF);
    #pragma unroll
    for (int i = 0; i < II; i++) g_xhat[b * II + i] = (x[b * II + i] - mu) * rinv;
}

// ---------------- K1: layer1 dual GEMM, K padded 50->56, tf32 mma ----------------
__global__ void __launch_bounds__(512) k1_layer1(
        const float* __restrict__ ling, const float* __restrict__ linb,
        const float* __restrict__ W1,  const float* __restrict__ b1,
        const float* __restrict__ Ws1, const float* __restrict__ bs1) {
    int a = blockIdx.x;
    extern __shared__ float sm[];
    float* smA = sm;                      // 64 x 60 (stride 60)
    float* w1s = sm + 64 * 60;            // 56 x 200
    float* w2s = w1s + 56 * 200;          // 56 x 200
    int tid = threadIdx.x, lane = tid & 31, wid = tid >> 5;
    int mrow = (wid & 3) * 16, ncol = (wid >> 2) * 48;

    for (int idx = tid; idx < 64 * 60; idx += 512) {
        int r = idx / 60, c = idx % 60;
        float v = 0.f;
        if (c < II) v = f2tf(g_xhat[r * II + c] * ling[a * II + c] + linb[a * II + c]);
        smA[idx] = v;
    }
    for (int idx = tid; idx < 56 * 200; idx += 512) {
        int k = idx / 200, n = idx % 200;
        float v1 = 0.f, v2 = 0.f;
        if (k < II && n < HH) {
            v1 = f2tf(W1 [a * II * HH + k * HH + n]);
            v2 = f2tf(Ws1[a * II * HH + k * HH + n]);
        }
        w1s[idx] = v1; w2s[idx] = v2;
    }
    __syncthreads();

    float accA[6][4] = {}, accB[6][4] = {};
    #pragma unroll
    for (int ks = 0; ks < 7; ks++) {
        int k0 = ks * 8;
        int ar = mrow + (lane >> 2);
        int ac = k0 + (lane & 3);
        uint32_t a0 = __float_as_uint(smA[ar * 60 + ac]);
        uint32_t a1 = __float_as_uint(smA[(ar + 8) * 60 + ac]);
        uint32_t a2 = __float_as_uint(smA[ar * 60 + ac + 4]);
        uint32_t a3 = __float_as_uint(smA[(ar + 8) * 60 + ac + 4]);
        #pragma unroll
        for (int nt = 0; nt < 6; nt++) {
            int bc = ncol + nt * 8 + (lane >> 2);
            int bo = (k0 + (lane & 3)) * 200 + bc;
            mma_tf32(accA[nt], a0, a1, a2, a3,
                     __float_as_uint(w1s[bo]), __float_as_uint(w1s[bo + 4 * 200]));
            mma_tf32(accB[nt], a0, a1, a2, a3,
                     __float_as_uint(w2s[bo]), __float_as_uint(w2s[bo + 4 * 200]));
        }
    }

    #pragma unroll
    for (int nt = 0; nt < 6; nt++)
        #pragma unroll
        for (int i = 0; i < 4; i++) {
            int row = mrow + (lane >> 2) + (i >> 1) * 8;
            int col = ncol + nt * 8 + (lane & 3) * 2 + (i & 1);
            float va = accA[nt][i] + b1 [a * HH + col];
            float vb = accB[nt][i] + bs1[a * HH + col];
            g_h1[(a * BB + row) * HH + col] = gelu_exact(va) + vb;
        }
}

// ---------------- K2: layer2 dual GEMM K=192, tf32 mma, K-slabs of 48 ----------------
__global__ void __launch_bounds__(512) k2_layer2(
        const float* __restrict__ W2,  const float* __restrict__ b2,
        const float* __restrict__ Ws2, const float* __restrict__ bs2) {
    int a = blockIdx.x;
    extern __shared__ float sm[];
    float* smA = sm;                      // 64 x 196
    float* w1s = sm + 64 * 196;           // 48 x 200
    float* w2s = w1s + 48 * 200;          // 48 x 200
    int tid = threadIdx.x, lane = tid & 31, wid = tid >> 5;
    int mrow = (wid & 3) * 16, ncol = (wid >> 2) * 48;

    const float* src = g_h1 + a * BB * HH;
    for (int idx = tid; idx < BB * HH; idx += 512) {
        int r = idx / HH, c = idx % HH;
        smA[r * 196 + c] = f2tf(src[idx]);
    }

    float accA[6][4] = {}, accB[6][4] = {};
    for (int slab = 0; slab < 4; slab++) {
        __syncthreads();
        const float* wp = W2  + a * HH * HH + slab * 48 * HH;
        const float* wq = Ws2 + a * HH * HH + slab * 48 * HH;
        for (int idx = tid; idx < 48 * HH; idx += 512) {
            int k = idx / HH, n = idx % HH;
            w1s[k * 200 + n] = f2tf(wp[idx]);
            w2s[k * 200 + n] = f2tf(wq[idx]);
        }
        __syncthreads();
        #pragma unroll
        for (int ks = 0; ks < 6; ks++) {
            int k0 = ks * 8;
            int ar = mrow + (lane >> 2);
            int ac = slab * 48 + k0 + (lane & 3);
            uint32_t a0 = __float_as_uint(smA[ar * 196 + ac]);
            uint32_t a1 = __float_as_uint(smA[(ar + 8) * 196 + ac]);
            uint32_t a2 = __float_as_uint(smA[ar * 196 + ac + 4]);
            uint32_t a3 = __float_as_uint(smA[(ar + 8) * 196 + ac + 4]);
            #pragma unroll
            for (int nt = 0; nt < 6; nt++) {
                int bo = (k0 + (lane & 3)) * 200 + ncol + nt * 8 + (lane >> 2);
                mma_tf32(accA[nt], a0, a1, a2, a3,
                         __float_as_uint(w1s[bo]), __float_as_uint(w1s[bo + 4 * 200]));
                mma_tf32(accB[nt], a0, a1, a2, a3,
                         __float_as_uint(w2s[bo]), __float_as_uint(w2s[bo + 4 * 200]));
            }
        }
    }

    #pragma unroll
    for (int nt = 0; nt < 6; nt++)
        #pragma unroll
        for (int i = 0; i < 4; i++) {
            int row = mrow + (lane >> 2) + (i >> 1) * 8;
            int col = ncol + nt * 8 + (lane & 3) * 2 + (i & 1);
            float va = accA[nt][i] + b2 [a * HH + col];
            float vb = accB[nt][i] + bs2[a * HH + col];
            g_h2[(a * BB + row) * HH + col] = gelu_exact(va) + vb;
        }
}

// ---------------- K3: layer3 single GEMM + residual + LN + LN ----------------
__global__ void __launch_bounds__(512) k3_layer3(
        const float* __restrict__ W3,   const float* __restrict__ b3v,
        const float* __restrict__ lhg,  const float* __restrict__ lhb,
        const float* __restrict__ alng, const float* __restrict__ alnb) {
    int a = blockIdx.x;
    extern __shared__ float sm[];
    float* smA = sm;                      // 64 x 196
    float* ws  = sm + 64 * 196;           // 96 x 200 (slab), reused as tbf 64x192
    float* tbf = ws;
    int tid = threadIdx.x, lane = tid & 31, wid = tid >> 5;
    int mrow = (wid & 3) * 16, ncol = (wid >> 2) * 48;

    const float* src = g_h2 + a * BB * HH;
    for (int idx = tid; idx < BB * HH; idx += 512) {
        int r = idx / HH, c = idx % HH;
        smA[r * 196 + c] = f2tf(src[idx]);
    }

    float acc[6][4] = {};
    for (int slab = 0; slab < 2; slab++) {
        __syncthreads();
        const float* wp = W3 + a * HH * HH + slab * 96 * HH;
        for (int idx = tid; idx < 96 * HH; idx += 512) {
            int k = idx / HH, n = idx % HH;
            ws[k * 200 + n] = f2tf(wp[idx]);
        }
        __syncthreads();
        #pragma unroll
        for (int ks = 0; ks < 12; ks++) {
            int k0 = ks * 8;
            int ar = mrow + (lane >> 2);
            int ac = slab * 96 + k0 + (lane & 3);
            uint32_t a0 = __float_as_uint(smA[ar * 196 + ac]);
            uint32_t a1 = __float_as_uint(smA[(ar + 8) * 196 + ac]);
            uint32_t a2 = __float_as_uint(smA[ar * 196 + ac + 4]);
            uint32_t a3 = __float_as_uint(smA[(ar + 8) * 196 + ac + 4]);
            #pragma unroll
            for (int nt = 0; nt < 6; nt++) {
                int bo = (k0 + (lane & 3)) * 200 + ncol + nt * 8 + (lane >> 2);
                mma_tf32(acc[nt], a0, a1, a2, a3,
                         __float_as_uint(ws[bo]), __float_as_uint(ws[bo + 4 * 200]));
            }
        }
    }
    __syncthreads();   // done reading ws; reuse as tbf

    #pragma unroll
    for (int nt = 0; nt < 6; nt++)
        #pragma unroll
        for (int i = 0; i < 4; i++) {
            int row = mrow + (lane >> 2) + (i >> 1) * 8;
            int col = ncol + nt * 8 + (lane & 3) * 2 + (i & 1);
            tbf[row * HH + col] = smA[row * 196 + col] + acc[nt][i] + b3v[a * HH + col];
        }
    __syncthreads();

    for (int r = wid; r < BB; r += 16) {
        float v[6];
        #pragma unroll
        for (int u = 0; u < 6; u++) v[u] = tbf[r * HH + u * 32 + lane];
        float s = 0.f;
        #pragma unroll
        for (int u = 0; u < 6; u++) s += v[u];
        s = warp_sum(s);
        float mu = s * (1.0f / HH);
        float ss = 0.f;
        #pragma unroll
        for (int u = 0; u < 6; u++) { float d = v[u] - mu; ss += d * d; }
        ss = warp_sum(ss);
        float rinv = rsqrtf(ss * (1.0f / HH) + EPSF);

        float h3v[6]; float s2 = 0.f;
        #pragma unroll
        for (int u = 0; u < 6; u++) {
            int i = u * 32 + lane;
            h3v[u] = (v[u] - mu) * rinv * lhg[a * HH + i] + lhb[a * HH + i];
            g_h3[(a * BB + r) * HH + i] = h3v[u];
            s2 += h3v[u];
        }
        s2 = warp_sum(s2);
        float mu2 = s2 * (1.0f / HH);
        float ss2 = 0.f;
        #pragma unroll
        for (int u = 0; u < 6; u++) { float d = h3v[u] - mu2; ss2 += d * d; }
        ss2 = warp_sum(ss2);
        float rinv2 = rsqrtf(ss2 * (1.0f / HH) + EPSF);
        #pragma unroll
        for (int u = 0; u < 6; u++) {
            int i = u * 32 + lane;
            g_y[(a * BB + r) * HH + i] = (h3v[u] - mu2) * rinv2 * alng[i] + alnb[i];
        }
    }
}

// ---------------- K4: fused QKV (N=384) tf32 mma -> fp16 q/k/v (q pre-scaled) ----------------
__global__ void __launch_bounds__(512) k4_qkv(
        const float* __restrict__ Wq, const float* __restrict__ bq,
        const float* __restrict__ Wk, const float* __restrict__ bk,
        const float* __restrict__ Wv, const float* __restrict__ bv) {
    int a = blockIdx.x;
    extern __shared__ float sm[];
    float* smA = sm;                      // 64 x 196
    float* ws  = sm + 64 * 196;           // 32 x 392
    int tid = threadIdx.x, lane = tid & 31, wid = tid >> 5;
    int mrow = (wid & 3) * 16, ncol = (wid >> 2) * 96;

    const float* src = g_y + a * BB * HH;
    for (int idx = tid; idx < BB * HH; idx += 512) {
        int r = idx / HH, c = idx % HH;
        smA[r * 196 + c] = f2tf(src[idx]);
    }

    float acc[12][4] = {};
    for (int slab = 0; slab < 6; slab++) {
        __syncthreads();
        int kb = slab * 32;
        for (int idx = tid; idx < 32 * 384; idx += 512) {
            int k = idx / 384, n = idx % 384;
            int kk = kb + k;
            float w;
            if (n < 128)      w = Wq[kk * AD + n];
            else if (n < 256) w = Wk[kk * AD + n - 128];
            else              w = Wv[kk * AD + n - 256];
            ws[k * 392 + n] = f2tf(w);
        }
        __syncthreads();
        #pragma unroll
        for (int ks = 0; ks < 4; ks++) {
            int k0 = ks * 8;
            int ar = mrow + (lane >> 2);
            int ac = kb + k0 + (lane & 3);
            uint32_t a0 = __float_as_uint(smA[ar * 196 + ac]);
            uint32_t a1 = __float_as_uint(smA[(ar + 8) * 196 + ac]);
            uint32_t a2 = __float_as_uint(smA[ar * 196 + ac + 4]);
            uint32_t a3 = __float_as_uint(smA[(ar + 8) * 196 + ac + 4]);
            #pragma unroll
            for (int nt = 0; nt < 12; nt++) {
                int bo = (k0 + (lane & 3)) * 392 + ncol + nt * 8 + (lane >> 2);
                mma_tf32(acc[nt], a0, a1, a2, a3,
                         __float_as_uint(ws[bo]), __float_as_uint(ws[bo + 4 * 392]));
            }
        }
    }

    #pragma unroll
    for (int nt = 0; nt < 12; nt++)
        #pragma unroll
        for (int i = 0; i < 4; i++) {
            int row = mrow + (lane >> 2) + (i >> 1) * 8;
            int col = ncol + nt * 8 + (lane & 3) * 2 + (i & 1);
            float val = acc[nt][i];
            __half* dst; int c;
            if (col < 128)      { val = (val + bq[col]) * 0.25f; c = col;       dst = g_qh; }
            else if (col < 256) { val = val + bk[col - 128];     c = col - 128; dst = g_kh; }
            else                { val = val + bv[col - 256];     c = col - 256; dst = g_vh; }
            dst[(((row * NHD) + (c >> 4)) * AA + a) * HDD + (c & 15)] = __float2half_rn(val);
        }
}

// ---------------- K5: flash attention over agents, fp16 mma ----------------
template<int NTS>
__device__ __forceinline__ void attn_chunk(int jbase, const __half* ks, const __half* vt,
                                           uint32_t qa0, uint32_t qa1, uint32_t qa2, uint32_t qa3,
                                           float* m, float* l, float* o0, float* o1, int lane) {
    float sc[NTS][4];
    #pragma unroll
    for (int nt = 0; nt < NTS; nt++) { sc[nt][0] = sc[nt][1] = sc[nt][2] = sc[nt][3] = 0.f; }
    #pragma unroll
    for (int nt = 0; nt < NTS; nt++) {
        const __half* bp = ks + (jbase + nt * 8 + (lane >> 2)) * 16 + 2 * (lane & 3);
        uint32_t b0 = *(const uint32_t*)bp;
        uint32_t b1 = *(const uint32_t*)(bp + 8);
        mma_f16(sc[nt], qa0, qa1, qa2, qa3, b0, b1);
    }
    float mx0 = -1e30f, mx1 = -1e30f;
    #pragma unroll
    for (int nt = 0; nt < NTS; nt++) {
        mx0 = fmaxf(mx0, fmaxf(sc[nt][0], sc[nt][1]));
        mx1 = fmaxf(mx1, fmaxf(sc[nt][2], sc[nt][3]));
    }
    mx0 = fmaxf(mx0, __shfl_xor_sync(0xffffffffu, mx0, 1));
    mx0 = fmaxf(mx0, __shfl_xor_sync(0xffffffffu, mx0, 2));
    mx1 = fmaxf(mx1, __shfl_xor_sync(0xffffffffu, mx1, 1));
    mx1 = fmaxf(mx1, __shfl_xor_sync(0xffffffffu, mx1, 2));
    float mn0 = fmaxf(m[0], mx0), mn1 = fmaxf(m[1], mx1);
    float f0 = __expf(m[0] - mn0), f1 = __expf(m[1] - mn1);
    float p[NTS][4];
    float sum0 = 0.f, sum1 = 0.f;
    #pragma unroll
    for (int nt = 0; nt < NTS; nt++) {
        p[nt][0] = __expf(sc[nt][0] - mn0);
        p[nt][1] = __expf(sc[nt][1] - mn0);
        p[nt][2] = __expf(sc[nt][2] - mn1);
        p[nt][3] = __expf(sc[nt][3] - mn1);
        sum0 += p[nt][0] + p[nt][1];
        sum1 += p[nt][2] + p[nt][3];
    }
    sum0 += __shfl_xor_sync(0xffffffffu, sum0, 1);
    sum0 += __shfl_xor_sync(0xffffffffu, sum0, 2);
    sum1 += __shfl_xor_sync(0xffffffffu, sum1, 1);
    sum1 += __shfl_xor_sync(0xffffffffu, sum1, 2);
    l[0] = l[0] * f0 + sum0;
    l[1] = l[1] * f1 + sum1;
    o0[0] *= f0; o0[1] *= f0; o0[2] *= f1; o0[3] *= f1;
    o1[0] *= f0; o1[1] *= f0; o1[2] *= f1; o1[3] *= f1;
    m[0] = mn0; m[1] = mn1;
    #pragma unroll
    for (int s = 0; s < NTS / 2; s++) {
        uint32_t pa0 = pack2h(p[2*s][0],   p[2*s][1]);
        uint32_t pa1 = pack2h(p[2*s][2],   p[2*s][3]);
        uint32_t pa2 = pack2h(p[2*s+1][0], p[2*s+1][1]);
        uint32_t pa3 = pack2h(p[2*s+1][2], p[2*s+1][3]);
        #pragma unroll
        for (int d = 0; d < 2; d++) {
            const __half* bp = vt + (d * 8 + (lane >> 2)) * 456 + jbase + 16 * s + 2 * (lane & 3);
            uint32_t b0 = *(const uint32_t*)bp;
            uint32_t b1 = *(const uint32_t*)(bp + 8);
            mma_f16(d ? o1 : o0, pa0, pa1, pa2, pa3, b0, b1);
        }
    }
}

__global__ void __launch_bounds__(128) k5_attn() {
    int bh = blockIdx.x;
    int tid = threadIdx.x, lane = tid & 31, wid = tid >> 5;
    extern __shared__ __half smh[];
    __half* qs = smh;                 // 448 x 16
    __half* ks = smh + 448 * 16;      // 400 x 16
    __half* vt = ks + 400 * 16;       // 16 x 456 (transposed V)

    const __half* qg = g_qh + bh * AA * HDD;
    const __half* kg = g_kh + bh * AA * HDD;
    const __half* vg = g_vh + bh * AA * HDD;

    {
        uint4* qd = (uint4*)qs; const uint4* qsrc = (const uint4*)qg;
        for (int i = tid; i < 800; i += 128) qd[i] = qsrc[i];
        uint4 z; z.x = z.y = z.z = z.w = 0u;
        for (int i = tid; i < 96; i += 128) qd[800 + i] = z;
        uint4* kd = (uint4*)ks; const uint4* ksrc = (const uint4*)kg;
        for (int i = tid; i < 800; i += 128) kd[i] = ksrc[i];
        const __half2* vsrc = (const __half2*)vg;
        for (int i = tid; i < 3200; i += 128) {
            int ag = i >> 3, dd = i & 7;
            __half2 h = vsrc[i];
            vt[(2 * dd) * 456 + ag]     = __low2half(h);
            vt[(2 * dd + 1) * 456 + ag] = __high2half(h);
        }
    }
    __syncthreads();

    for (int p = 0; p < 7; p++) {
        int mrow = p * 64 + wid * 16;
        int r = mrow + (lane >> 2);
        const __half* qp = qs + r * 16 + 2 * (lane & 3);
        uint32_t qa0 = *(const uint32_t*)qp;
        uint32_t qa1 = *(const uint32_t*)(qp + 8 * 16);
        uint32_t qa2 = *(const uint32_t*)(qp + 8);
        uint32_t qa3 = *(const uint32_t*)(qp + 8 * 16 + 8);
        float m[2] = {-1e30f, -1e30f}, l[2] = {0.f, 0.f};
        float o0[4] = {0.f, 0.f, 0.f, 0.f}, o1[4] = {0.f, 0.f, 0.f, 0.f};
        #pragma unroll 1
        for (int c = 0; c < 6; c++)
            attn_chunk<8>(c * 64, ks, vt, qa0, qa1, qa2, qa3, m, l, o0, o1, lane);
        attn_chunk<2>(384, ks, vt, qa0, qa1, qa2, qa3, m, l, o0, o1, lane);

        float i0 = 1.0f / l[0], i1 = 1.0f / l[1];
        int row0 = mrow + (lane >> 2), row1 = row0 + 8;
        int colb = (lane & 3) * 2;
        if (row0 < AA) {
            float* op = g_o + (bh * AA + row0) * HDD;
            op[colb] = o0[0] * i0; op[colb + 1] = o0[1] * i0;
            op[8 + colb] = o1[0] * i0; op[8 + colb + 1] = o1[1] * i0;
        }
        if (row1 < AA) {
            float* op = g_o + (bh * AA + row1) * HDD;
            op[colb] = o0[2] * i1; op[colb + 1] = o0[3] * i1;
            op[8 + colb] = o1[2] * i1; op[8 + colb + 1] = o1[3] * i1;
        }
    }
}

// ---------------- K6: O-proj (tf32 mma) + residual + output head ----------------
__global__ void __launch_bounds__(512) k6_out(
        const float* __restrict__ Wo,   const float* __restrict__ bo,
        const float* __restrict__ Wout, const float* __restrict__ bout,
        float* __restrict__ out) {
    int a = blockIdx.x;
    extern __shared__ float sm[];
    float* smA = sm;                      // 64 x 132
    float* smW = sm + 64 * 132;           // 128 x 200
    float* att = smW + 128 * 200;         // 64 x 192
    int tid = threadIdx.x, lane = tid & 31, wid = tid >> 5;
    int mrow = (wid & 3) * 16, ncol = (wid >> 2) * 48;

    for (int idx = tid; idx < BB * AD; idx += 512) {
        int b = idx >> 7, c = idx & 127;
        smA[b * 132 + c] = f2tf(g_o[(((b * NHD) + (c >> 4)) * AA + a) * HDD + (c & 15)]);
    }
    for (int idx = tid; idx < AD * HH; idx += 512) {
        int k = idx / HH, n = idx % HH;
        smW[k * 200 + n] = f2tf(Wo[idx]);
    }
    __syncthreads();

    float acc[6][4] = {};
    #pragma unroll
    for (int ks = 0; ks < 16; ks++) {
        int k0 = ks * 8;
        int ar = mrow + (lane >> 2);
        int ac = k0 + (lane & 3);
        uint32_t a0 = __float_as_uint(smA[ar * 132 + ac]);
        uint32_t a1 = __float_as_uint(smA[(ar + 8) * 132 + ac]);
        uint32_t a2 = __float_as_uint(smA[ar * 132 + ac + 4]);
        uint32_t a3 = __float_as_uint(smA[(ar + 8) * 132 + ac + 4]);
        #pragma unroll
        for (int nt = 0; nt < 6; nt++) {
            int bo2 = (k0 + (lane & 3)) * 200 + ncol + nt * 8 + (lane >> 2);
            mma_tf32(acc[nt], a0, a1, a2, a3,
                     __float_as_uint(smW[bo2]), __float_as_uint(smW[bo2 + 4 * 200]));
        }
    }

    #pragma unroll
    for (int nt = 0; nt < 6; nt++)
        #pragma unroll
        for (int i = 0; i < 4; i++) {
            int row = mrow + (lane >> 2) + (i >> 1) * 8;
            int col = ncol + nt * 8 + (lane & 3) * 2 + (i & 1);
            att[row * HH + col] = g_h3[(a * BB + row) * HH + col] + acc[nt][i] + bo[col];
        }
    __syncthreads();

    if (tid < BB * OO) {
        int b = tid / OO, oo = tid % OO;
        float s = bout[a * OO + oo];
        #pragma unroll 4
        for (int k = 0; k < HH; k++)
            s = fmaf(att[b * HH + k], Wout[(a * HH + k) * OO + oo], s);
        out[(a * BB + b) * OO + oo] = s;
    }
}

// ---------------- host launcher ----------------
extern "C" void kernel_launch(void* const* d_in, const int* in_sizes, int n_in,
                              void* d_out, int out_size) {
    const float* x       = (const float*)d_in[0];
    const float* ln_in_g = (const float*)d_in[1];
    const float* ln_in_b = (const float*)d_in[2];
    const float* W1   = (const float*)d_in[3];
    const float* b1   = (const float*)d_in[4];
    const float* Ws1  = (const float*)d_in[5];
    const float* bs1  = (const float*)d_in[6];
    const float* W2   = (const float*)d_in[7];
    const float* b2   = (const float*)d_in[8];
    const float* Ws2  = (const float*)d_in[9];
    const float* bs2  = (const float*)d_in[10];
    const float* W3   = (const float*)d_in[11];
    const float* b3   = (const float*)d_in[12];
    const float* ln_h_g = (const float*)d_in[13];
    const float* ln_h_b = (const float*)d_in[14];
    const float* Wout = (const float*)d_in[15];
    const float* bout = (const float*)d_in[16];
    const float* aln_g = (const float*)d_in[17];
    const float* aln_b = (const float*)d_in[18];
    const float* Wq = (const float*)d_in[19];
    const float* bq = (const float*)d_in[20];
    const float* Wk = (const float*)d_in[21];
    const float* bk = (const float*)d_in[22];
    const float* Wv = (const float*)d_in[23];
    const float* bv = (const float*)d_in[24];
    const float* Wo = (const float*)d_in[25];
    const float* bo = (const float*)d_in[26];
    float* out = (float*)d_out;

    const int SM1 = (64 * 60 + 2 * 56 * 200) * 4;
    const int SM2 = (64 * 196 + 2 * 48 * 200) * 4;
    const int SM3 = (64 * 196 + 96 * 200) * 4;
    const int SM4 = (64 * 196 + 32 * 392) * 4;
    const int SM5 = (448 * 16 + 400 * 16 + 16 * 456) * 2;
    const int SM6 = (64 * 132 + 128 * 200 + 64 * 192) * 4;

    cudaFuncSetAttribute(k1_layer1, cudaFuncAttributeMaxDynamicSharedMemorySize, SM1);
    cudaFuncSetAttribute(k2_layer2, cudaFuncAttributeMaxDynamicSharedMemorySize, SM2);
    cudaFuncSetAttribute(k3_layer3, cudaFuncAttributeMaxDynamicSharedMemorySize, SM3);
    cudaFuncSetAttribute(k4_qkv,    cudaFuncAttributeMaxDynamicSharedMemorySize, SM4);
    cudaFuncSetAttribute(k5_attn,   cudaFuncAttributeMaxDynamicSharedMemorySize, SM5);
    cudaFuncSetAttribute(k6_out,    cudaFuncAttributeMaxDynamicSharedMemorySize, SM6);

    k0_xhat  <<<1, 64>>>(x);
    k1_layer1<<<AA, 512, SM1>>>(ln_in_g, ln_in_b, W1, b1, Ws1, bs1);
    k2_layer2<<<AA, 512, SM2>>>(W2, b2, Ws2, bs2);
    k3_layer3<<<AA, 512, SM3>>>(W3, b3, ln_h_g, ln_h_b, aln_g, aln_b);
    k4_qkv   <<<AA, 512, SM4>>>(Wq, bq, Wk, bk, Wv, bv);
    k5_attn  <<<BB * NHD, 128, SM5>>>();
    k6_out   <<<AA, 512, SM6>>>(Wo, bo, Wout, bout, out);
}

// round 6
// speedup vs baseline: 2.7551x; 1.8913x over previous
#include <cuda_runtime.h>
#include <cuda_fp16.h>
#include <math.h>
#include <stdint.h>

#define AA 400
#define BB 64
#define II 50
#define HH 192
#define OO 3
#define AD 128
#define NHD 8
#define HDD 16
#define EPSF 1e-5f

// ---------------- scratch (device globals) ----------------
__device__ __align__(16) float g_xhat[BB * II];
__device__ __align__(16) float g_h1[AA * BB * HH];
__device__ __align__(16) float g_h2[AA * BB * HH];
__device__ __align__(16) float g_h3[AA * BB * HH];
__device__ __align__(16) float g_y [AA * BB * HH];
__device__ __align__(16) __half g_qh[BB * NHD * AA * HDD];   // [b, h, a, d], pre-scaled by 0.25
__device__ __align__(16) __half g_kh[BB * NHD * AA * HDD];
__device__ __align__(16) __half g_vh[BB * NHD * AA * HDD];
__device__ __align__(16) float  g_o [BB * NHD * AA * HDD];

__device__ __forceinline__ float gelu_exact(float v) {
    return 0.5f * v * (1.0f + erff(v * 0.70710678118654752440f));
}
__device__ __forceinline__ float warp_sum(float v) {
    #pragma unroll
    for (int o = 16; o > 0; o >>= 1) v += __shfl_xor_sync(0xffffffffu, v, o);
    return v;
}
__device__ __forceinline__ float f2tf(float f) {
    uint32_t r;
    asm("cvt.rna.tf32.f32 %0, %1;" : "=r"(r) : "f"(f));
    return __uint_as_float(r);
}
__device__ __forceinline__ float4 f2tf4(float4 v) {
    return make_float4(f2tf(v.x), f2tf(v.y), f2tf(v.z), f2tf(v.w));
}
__device__ __forceinline__ void mma_tf32(float* c, uint32_t a0, uint32_t a1, uint32_t a2, uint32_t a3,
                                         uint32_t b0, uint32_t b1) {
    asm volatile("mma.sync.aligned.m16n8k8.row.col.f32.tf32.tf32.f32 "
                 "{%0,%1,%2,%3},{%4,%5,%6,%7},{%8,%9},{%0,%1,%2,%3};"
                 : "+f"(c[0]), "+f"(c[1]), "+f"(c[2]), "+f"(c[3])
                 : "r"(a0), "r"(a1), "r"(a2), "r"(a3), "r"(b0), "r"(b1));
}
__device__ __forceinline__ void mma_f16(float* c, uint32_t a0, uint32_t a1, uint32_t a2, uint32_t a3,
                                        uint32_t b0, uint32_t b1) {
    asm volatile("mma.sync.aligned.m16n8k16.row.col.f32.f16.f16.f32 "
                 "{%0,%1,%2,%3},{%4,%5,%6,%7},{%8,%9},{%0,%1,%2,%3};"
                 : "+f"(c[0]), "+f"(c[1]), "+f"(c[2]), "+f"(c[3])
                 : "r"(a0), "r"(a1), "r"(a2), "r"(a3), "r"(b0), "r"(b1));
}
__device__ __forceinline__ uint32_t pack2h(float x, float y) {
    __half2 h = __floats2half2_rn(x, y);
    return *reinterpret_cast<uint32_t*>(&h);
}

// ---------------- K0: shared input LN stats ----------------
__global__ void __launch_bounds__(64) k0_xhat(const float* __restrict__ x) {
    int b = threadIdx.x;
    if (b >= BB) return;
    float s = 0.f;
    #pragma unroll
    for (int i = 0; i < II; i++) s += x[b * II + i];
    float mu = s * (1.0f / II);
    float vv = 0.f;
    #pragma unroll
    for (int i = 0; i < II; i++) { float d = x[b * II + i] - mu; vv += d * d; }
    float rinv = rsqrtf(vv * (1.0f / II) + EPSF);
    #pragma unroll
    for (int i = 0; i < II; i++) g_xhat[b * II + i] = (x[b * II + i] - mu) * rinv;
}

// ---------------- K1: layer1 dual GEMM, K padded 50->56, tf32 mma, vectorized loads ----------------
__global__ void __launch_bounds__(512) k1_layer1(
        const float* __restrict__ ling, const float* __restrict__ linb,
        const float* __restrict__ W1,  const float* __restrict__ b1,
        const float* __restrict__ Ws1, const float* __restrict__ bs1) {
    int a = blockIdx.x;
    extern __shared__ float sm[];
    float* smA = sm;                      // 64 x 60
    float* w1s = sm + 64 * 60;            // 56 x 200
    float* w2s = w1s + 56 * 200;          // 56 x 200
    int tid = threadIdx.x, lane = tid & 31, wid = tid >> 5;
    int mrow = (wid & 3) * 16, ncol = (wid >> 2) * 48;

    // weights: II*HH = 9600 floats = 2400 float4 each, contiguous
    const float4* w1g = (const float4*)(W1  + a * II * HH);
    const float4* w2g = (const float4*)(Ws1 + a * II * HH);
    for (int f = tid; f < 2400; f += 512) {
        int k = f / 48, n4 = (f % 48) * 4;
        float4 v1 = f2tf4(w1g[f]);
        float4 v2 = f2tf4(w2g[f]);
        *(float4*)(w1s + k * 200 + n4) = v1;
        *(float4*)(w2s + k * 200 + n4) = v2;
    }
    for (int idx = tid; idx < 6 * 200; idx += 512) { w1s[10000 + idx] = 0.f; w2s[10000 + idx] = 0.f; }

    for (int idx = tid; idx < 64 * 60; idx += 512) {
        int r = idx / 60, c = idx % 60;
        float v = 0.f;
        if (c < II) v = f2tf(g_xhat[r * II + c] * ling[a * II + c] + linb[a * II + c]);
        smA[idx] = v;
    }
    __syncthreads();

    float accA[6][4] = {}, accB[6][4] = {};
    #pragma unroll
    for (int ks = 0; ks < 7; ks++) {
        int k0 = ks * 8;
        int ar = mrow + (lane >> 2);
        int ac = k0 + (lane & 3);
        uint32_t a0 = __float_as_uint(smA[ar * 60 + ac]);
        uint32_t a1 = __float_as_uint(smA[(ar + 8) * 60 + ac]);
        uint32_t a2 = __float_as_uint(smA[ar * 60 + ac + 4]);
        uint32_t a3 = __float_as_uint(smA[(ar + 8) * 60 + ac + 4]);
        #pragma unroll
        for (int nt = 0; nt < 6; nt++) {
            int bo = (k0 + (lane & 3)) * 200 + ncol + nt * 8 + (lane >> 2);
            mma_tf32(accA[nt], a0, a1, a2, a3,
                     __float_as_uint(w1s[bo]), __float_as_uint(w1s[bo + 4 * 200]));
            mma_tf32(accB[nt], a0, a1, a2, a3,
                     __float_as_uint(w2s[bo]), __float_as_uint(w2s[bo + 4 * 200]));
        }
    }

    #pragma unroll
    for (int nt = 0; nt < 6; nt++)
        #pragma unroll
        for (int j = 0; j < 2; j++) {
            int row = mrow + (lane >> 2) + j * 8;
            int col = ncol + nt * 8 + (lane & 3) * 2;
            float va0 = accA[nt][j*2]   + b1 [a * HH + col];
            float va1 = accA[nt][j*2+1] + b1 [a * HH + col + 1];
            float vb0 = accB[nt][j*2]   + bs1[a * HH + col];
            float vb1 = accB[nt][j*2+1] + bs1[a * HH + col + 1];
            float2 o = make_float2(gelu_exact(va0) + vb0, gelu_exact(va1) + vb1);
            *(float2*)(g_h1 + (a * BB + row) * HH + col) = o;
        }
}

// ---------------- K2: layer2 dual GEMM K=192, pipelined 32-row slabs ----------------
__global__ void __launch_bounds__(512) k2_layer2(
        const float* __restrict__ W2,  const float* __restrict__ b2,
        const float* __restrict__ Ws2, const float* __restrict__ bs2) {
    int a = blockIdx.x;
    extern __shared__ float sm[];
    float* smA = sm;                       // 64 x 196
    float* wb  = sm + 64 * 196;            // 2 stages x 2 matrices x 32 x 200
    int tid = threadIdx.x, lane = tid & 31, wid = tid >> 5;
    int mrow = (wid & 3) * 16, ncol = (wid >> 2) * 48;

    // A tile: 64x192 = 3072 float4
    const float4* src = (const float4*)(g_h1 + a * BB * HH);
    #pragma unroll
    for (int i = 0; i < 6; i++) {
        int f = tid + i * 512;
        int r = f / 48, n4 = (f % 48) * 4;
        *(float4*)(smA + r * 196 + n4) = f2tf4(src[f]);
    }

    const float4* w1g = (const float4*)(W2  + a * HH * HH);
    const float4* w2g = (const float4*)(Ws2 + a * HH * HH);
    // slab = 32 rows x 192 cols = 1536 float4; 3 per thread
    float4 r1[3], r2[3];
    #pragma unroll
    for (int j = 0; j < 3; j++) { r1[j] = w1g[tid + j * 512]; r2[j] = w2g[tid + j * 512]; }
    {
        #pragma unroll
        for (int j = 0; j < 3; j++) {
            int f = tid + j * 512;
            int k = f / 48, n4 = (f % 48) * 4;
            *(float4*)(wb + k * 200 + n4)            = f2tf4(r1[j]);
            *(float4*)(wb + 32 * 200 + k * 200 + n4) = f2tf4(r2[j]);
        }
    }
    __syncthreads();

    float accA[6][4] = {}, accB[6][4] = {};
    #pragma unroll 1
    for (int slab = 0; slab < 6; slab++) {
        if (slab < 5) {
            const float4* p1 = w1g + (slab + 1) * 1536;
            const float4* p2 = w2g + (slab + 1) * 1536;
            #pragma unroll
            for (int j = 0; j < 3; j++) { r1[j] = p1[tid + j * 512]; r2[j] = p2[tid + j * 512]; }
        }
        float* cw1 = wb + (slab & 1) * 2 * 32 * 200;
        float* cw2 = cw1 + 32 * 200;
        #pragma unroll
        for (int ks = 0; ks < 4; ks++) {
            int k0 = ks * 8;
            int ar = mrow + (lane >> 2);
            int ac = slab * 32 + k0 + (lane & 3);
            uint32_t a0 = __float_as_uint(smA[ar * 196 + ac]);
            uint32_t a1 = __float_as_uint(smA[(ar + 8) * 196 + ac]);
            uint32_t a2 = __float_as_uint(smA[ar * 196 + ac + 4]);
            uint32_t a3 = __float_as_uint(smA[(ar + 8) * 196 + ac + 4]);
            #pragma unroll
            for (int nt = 0; nt < 6; nt++) {
                int bo = (k0 + (lane & 3)) * 200 + ncol + nt * 8 + (lane >> 2);
                mma_tf32(accA[nt], a0, a1, a2, a3,
                         __float_as_uint(cw1[bo]), __float_as_uint(cw1[bo + 4 * 200]));
                mma_tf32(accB[nt], a0, a1, a2, a3,
                         __float_as_uint(cw2[bo]), __float_as_uint(cw2[bo + 4 * 200]));
            }
        }
        if (slab < 5) {
            float* n1 = wb + ((slab + 1) & 1) * 2 * 32 * 200;
            float* n2 = n1 + 32 * 200;
            #pragma unroll
            for (int j = 0; j < 3; j++) {
                int f = tid + j * 512;
                int k = f / 48, n4 = (f % 48) * 4;
                *(float4*)(n1 + k * 200 + n4) = f2tf4(r1[j]);
                *(float4*)(n2 + k * 200 + n4) = f2tf4(r2[j]);
            }
        }
        __syncthreads();
    }

    #pragma unroll
    for (int nt = 0; nt < 6; nt++)
        #pragma unroll
        for (int j = 0; j < 2; j++) {
            int row = mrow + (lane >> 2) + j * 8;
            int col = ncol + nt * 8 + (lane & 3) * 2;
            float va0 = accA[nt][j*2]   + b2 [a * HH + col];
            float va1 = accA[nt][j*2+1] + b2 [a * HH + col + 1];
            float vb0 = accB[nt][j*2]   + bs2[a * HH + col];
            float vb1 = accB[nt][j*2+1] + bs2[a * HH + col + 1];
            float2 o = make_float2(gelu_exact(va0) + vb0, gelu_exact(va1) + vb1);
            *(float2*)(g_h2 + (a * BB + row) * HH + col) = o;
        }
}

// ---------------- K3: layer3 GEMM (pipelined) + residual + LN + LN ----------------
__global__ void __launch_bounds__(512) k3_layer3(
        const float* __restrict__ W3,   const float* __restrict__ b3v,
        const float* __restrict__ lhg,  const float* __restrict__ lhb,
        const float* __restrict__ alng, const float* __restrict__ alnb) {
    int a = blockIdx.x;
    extern __shared__ float sm[];
    float* smA = sm;                       // 64 x 196
    float* wb  = sm + 64 * 196;            // 2 stages x 32 x 200 (reused as tbf 64x192)
    float* tbf = wb;
    int tid = threadIdx.x, lane = tid & 31, wid = tid >> 5;
    int mrow = (wid & 3) * 16, ncol = (wid >> 2) * 48;

    const float4* src = (const float4*)(g_h2 + a * BB * HH);
    #pragma unroll
    for (int i = 0; i < 6; i++) {
        int f = tid + i * 512;
        int r = f / 48, n4 = (f % 48) * 4;
        *(float4*)(smA + r * 196 + n4) = f2tf4(src[f]);
    }

    const float4* wg = (const float4*)(W3 + a * HH * HH);
    float4 rw[3];
    #pragma unroll
    for (int j = 0; j < 3; j++) rw[j] = wg[tid + j * 512];
    #pragma unroll
    for (int j = 0; j < 3; j++) {
        int f = tid + j * 512;
        int k = f / 48, n4 = (f % 48) * 4;
        *(float4*)(wb + k * 200 + n4) = f2tf4(rw[j]);
    }
    __syncthreads();

    float acc[6][4] = {};
    #pragma unroll 1
    for (int slab = 0; slab < 6; slab++) {
        if (slab < 5) {
            const float4* p = wg + (slab + 1) * 1536;
            #pragma unroll
            for (int j = 0; j < 3; j++) rw[j] = p[tid + j * 512];
        }
        float* cw = wb + (slab & 1) * 32 * 200;
        #pragma unroll
        for (int ks = 0; ks < 4; ks++) {
            int k0 = ks * 8;
            int ar = mrow + (lane >> 2);
            int ac = slab * 32 + k0 + (lane & 3);
            uint32_t a0 = __float_as_uint(smA[ar * 196 + ac]);
            uint32_t a1 = __float_as_uint(smA[(ar + 8) * 196 + ac]);
            uint32_t a2 = __float_as_uint(smA[ar * 196 + ac + 4]);
            uint32_t a3 = __float_as_uint(smA[(ar + 8) * 196 + ac + 4]);
            #pragma unroll
            for (int nt = 0; nt < 6; nt++) {
                int bo = (k0 + (lane & 3)) * 200 + ncol + nt * 8 + (lane >> 2);
                mma_tf32(acc[nt], a0, a1, a2, a3,
                         __float_as_uint(cw[bo]), __float_as_uint(cw[bo + 4 * 200]));
            }
        }
        if (slab < 5) {
            float* nw = wb + ((slab + 1) & 1) * 32 * 200;
            #pragma unroll
            for (int j = 0; j < 3; j++) {
                int f = tid + j * 512;
                int k = f / 48, n4 = (f % 48) * 4;
                *(float4*)(nw + k * 200 + n4) = f2tf4(rw[j]);
            }
        }
        __syncthreads();
    }

    // t = h2 + h2@W3 + b3 (smA holds tf32-rounded h2; close enough? NO — need exact h2)
    // residual must be exact h2: reload from global (L2-hot) as float2
    #pragma unroll
    for (int nt = 0; nt < 6; nt++)
        #pragma unroll
        for (int j = 0; j < 2; j++) {
            int row = mrow + (lane >> 2) + j * 8;
            int col = ncol + nt * 8 + (lane & 3) * 2;
            float2 h2v = *(const float2*)(g_h2 + (a * BB + row) * HH + col);
            tbf[row * HH + col]     = h2v.x + acc[nt][j*2]   + b3v[a * HH + col];
            tbf[row * HH + col + 1] = h2v.y + acc[nt][j*2+1] + b3v[a * HH + col + 1];
        }
    __syncthreads();

    for (int r = wid; r < BB; r += 16) {
        float v[6];
        #pragma unroll
        for (int u = 0; u < 6; u++) v[u] = tbf[r * HH + u * 32 + lane];
        float s = 0.f;
        #pragma unroll
        for (int u = 0; u < 6; u++) s += v[u];
        s = warp_sum(s);
        float mu = s * (1.0f / HH);
        float ss = 0.f;
        #pragma unroll
        for (int u = 0; u < 6; u++) { float d = v[u] - mu; ss += d * d; }
        ss = warp_sum(ss);
        float rinv = rsqrtf(ss * (1.0f / HH) + EPSF);

        float h3v[6]; float s2 = 0.f;
        #pragma unroll
        for (int u = 0; u < 6; u++) {
            int i = u * 32 + lane;
            h3v[u] = (v[u] - mu) * rinv * lhg[a * HH + i] + lhb[a * HH + i];
            g_h3[(a * BB + r) * HH + i] = h3v[u];
            s2 += h3v[u];
        }
        s2 = warp_sum(s2);
        float mu2 = s2 * (1.0f / HH);
        float ss2 = 0.f;
        #pragma unroll
        for (int u = 0; u < 6; u++) { float d = h3v[u] - mu2; ss2 += d * d; }
        ss2 = warp_sum(ss2);
        float rinv2 = rsqrtf(ss2 * (1.0f / HH) + EPSF);
        #pragma unroll
        for (int u = 0; u < 6; u++) {
            int i = u * 32 + lane;
            g_y[(a * BB + r) * HH + i] = (h3v[u] - mu2) * rinv2 * alng[i] + alnb[i];
        }
    }
}

// ---------------- K4: fused QKV (N=384) tf32 mma -> fp16 q/k/v ----------------
__global__ void __launch_bounds__(512) k4_qkv(
        const float* __restrict__ Wq, const float* __restrict__ bq,
        const float* __restrict__ Wk, const float* __restrict__ bk,
        const float* __restrict__ Wv, const float* __restrict__ bv) {
    int a = blockIdx.x;
    extern __shared__ float sm[];
    float* smA = sm;                      // 64 x 196
    float* ws  = sm + 64 * 196;           // 32 x 392
    int tid = threadIdx.x, lane = tid & 31, wid = tid >> 5;
    int mrow = (wid & 3) * 16, ncol = (wid >> 2) * 96;

    const float4* src = (const float4*)(g_y + a * BB * HH);
    #pragma unroll
    for (int i = 0; i < 6; i++) {
        int f = tid + i * 512;
        int r = f / 48, n4 = (f % 48) * 4;
        *(float4*)(smA + r * 196 + n4) = f2tf4(src[f]);
    }

    float acc[12][4] = {};
    for (int slab = 0; slab < 6; slab++) {
        __syncthreads();
        int kb = slab * 32;
        // 32 rows x 384 cols = 32 x 96 float4 = 3072 f4; 6 per thread
        #pragma unroll
        for (int j = 0; j < 6; j++) {
            int f = tid + j * 512;
            int k = f / 96, n4 = f % 96;
            int mat = n4 / 32, c4 = (n4 % 32) * 4;
            const float* W = (mat == 0) ? Wq : (mat == 1) ? Wk : Wv;
            float4 v = *(const float4*)(W + (kb + k) * AD + c4);
            *(float4*)(ws + k * 392 + n4 * 4) = f2tf4(v);
        }
        __syncthreads();
        #pragma unroll
        for (int ks = 0; ks < 4; ks++) {
            int k0 = ks * 8;
            int ar = mrow + (lane >> 2);
            int ac = kb + k0 + (lane & 3);
            uint32_t a0 = __float_as_uint(smA[ar * 196 + ac]);
            uint32_t a1 = __float_as_uint(smA[(ar + 8) * 196 + ac]);
            uint32_t a2 = __float_as_uint(smA[ar * 196 + ac + 4]);
            uint32_t a3 = __float_as_uint(smA[(ar + 8) * 196 + ac + 4]);
            #pragma unroll
            for (int nt = 0; nt < 12; nt++) {
                int bo = (k0 + (lane & 3)) * 392 + ncol + nt * 8 + (lane >> 2);
                mma_tf32(acc[nt], a0, a1, a2, a3,
                         __float_as_uint(ws[bo]), __float_as_uint(ws[bo + 4 * 392]));
            }
        }
    }

    #pragma unroll
    for (int nt = 0; nt < 12; nt++)
        #pragma unroll
        for (int i = 0; i < 4; i++) {
            int row = mrow + (lane >> 2) + (i >> 1) * 8;
            int col = ncol + nt * 8 + (lane & 3) * 2 + (i & 1);
            float val = acc[nt][i];
            __half* dst; int c;
            if (col < 128)      { val = (val + bq[col]) * 0.25f; c = col;       dst = g_qh; }
            else if (col < 256) { val = val + bk[col - 128];     c = col - 128; dst = g_kh; }
            else                { val = val + bv[col - 256];     c = col - 256; dst = g_vh; }
            dst[(((row * NHD) + (c >> 4)) * AA + a) * HDD + (c & 15)] = __float2half_rn(val);
        }
}

// ---------------- K5: flash attention over agents, fp16 mma ----------------
template<int NTS>
__device__ __forceinline__ void attn_chunk(int jbase, const __half* ks, const __half* vt,
                                           uint32_t qa0, uint32_t qa1, uint32_t qa2, uint32_t qa3,
                                           float* m, float* l, float* o0, float* o1, int lane) {
    float sc[NTS][4];
    #pragma unroll
    for (int nt = 0; nt < NTS; nt++) { sc[nt][0] = sc[nt][1] = sc[nt][2] = sc[nt][3] = 0.f; }
    #pragma unroll
    for (int nt = 0; nt < NTS; nt++) {
        const __half* bp = ks + (jbase + nt * 8 + (lane >> 2)) * 16 + 2 * (lane & 3);
        uint32_t b0 = *(const uint32_t*)bp;
        uint32_t b1 = *(const uint32_t*)(bp + 8);
        mma_f16(sc[nt], qa0, qa1, qa2, qa3, b0, b1);
    }
    float mx0 = -1e30f, mx1 = -1e30f;
    #pragma unroll
    for (int nt = 0; nt < NTS; nt++) {
        mx0 = fmaxf(mx0, fmaxf(sc[nt][0], sc[nt][1]));
        mx1 = fmaxf(mx1, fmaxf(sc[nt][2], sc[nt][3]));
    }
    mx0 = fmaxf(mx0, __shfl_xor_sync(0xffffffffu, mx0, 1));
    mx0 = fmaxf(mx0, __shfl_xor_sync(0xffffffffu, mx0, 2));
    mx1 = fmaxf(mx1, __shfl_xor_sync(0xffffffffu, mx1, 1));
    mx1 = fmaxf(mx1, __shfl_xor_sync(0xffffffffu, mx1, 2));
    float mn0 = fmaxf(m[0], mx0), mn1 = fmaxf(m[1], mx1);
    float f0 = __expf(m[0] - mn0), f1 = __expf(m[1] - mn1);
    float p[NTS][4];
    float sum0 = 0.f, sum1 = 0.f;
    #pragma unroll
    for (int nt = 0; nt < NTS; nt++) {
        p[nt][0] = __expf(sc[nt][0] - mn0);
        p[nt][1] = __expf(sc[nt][1] - mn0);
        p[nt][2] = __expf(sc[nt][2] - mn1);
        p[nt][3] = __expf(sc[nt][3] - mn1);
        sum0 += p[nt][0] + p[nt][1];
        sum1 += p[nt][2] + p[nt][3];
    }
    sum0 += __shfl_xor_sync(0xffffffffu, sum0, 1);
    sum0 += __shfl_xor_sync(0xffffffffu, sum0, 2);
    sum1 += __shfl_xor_sync(0xffffffffu, sum1, 1);
    sum1 += __shfl_xor_sync(0xffffffffu, sum1, 2);
    l[0] = l[0] * f0 + sum0;
    l[1] = l[1] * f1 + sum1;
    o0[0] *= f0; o0[1] *= f0; o0[2] *= f1; o0[3] *= f1;
    o1[0] *= f0; o1[1] *= f0; o1[2] *= f1; o1[3] *= f1;
    m[0] = mn0; m[1] = mn1;
    #pragma unroll
    for (int s = 0; s < NTS / 2; s++) {
        uint32_t pa0 = pack2h(p[2*s][0],   p[2*s][1]);
        uint32_t pa1 = pack2h(p[2*s][2],   p[2*s][3]);
        uint32_t pa2 = pack2h(p[2*s+1][0], p[2*s+1][1]);
        uint32_t pa3 = pack2h(p[2*s+1][2], p[2*s+1][3]);
        #pragma unroll
        for (int d = 0; d < 2; d++) {
            const __half* bp = vt + (d * 8 + (lane >> 2)) * 456 + jbase + 16 * s + 2 * (lane & 3);
            uint32_t b0 = *(const uint32_t*)bp;
            uint32_t b1 = *(const uint32_t*)(bp + 8);
            mma_f16(d ? o1 : o0, pa0, pa1, pa2, pa3, b0, b1);
        }
    }
}

__global__ void __launch_bounds__(128) k5_attn() {
    int bh = blockIdx.x;
    int tid = threadIdx.x, lane = tid & 31, wid = tid >> 5;
    extern __shared__ __half smh[];
    __half* qs = smh;                 // 448 x 16
    __half* ks = smh + 448 * 16;      // 400 x 16
    __half* vt = ks + 400 * 16;       // 16 x 456 (transposed V)

    const __half* qg = g_qh + bh * AA * HDD;
    const __half* kg = g_kh + bh * AA * HDD;
    const __half* vg = g_vh + bh * AA * HDD;

    {
        uint4* qd = (uint4*)qs; const uint4* qsrc = (const uint4*)qg;
        for (int i = tid; i < 800; i += 128) qd[i] = qsrc[i];
        uint4 z; z.x = z.y = z.z = z.w = 0u;
        for (int i = tid; i < 96; i += 128) qd[800 + i] = z;
        uint4* kd = (uint4*)ks; const uint4* ksrc = (const uint4*)kg;
        for (int i = tid; i < 800; i += 128) kd[i] = ksrc[i];
        const __half2* vsrc = (const __half2*)vg;
        for (int i = tid; i < 3200; i += 128) {
            int ag = i >> 3, dd = i & 7;
            __half2 h = vsrc[i];
            vt[(2 * dd) * 456 + ag]     = __low2half(h);
            vt[(2 * dd + 1) * 456 + ag] = __high2half(h);
        }
    }
    __syncthreads();

    for (int p = 0; p < 7; p++) {
        int mrow = p * 64 + wid * 16;
        int r = mrow + (lane >> 2);
        const __half* qp = qs + r * 16 + 2 * (lane & 3);
        uint32_t qa0 = *(const uint32_t*)qp;
        uint32_t qa1 = *(const uint32_t*)(qp + 8 * 16);
        uint32_t qa2 = *(const uint32_t*)(qp + 8);
        uint32_t qa3 = *(const uint32_t*)(qp + 8 * 16 + 8);
        float m[2] = {-1e30f, -1e30f}, l[2] = {0.f, 0.f};
        float o0[4] = {0.f, 0.f, 0.f, 0.f}, o1[4] = {0.f, 0.f, 0.f, 0.f};
        #pragma unroll 1
        for (int c = 0; c < 6; c++)
            attn_chunk<8>(c * 64, ks, vt, qa0, qa1, qa2, qa3, m, l, o0, o1, lane);
        attn_chunk<2>(384, ks, vt, qa0, qa1, qa2, qa3, m, l, o0, o1, lane);

        float i0 = 1.0f / l[0], i1 = 1.0f / l[1];
        int row0 = mrow + (lane >> 2), row1 = row0 + 8;
        int colb = (lane & 3) * 2;
        if (row0 < AA) {
            float* op = g_o + (bh * AA + row0) * HDD;
            op[colb] = o0[0] * i0; op[colb + 1] = o0[1] * i0;
            op[8 + colb] = o1[0] * i0; op[8 + colb + 1] = o1[1] * i0;
        }
        if (row1 < AA) {
            float* op = g_o + (bh * AA + row1) * HDD;
            op[colb] = o0[2] * i1; op[colb + 1] = o0[3] * i1;
            op[8 + colb] = o1[2] * i1; op[8 + colb + 1] = o1[3] * i1;
        }
    }
}

// ---------------- K6: O-proj (tf32 mma) + residual + output head ----------------
__global__ void __launch_bounds__(512) k6_out(
        const float* __restrict__ Wo,   const float* __restrict__ bo,
        const float* __restrict__ Wout, const float* __restrict__ bout,
        float* __restrict__ out) {
    int a = blockIdx.x;
    extern __shared__ float sm[];
    float* smA = sm;                      // 64 x 132
    float* smW = sm + 64 * 132;           // 128 x 200
    float* att = smW + 128 * 200;         // 64 x 192
    int tid = threadIdx.x, lane = tid & 31, wid = tid >> 5;
    int mrow = (wid & 3) * 16, ncol = (wid >> 2) * 48;

    // o gather: 64*128 floats = 2048 f4 (16 contiguous floats per (b,head))
    #pragma unroll
    for (int j = 0; j < 4; j++) {
        int f = tid + j * 512;
        int b = f >> 5, c4 = f & 31;      // 32 f4 per row of 128
        int head = c4 >> 2, d4 = (c4 & 3) * 4;
        float4 v = *(const float4*)(g_o + (((b * NHD) + head) * AA + a) * HDD + d4);
        *(float4*)(smA + b * 132 + c4 * 4) = f2tf4(v);
    }
    // Wo: 128*192 = 6144 f4
    const float4* wg = (const float4*)Wo;
    #pragma unroll
    for (int j = 0; j < 12; j++) {
        int f = tid + j * 512;
        int k = f / 48, n4 = (f % 48) * 4;
        *(float4*)(smW + k * 200 + n4) = f2tf4(wg[f]);
    }
    __syncthreads();

    float acc[6][4] = {};
    #pragma unroll
    for (int ks = 0; ks < 16; ks++) {
        int k0 = ks * 8;
        int ar = mrow + (lane >> 2);
        int ac = k0 + (lane & 3);
        uint32_t a0 = __float_as_uint(smA[ar * 132 + ac]);
        uint32_t a1 = __float_as_uint(smA[(ar + 8) * 132 + ac]);
        uint32_t a2 = __float_as_uint(smA[ar * 132 + ac + 4]);
        uint32_t a3 = __float_as_uint(smA[(ar + 8) * 132 + ac + 4]);
        #pragma unroll
        for (int nt = 0; nt < 6; nt++) {
            int bo2 = (k0 + (lane & 3)) * 200 + ncol + nt * 8 + (lane >> 2);
            mma_tf32(acc[nt], a0, a1, a2, a3,
                     __float_as_uint(smW[bo2]), __float_as_uint(smW[bo2 + 4 * 200]));
        }
    }

    #pragma unroll
    for (int nt = 0; nt < 6; nt++)
        #pragma unroll
        for (int i = 0; i < 4; i++) {
            int row = mrow + (lane >> 2) + (i >> 1) * 8;
            int col = ncol + nt * 8 + (lane & 3) * 2 + (i & 1);
            att[row * HH + col] = g_h3[(a * BB + row) * HH + col] + acc[nt][i] + bo[col];
        }
    __syncthreads();

    if (tid < BB * OO) {
        int b = tid / OO, oo = tid % OO;
        float s = bout[a * OO + oo];
        #pragma unroll 4
        for (int k = 0; k < HH; k++)
            s = fmaf(att[b * HH + k], Wout[(a * HH + k) * OO + oo], s);
        out[(a * BB + b) * OO + oo] = s;
    }
}

// ---------------- host launcher ----------------
extern "C" void kernel_launch(void* const* d_in, const int* in_sizes, int n_in,
                              void* d_out, int out_size) {
    const float* x       = (const float*)d_in[0];
    const float* ln_in_g = (const float*)d_in[1];
    const float* ln_in_b = (const float*)d_in[2];
    const float* W1   = (const float*)d_in[3];
    const float* b1   = (const float*)d_in[4];
    const float* Ws1  = (const float*)d_in[5];
    const float* bs1  = (const float*)d_in[6];
    const float* W2   = (const float*)d_in[7];
    const float* b2   = (const float*)d_in[8];
    const float* Ws2  = (const float*)d_in[9];
    const float* bs2  = (const float*)d_in[10];
    const float* W3   = (const float*)d_in[11];
    const float* b3   = (const float*)d_in[12];
    const float* ln_h_g = (const float*)d_in[13];
    const float* ln_h_b = (const float*)d_in[14];
    const float* Wout = (const float*)d_in[15];
    const float* bout = (const float*)d_in[16];
    const float* aln_g = (const float*)d_in[17];
    const float* aln_b = (const float*)d_in[18];
    const float* Wq = (const float*)d_in[19];
    const float* bq = (const float*)d_in[20];
    const float* Wk = (const float*)d_in[21];
    const float* bk = (const float*)d_in[22];
    const float* Wv = (const float*)d_in[23];
    const float* bv = (const float*)d_in[24];
    const float* Wo = (const float*)d_in[25];
    const float* bo = (const float*)d_in[26];
    float* out = (float*)d_out;

    const int SM1 = (64 * 60 + 2 * 56 * 200) * 4;
    const int SM2 = (64 * 196 + 4 * 32 * 200) * 4;
    const int SM3 = (64 * 196 + 2 * 32 * 200) * 4;
    const int SM4 = (64 * 196 + 32 * 392) * 4;
    const int SM5 = (448 * 16 + 400 * 16 + 16 * 456) * 2;
    const int SM6 = (64 * 132 + 128 * 200 + 64 * 192) * 4;

    cudaFuncSetAttribute(k1_layer1, cudaFuncAttributeMaxDynamicSharedMemorySize, SM1);
    cudaFuncSetAttribute(k2_layer2, cudaFuncAttributeMaxDynamicSharedMemorySize, SM2);
    cudaFuncSetAttribute(k3_layer3, cudaFuncAttributeMaxDynamicSharedMemorySize, SM3);
    cudaFuncSetAttribute(k4_qkv,    cudaFuncAttributeMaxDynamicSharedMemorySize, SM4);
    cudaFuncSetAttribute(k5_attn,   cudaFuncAttributeMaxDynamicSharedMemorySize, SM5);
    cudaFuncSetAttribute(k6_out,    cudaFuncAttributeMaxDynamicSharedMemorySize, SM6);

    k0_xhat  <<<1, 64>>>(x);
    k1_layer1<<<AA, 512, SM1>>>(ln_in_g, ln_in_b, W1, b1, Ws1, bs1);
    k2_layer2<<<AA, 512, SM2>>>(W2, b2, Ws2, bs2);
    k3_layer3<<<AA, 512, SM3>>>(W3, b3, ln_h_g, ln_h_b, aln_g, aln_b);
    k4_qkv   <<<AA, 512, SM4>>>(Wq, bq, Wk, bk, Wv, bv);
    k5_attn  <<<BB * NHD, 128, SM5>>>();
    k6_out   <<<AA, 512, SM6>>>(Wo, bo, Wout, bout, out);
}

// round 7
// speedup vs baseline: 2.8087x; 1.0194x over previous
#include <cuda_runtime.h>
#include <cuda_fp16.h>
#include <math.h>
#include <stdint.h>

#define AA 400
#define BB 64
#define II 50
#define HH 192
#define OO 3
#define AD 128
#define NHD 8
#define HDD 16
#define EPSF 1e-5f

// ---------------- scratch (device globals) ----------------
__device__ __align__(16) float g_xhat[BB * II];
__device__ __align__(16) float g_h1[AA * BB * HH];
__device__ __align__(16) float g_h2[AA * BB * HH];
__device__ __align__(16) float g_h3[AA * BB * HH];
__device__ __align__(16) float g_y [AA * BB * HH];
__device__ __align__(16) __half g_qh[BB * NHD * AA * HDD];   // [b, h, a, d], q pre-scaled by 0.25
__device__ __align__(16) __half g_kh[BB * NHD * AA * HDD];
__device__ __align__(16) __half g_vh[BB * NHD * AA * HDD];
__device__ __align__(16) float  g_o [BB * NHD * AA * HDD];

__device__ __forceinline__ float gelu_exact(float v) {
    return 0.5f * v * (1.0f + erff(v * 0.70710678118654752440f));
}
__device__ __forceinline__ float warp_sum(float v) {
    #pragma unroll
    for (int o = 16; o > 0; o >>= 1) v += __shfl_xor_sync(0xffffffffu, v, o);
    return v;
}
__device__ __forceinline__ float f2tf(float f) {
    uint32_t r;
    asm("cvt.rna.tf32.f32 %0, %1;" : "=r"(r) : "f"(f));
    return __uint_as_float(r);
}
__device__ __forceinline__ uint32_t tfbits(float f) {
    uint32_t r;
    asm("cvt.rna.tf32.f32 %0, %1;" : "=r"(r) : "f"(f));
    return r;
}
__device__ __forceinline__ void cpa16(float* s, const float* g) {
    uint32_t sa = (uint32_t)__cvta_generic_to_shared(s);
    asm volatile("cp.async.cg.shared.global [%0], [%1], 16;" :: "r"(sa), "l"(g));
}
__device__ __forceinline__ void cpa_commit() { asm volatile("cp.async.commit_group;"); }
template<int N>
__device__ __forceinline__ void cpa_wait() { asm volatile("cp.async.wait_group %0;" :: "n"(N)); }

__device__ __forceinline__ void mma_tf32(float* c, uint32_t a0, uint32_t a1, uint32_t a2, uint32_t a3,
                                         uint32_t b0, uint32_t b1) {
    asm volatile("mma.sync.aligned.m16n8k8.row.col.f32.tf32.tf32.f32 "
                 "{%0,%1,%2,%3},{%4,%5,%6,%7},{%8,%9},{%0,%1,%2,%3};"
                 : "+f"(c[0]), "+f"(c[1]), "+f"(c[2]), "+f"(c[3])
                 : "r"(a0), "r"(a1), "r"(a2), "r"(a3), "r"(b0), "r"(b1));
}
__device__ __forceinline__ void mma_f16(float* c, uint32_t a0, uint32_t a1, uint32_t a2, uint32_t a3,
                                        uint32_t b0, uint32_t b1) {
    asm volatile("mma.sync.aligned.m16n8k16.row.col.f32.f16.f16.f32 "
                 "{%0,%1,%2,%3},{%4,%5,%6,%7},{%8,%9},{%0,%1,%2,%3};"
                 : "+f"(c[0]), "+f"(c[1]), "+f"(c[2]), "+f"(c[3])
                 : "r"(a0), "r"(a1), "r"(a2), "r"(a3), "r"(b0), "r"(b1));
}
__device__ __forceinline__ uint32_t pack2h(float x, float y) {
    __half2 h = __floats2half2_rn(x, y);
    return *reinterpret_cast<uint32_t*>(&h);
}

// ---------------- K0: shared input LN stats ----------------
__global__ void __launch_bounds__(64) k0_xhat(const float* __restrict__ x) {
    int b = threadIdx.x;
    if (b >= BB) return;
    float s = 0.f;
    #pragma unroll
    for (int i = 0; i < II; i++) s += x[b * II + i];
    float mu = s * (1.0f / II);
    float vv = 0.f;
    #pragma unroll
    for (int i = 0; i < II; i++) { float d = x[b * II + i] - mu; vv += d * d; }
    float rinv = rsqrtf(vv * (1.0f / II) + EPSF);
    #pragma unroll
    for (int i = 0; i < II; i++) g_xhat[b * II + i] = (x[b * II + i] - mu) * rinv;
}

// ---------------- K1: layer1 dual GEMM, K padded 50->56, cp.async bulk ----------------
__global__ void __launch_bounds__(512) k1_layer1(
        const float* __restrict__ ling, const float* __restrict__ linb,
        const float* __restrict__ W1,  const float* __restrict__ b1,
        const float* __restrict__ Ws1, const float* __restrict__ bs1) {
    int a = blockIdx.x;
    extern __shared__ float sm[];
    float* smA = sm;                      // 64 x 60 (raw xn)
    float* w1s = sm + 64 * 60;            // 56 x 200 (raw)
    float* w2s = w1s + 56 * 200;          // 56 x 200 (raw)
    int tid = threadIdx.x, lane = tid & 31, wid = tid >> 5;
    int mrow = (wid & 3) * 16, ncol = (wid >> 2) * 48;

    const float* w1g = W1  + a * II * HH;
    const float* w2g = Ws1 + a * II * HH;
    for (int f = tid; f < 2400; f += 512) {
        int k = f / 48, n4 = (f % 48) * 4;
        cpa16(w1s + k * 200 + n4, w1g + f * 4);
        cpa16(w2s + k * 200 + n4, w2g + f * 4);
    }
    cpa_commit();

    // zero padding: rows 50..55, cols 192..199
    for (int idx = tid; idx < 6 * 200; idx += 512) { w1s[50 * 200 + idx] = 0.f; w2s[50 * 200 + idx] = 0.f; }
    for (int idx = tid; idx < 50 * 8; idx += 512) {
        int k = idx / 8, c = 192 + (idx % 8);
        w1s[k * 200 + c] = 0.f; w2s[k * 200 + c] = 0.f;
    }
    for (int idx = tid; idx < 64 * 60; idx += 512) {
        int r = idx / 60, c = idx % 60;
        float v = 0.f;
        if (c < II) v = g_xhat[r * II + c] * ling[a * II + c] + linb[a * II + c];
        smA[idx] = v;
    }
    cpa_wait<0>();
    __syncthreads();

    float accA[6][4] = {}, accB[6][4] = {};
    #pragma unroll
    for (int ks = 0; ks < 7; ks++) {
        int k0 = ks * 8;
        int ar = mrow + (lane >> 2);
        int ac = k0 + (lane & 3);
        uint32_t a0 = tfbits(smA[ar * 60 + ac]);
        uint32_t a1 = tfbits(smA[(ar + 8) * 60 + ac]);
        uint32_t a2 = tfbits(smA[ar * 60 + ac + 4]);
        uint32_t a3 = tfbits(smA[(ar + 8) * 60 + ac + 4]);
        #pragma unroll
        for (int nt = 0; nt < 6; nt++) {
            int bo = (k0 + (lane & 3)) * 200 + ncol + nt * 8 + (lane >> 2);
            mma_tf32(accA[nt], a0, a1, a2, a3, tfbits(w1s[bo]), tfbits(w1s[bo + 4 * 200]));
            mma_tf32(accB[nt], a0, a1, a2, a3, tfbits(w2s[bo]), tfbits(w2s[bo + 4 * 200]));
        }
    }

    #pragma unroll
    for (int nt = 0; nt < 6; nt++)
        #pragma unroll
        for (int j = 0; j < 2; j++) {
            int row = mrow + (lane >> 2) + j * 8;
            int col = ncol + nt * 8 + (lane & 3) * 2;
            float va0 = accA[nt][j*2]   + b1 [a * HH + col];
            float va1 = accA[nt][j*2+1] + b1 [a * HH + col + 1];
            float vb0 = accB[nt][j*2]   + bs1[a * HH + col];
            float vb1 = accB[nt][j*2+1] + bs1[a * HH + col + 1];
            float2 o = make_float2(gelu_exact(va0) + vb0, gelu_exact(va1) + vb1);
            *(float2*)(g_h1 + (a * BB + row) * HH + col) = o;
        }
}

// ---------------- K2: layer2 dual GEMM K=192, 3-stage cp.async pipeline ----------------
__device__ __forceinline__ void k2_issue(const float* w1g, const float* w2g, int slab,
                                         float* st, int tid) {
    #pragma unroll
    for (int j = 0; j < 3; j++) {
        int f = tid + j * 512;
        int k = f / 48, n4 = (f % 48) * 4;
        cpa16(st + k * 200 + n4,        w1g + slab * 6144 + f * 4);
        cpa16(st + 6400 + k * 200 + n4, w2g + slab * 6144 + f * 4);
    }
}

__global__ void __launch_bounds__(512) k2_layer2(
        const float* __restrict__ W2,  const float* __restrict__ b2,
        const float* __restrict__ Ws2, const float* __restrict__ bs2) {
    int a = blockIdx.x;
    extern __shared__ float sm[];
    float* smA = sm;                       // 64 x 196 (raw h1)
    float* wst = sm + 64 * 196;            // 3 stages x (2 x 32 x 200)
    int tid = threadIdx.x, lane = tid & 31, wid = tid >> 5;
    int mrow = (wid & 3) * 16, ncol = (wid >> 2) * 48;

    const float* src = g_h1 + a * BB * HH;
    #pragma unroll
    for (int j = 0; j < 6; j++) {
        int f = tid + j * 512;
        int r = f / 48, n4 = (f % 48) * 4;
        cpa16(smA + r * 196 + n4, src + f * 4);
    }
    const float* w1g = W2  + a * HH * HH;
    const float* w2g = Ws2 + a * HH * HH;
    k2_issue(w1g, w2g, 0, wst, tid);
    cpa_commit();                                  // g0 = A + slab0
    k2_issue(w1g, w2g, 1, wst + 12800, tid);
    cpa_commit();                                  // g1 = slab1

    float accA[6][4] = {}, accB[6][4] = {};
    #pragma unroll 1
    for (int slab = 0; slab < 6; slab++) {
        if (slab + 2 < 6) k2_issue(w1g, w2g, slab + 2, wst + ((slab + 2) % 3) * 12800, tid);
        cpa_commit();
        cpa_wait<2>();
        __syncthreads();
        float* cw1 = wst + (slab % 3) * 12800;
        float* cw2 = cw1 + 6400;
        #pragma unroll
        for (int ks = 0; ks < 4; ks++) {
            int k0 = ks * 8;
            int ar = mrow + (lane >> 2);
            int ac = slab * 32 + k0 + (lane & 3);
            uint32_t a0 = tfbits(smA[ar * 196 + ac]);
            uint32_t a1 = tfbits(smA[(ar + 8) * 196 + ac]);
            uint32_t a2 = tfbits(smA[ar * 196 + ac + 4]);
            uint32_t a3 = tfbits(smA[(ar + 8) * 196 + ac + 4]);
            #pragma unroll
            for (int nt = 0; nt < 6; nt++) {
                int bo = (k0 + (lane & 3)) * 200 + ncol + nt * 8 + (lane >> 2);
                mma_tf32(accA[nt], a0, a1, a2, a3, tfbits(cw1[bo]), tfbits(cw1[bo + 4 * 200]));
                mma_tf32(accB[nt], a0, a1, a2, a3, tfbits(cw2[bo]), tfbits(cw2[bo + 4 * 200]));
            }
        }
        __syncthreads();
    }

    #pragma unroll
    for (int nt = 0; nt < 6; nt++)
        #pragma unroll
        for (int j = 0; j < 2; j++) {
            int row = mrow + (lane >> 2) + j * 8;
            int col = ncol + nt * 8 + (lane & 3) * 2;
            float va0 = accA[nt][j*2]   + b2 [a * HH + col];
            float va1 = accA[nt][j*2+1] + b2 [a * HH + col + 1];
            float vb0 = accB[nt][j*2]   + bs2[a * HH + col];
            float vb1 = accB[nt][j*2+1] + bs2[a * HH + col + 1];
            float2 o = make_float2(gelu_exact(va0) + vb0, gelu_exact(va1) + vb1);
            *(float2*)(g_h2 + (a * BB + row) * HH + col) = o;
        }
}

// ---------------- K3: layer3 GEMM (3-stage cp.async) + residual + LN + LN ----------------
__device__ __forceinline__ void k3_issue(const float* wg, int slab, float* st, int tid) {
    #pragma unroll
    for (int j = 0; j < 3; j++) {
        int f = tid + j * 512;
        int k = f / 48, n4 = (f % 48) * 4;
        cpa16(st + k * 200 + n4, wg + slab * 6144 + f * 4);
    }
}

__global__ void __launch_bounds__(512) k3_layer3(
        const float* __restrict__ W3,   const float* __restrict__ b3v,
        const float* __restrict__ lhg,  const float* __restrict__ lhb,
        const float* __restrict__ alng, const float* __restrict__ alnb) {
    int a = blockIdx.x;
    extern __shared__ float sm[];
    float* smA = sm;                       // 64 x 196 (raw h2)
    float* wst = sm + 64 * 196;            // 3 stages x 32 x 200 (reused as tbf 64x192)
    float* tbf = wst;
    int tid = threadIdx.x, lane = tid & 31, wid = tid >> 5;
    int mrow = (wid & 3) * 16, ncol = (wid >> 2) * 48;

    const float* src = g_h2 + a * BB * HH;
    #pragma unroll
    for (int j = 0; j < 6; j++) {
        int f = tid + j * 512;
        int r = f / 48, n4 = (f % 48) * 4;
        cpa16(smA + r * 196 + n4, src + f * 4);
    }
    const float* wg = W3 + a * HH * HH;
    k3_issue(wg, 0, wst, tid);
    cpa_commit();                                  // g0 = A + slab0
    k3_issue(wg, 1, wst + 6400, tid);
    cpa_commit();                                  // g1

    float acc[6][4] = {};
    #pragma unroll 1
    for (int slab = 0; slab < 6; slab++) {
        if (slab + 2 < 6) k3_issue(wg, slab + 2, wst + ((slab + 2) % 3) * 6400, tid);
        cpa_commit();
        cpa_wait<2>();
        __syncthreads();
        float* cw = wst + (slab % 3) * 6400;
        #pragma unroll
        for (int ks = 0; ks < 4; ks++) {
            int k0 = ks * 8;
            int ar = mrow + (lane >> 2);
            int ac = slab * 32 + k0 + (lane & 3);
            uint32_t a0 = tfbits(smA[ar * 196 + ac]);
            uint32_t a1 = tfbits(smA[(ar + 8) * 196 + ac]);
            uint32_t a2 = tfbits(smA[ar * 196 + ac + 4]);
            uint32_t a3 = tfbits(smA[(ar + 8) * 196 + ac + 4]);
            #pragma unroll
            for (int nt = 0; nt < 6; nt++) {
                int bo = (k0 + (lane & 3)) * 200 + ncol + nt * 8 + (lane >> 2);
                mma_tf32(acc[nt], a0, a1, a2, a3, tfbits(cw[bo]), tfbits(cw[bo + 4 * 200]));
            }
        }
        __syncthreads();
    }

    // t = h2 + h2@W3 + b3   (smA holds exact fp32 h2)
    #pragma unroll
    for (int nt = 0; nt < 6; nt++)
        #pragma unroll
        for (int j = 0; j < 2; j++) {
            int row = mrow + (lane >> 2) + j * 8;
            int col = ncol + nt * 8 + (lane & 3) * 2;
            tbf[row * HH + col]     = smA[row * 196 + col]     + acc[nt][j*2]   + b3v[a * HH + col];
            tbf[row * HH + col + 1] = smA[row * 196 + col + 1] + acc[nt][j*2+1] + b3v[a * HH + col + 1];
        }
    __syncthreads();

    for (int r = wid; r < BB; r += 16) {
        float v[6];
        #pragma unroll
        for (int u = 0; u < 6; u++) v[u] = tbf[r * HH + u * 32 + lane];
        float s = 0.f;
        #pragma unroll
        for (int u = 0; u < 6; u++) s += v[u];
        s = warp_sum(s);
        float mu = s * (1.0f / HH);
        float ss = 0.f;
        #pragma unroll
        for (int u = 0; u < 6; u++) { float d = v[u] - mu; ss += d * d; }
        ss = warp_sum(ss);
        float rinv = rsqrtf(ss * (1.0f / HH) + EPSF);

        float h3v[6]; float s2 = 0.f;
        #pragma unroll
        for (int u = 0; u < 6; u++) {
            int i = u * 32 + lane;
            h3v[u] = (v[u] - mu) * rinv * lhg[a * HH + i] + lhb[a * HH + i];
            g_h3[(a * BB + r) * HH + i] = h3v[u];
            s2 += h3v[u];
        }
        s2 = warp_sum(s2);
        float mu2 = s2 * (1.0f / HH);
        float ss2 = 0.f;
        #pragma unroll
        for (int u = 0; u < 6; u++) { float d = h3v[u] - mu2; ss2 += d * d; }
        ss2 = warp_sum(ss2);
        float rinv2 = rsqrtf(ss2 * (1.0f / HH) + EPSF);
        #pragma unroll
        for (int u = 0; u < 6; u++) {
            int i = u * 32 + lane;
            g_y[(a * BB + r) * HH + i] = (h3v[u] - mu2) * rinv2 * alng[i] + alnb[i];
        }
    }
}

// ---------------- K4: fused QKV (N=384), 2-stage cp.async pipeline ----------------
__device__ __forceinline__ void k4_issue(const float* Wq, const float* Wk, const float* Wv,
                                         int slab, float* st, int tid) {
    #pragma unroll
    for (int j = 0; j < 6; j++) {
        int f = tid + j * 512;
        int k = f / 96, n4g = f % 96;
        int mat = n4g / 32, c4 = (n4g % 32) * 4;
        const float* W = (mat == 0) ? Wq : (mat == 1) ? Wk : Wv;
        cpa16(st + k * 392 + n4g * 4, W + (slab * 32 + k) * AD + c4);
    }
}

__global__ void __launch_bounds__(512) k4_qkv(
        const float* __restrict__ Wq, const float* __restrict__ bq,
        const float* __restrict__ Wk, const float* __restrict__ bk,
        const float* __restrict__ Wv, const float* __restrict__ bv) {
    int a = blockIdx.x;
    extern __shared__ float sm[];
    float* smA = sm;                      // 64 x 196 (raw y)
    float* wst = sm + 64 * 196;           // 2 stages x 32 x 392
    int tid = threadIdx.x, lane = tid & 31, wid = tid >> 5;
    int mrow = (wid & 3) * 16, ncol = (wid >> 2) * 96;

    const float* src = g_y + a * BB * HH;
    #pragma unroll
    for (int j = 0; j < 6; j++) {
        int f = tid + j * 512;
        int r = f / 48, n4 = (f % 48) * 4;
        cpa16(smA + r * 196 + n4, src + f * 4);
    }
    k4_issue(Wq, Wk, Wv, 0, wst, tid);
    cpa_commit();                                  // g0 = A + slab0

    float acc[12][4] = {};
    #pragma unroll 1
    for (int slab = 0; slab < 6; slab++) {
        if (slab + 1 < 6) k4_issue(Wq, Wk, Wv, slab + 1, wst + ((slab + 1) & 1) * 12544, tid);
        cpa_commit();
        cpa_wait<1>();
        __syncthreads();
        float* ws = wst + (slab & 1) * 12544;
        #pragma unroll
        for (int ks = 0; ks < 4; ks++) {
            int k0 = ks * 8;
            int ar = mrow + (lane >> 2);
            int ac = slab * 32 + k0 + (lane & 3);
            uint32_t a0 = tfbits(smA[ar * 196 + ac]);
            uint32_t a1 = tfbits(smA[(ar + 8) * 196 + ac]);
            uint32_t a2 = tfbits(smA[ar * 196 + ac + 4]);
            uint32_t a3 = tfbits(smA[(ar + 8) * 196 + ac + 4]);
            #pragma unroll
            for (int nt = 0; nt < 12; nt++) {
                int bo = (k0 + (lane & 3)) * 392 + ncol + nt * 8 + (lane >> 2);
                mma_tf32(acc[nt], a0, a1, a2, a3, tfbits(ws[bo]), tfbits(ws[bo + 4 * 392]));
            }
        }
        __syncthreads();
    }

    #pragma unroll
    for (int nt = 0; nt < 12; nt++)
        #pragma unroll
        for (int i = 0; i < 4; i++) {
            int row = mrow + (lane >> 2) + (i >> 1) * 8;
            int col = ncol + nt * 8 + (lane & 3) * 2 + (i & 1);
            float val = acc[nt][i];
            __half* dst; int c;
            if (col < 128)      { val = (val + bq[col]) * 0.25f; c = col;       dst = g_qh; }
            else if (col < 256) { val = val + bk[col - 128];     c = col - 128; dst = g_kh; }
            else                { val = val + bv[col - 256];     c = col - 256; dst = g_vh; }
            dst[(((row * NHD) + (c >> 4)) * AA + a) * HDD + (c & 15)] = __float2half_rn(val);
        }
}

// ---------------- K5: flash attention over agents, fp16 mma ----------------
template<int NTS>
__device__ __forceinline__ void attn_chunk(int jbase, const __half* ks, const __half* vt,
                                           uint32_t qa0, uint32_t qa1, uint32_t qa2, uint32_t qa3,
                                           float* m, float* l, float* o0, float* o1, int lane) {
    float sc[NTS][4];
    #pragma unroll
    for (int nt = 0; nt < NTS; nt++) { sc[nt][0] = sc[nt][1] = sc[nt][2] = sc[nt][3] = 0.f; }
    #pragma unroll
    for (int nt = 0; nt < NTS; nt++) {
        const __half* bp = ks + (jbase + nt * 8 + (lane >> 2)) * 16 + 2 * (lane & 3);
        uint32_t b0 = *(const uint32_t*)bp;
        uint32_t b1 = *(const uint32_t*)(bp + 8);
        mma_f16(sc[nt], qa0, qa1, qa2, qa3, b0, b1);
    }
    float mx0 = -1e30f, mx1 = -1e30f;
    #pragma unroll
    for (int nt = 0; nt < NTS; nt++) {
        mx0 = fmaxf(mx0, fmaxf(sc[nt][0], sc[nt][1]));
        mx1 = fmaxf(mx1, fmaxf(sc[nt][2], sc[nt][3]));
    }
    mx0 = fmaxf(mx0, __shfl_xor_sync(0xffffffffu, mx0, 1));
    mx0 = fmaxf(mx0, __shfl_xor_sync(0xffffffffu, mx0, 2));
    mx1 = fmaxf(mx1, __shfl_xor_sync(0xffffffffu, mx1, 1));
    mx1 = fmaxf(mx1, __shfl_xor_sync(0xffffffffu, mx1, 2));
    float mn0 = fmaxf(m[0], mx0), mn1 = fmaxf(m[1], mx1);
    float f0 = __expf(m[0] - mn0), f1 = __expf(m[1] - mn1);
    float p[NTS][4];
    float sum0 = 0.f, sum1 = 0.f;
    #pragma unroll
    for (int nt = 0; nt < NTS; nt++) {
        p[nt][0] = __expf(sc[nt][0] - mn0);
        p[nt][1] = __expf(sc[nt][1] - mn0);
        p[nt][2] = __expf(sc[nt][2] - mn1);
        p[nt][3] = __expf(sc[nt][3] - mn1);
        sum0 += p[nt][0] + p[nt][1];
        sum1 += p[nt][2] + p[nt][3];
    }
    sum0 += __shfl_xor_sync(0xffffffffu, sum0, 1);
    sum0 += __shfl_xor_sync(0xffffffffu, sum0, 2);
    sum1 += __shfl_xor_sync(0xffffffffu, sum1, 1);
    sum1 += __shfl_xor_sync(0xffffffffu, sum1, 2);
    l[0] = l[0] * f0 + sum0;
    l[1] = l[1] * f1 + sum1;
    o0[0] *= f0; o0[1] *= f0; o0[2] *= f1; o0[3] *= f1;
    o1[0] *= f0; o1[1] *= f0; o1[2] *= f1; o1[3] *= f1;
    m[0] = mn0; m[1] = mn1;
    #pragma unroll
    for (int s = 0; s < NTS / 2; s++) {
        uint32_t pa0 = pack2h(p[2*s][0],   p[2*s][1]);
        uint32_t pa1 = pack2h(p[2*s][2],   p[2*s][3]);
        uint32_t pa2 = pack2h(p[2*s+1][0], p[2*s+1][1]);
        uint32_t pa3 = pack2h(p[2*s+1][2], p[2*s+1][3]);
        #pragma unroll
        for (int d = 0; d < 2; d++) {
            const __half* bp = vt + (d * 8 + (lane >> 2)) * 456 + jbase + 16 * s + 2 * (lane & 3);
            uint32_t b0 = *(const uint32_t*)bp;
            uint32_t b1 = *(const uint32_t*)(bp + 8);
            mma_f16(d ? o1 : o0, pa0, pa1, pa2, pa3, b0, b1);
        }
    }
}

__global__ void __launch_bounds__(128) k5_attn() {
    int bh = blockIdx.x;
    int tid = threadIdx.x, lane = tid & 31, wid = tid >> 5;
    extern __shared__ __half smh[];
    __half* qs = smh;                 // 448 x 16
    __half* ks = smh + 448 * 16;      // 400 x 16
    __half* vt = ks + 400 * 16;       // 16 x 456 (transposed V)

    const __half* qg = g_qh + bh * AA * HDD;
    const __half* kg = g_kh + bh * AA * HDD;
    const __half* vg = g_vh + bh * AA * HDD;

    {
        uint4* qd = (uint4*)qs; const uint4* qsrc = (const uint4*)qg;
        for (int i = tid; i < 800; i += 128) qd[i] = qsrc[i];
        uint4 z; z.x = z.y = z.z = z.w = 0u;
        for (int i = tid; i < 96; i += 128) qd[800 + i] = z;
        uint4* kd = (uint4*)ks; const uint4* ksrc = (const uint4*)kg;
        for (int i = tid; i < 800; i += 128) kd[i] = ksrc[i];
        const __half2* vsrc = (const __half2*)vg;
        for (int i = tid; i < 3200; i += 128) {
            int ag = i >> 3, dd = i & 7;
            __half2 h = vsrc[i];
            vt[(2 * dd) * 456 + ag]     = __low2half(h);
            vt[(2 * dd + 1) * 456 + ag] = __high2half(h);
        }
    }
    __syncthreads();

    for (int p = 0; p < 7; p++) {
        int mrow = p * 64 + wid * 16;
        int r = mrow + (lane >> 2);
        const __half* qp = qs + r * 16 + 2 * (lane & 3);
        uint32_t qa0 = *(const uint32_t*)qp;
        uint32_t qa1 = *(const uint32_t*)(qp + 8 * 16);
        uint32_t qa2 = *(const uint32_t*)(qp + 8);
        uint32_t qa3 = *(const uint32_t*)(qp + 8 * 16 + 8);
        float m[2] = {-1e30f, -1e30f}, l[2] = {0.f, 0.f};
        float o0[4] = {0.f, 0.f, 0.f, 0.f}, o1[4] = {0.f, 0.f, 0.f, 0.f};
        #pragma unroll 1
        for (int c = 0; c < 6; c++)
            attn_chunk<8>(c * 64, ks, vt, qa0, qa1, qa2, qa3, m, l, o0, o1, lane);
        attn_chunk<2>(384, ks, vt, qa0, qa1, qa2, qa3, m, l, o0, o1, lane);

        float i0 = 1.0f / l[0], i1 = 1.0f / l[1];
        int row0 = mrow + (lane >> 2), row1 = row0 + 8;
        int colb = (lane & 3) * 2;
        if (row0 < AA) {
            float* op = g_o + (bh * AA + row0) * HDD;
            op[colb] = o0[0] * i0; op[colb + 1] = o0[1] * i0;
            op[8 + colb] = o1[0] * i0; op[8 + colb + 1] = o1[1] * i0;
        }
        if (row1 < AA) {
            float* op = g_o + (bh * AA + row1) * HDD;
            op[colb] = o0[2] * i1; op[colb + 1] = o0[3] * i1;
            op[8 + colb] = o1[2] * i1; op[8 + colb + 1] = o1[3] * i1;
        }
    }
}

// ---------------- K6: O-proj (tf32 mma) + residual + output head ----------------
__global__ void __launch_bounds__(512) k6_out(
        const float* __restrict__ Wo,   const float* __restrict__ bo,
        const float* __restrict__ Wout, const float* __restrict__ bout,
        float* __restrict__ out) {
    int a = blockIdx.x;
    extern __shared__ float sm[];
    float* smA = sm;                      // 64 x 132 (raw o)
    float* smW = sm + 64 * 132;           // 128 x 200 (raw Wo)
    float* att = smW + 128 * 200;         // 64 x 192
    int tid = threadIdx.x, lane = tid & 31, wid = tid >> 5;
    int mrow = (wid & 3) * 16, ncol = (wid >> 2) * 48;

    // o gather: 2048 f4 (16B chunks contiguous per (b,head))
    #pragma unroll
    for (int j = 0; j < 4; j++) {
        int f = tid + j * 512;
        int b = f >> 5, c4 = f & 31;
        int head = c4 >> 2, d4 = (c4 & 3) * 4;
        cpa16(smA + b * 132 + c4 * 4, g_o + (((b * NHD) + head) * AA + a) * HDD + d4);
    }
    // Wo: 6144 f4
    #pragma unroll
    for (int j = 0; j < 12; j++) {
        int f = tid + j * 512;
        int k = f / 48, n4 = (f % 48) * 4;
        cpa16(smW + k * 200 + n4, Wo + f * 4);
    }
    cpa_commit();
    cpa_wait<0>();
    __syncthreads();

    float acc[6][4] = {};
    #pragma unroll
    for (int ks = 0; ks < 16; ks++) {
        int k0 = ks * 8;
        int ar = mrow + (lane >> 2);
        int ac = k0 + (lane & 3);
        uint32_t a0 = tfbits(smA[ar * 132 + ac]);
        uint32_t a1 = tfbits(smA[(ar + 8) * 132 + ac]);
        uint32_t a2 = tfbits(smA[ar * 132 + ac + 4]);
        uint32_t a3 = tfbits(smA[(ar + 8) * 132 + ac + 4]);
        #pragma unroll
        for (int nt = 0; nt < 6; nt++) {
            int bo2 = (k0 + (lane & 3)) * 200 + ncol + nt * 8 + (lane >> 2);
            mma_tf32(acc[nt], a0, a1, a2, a3, tfbits(smW[bo2]), tfbits(smW[bo2 + 4 * 200]));
        }
    }

    #pragma unroll
    for (int nt = 0; nt < 6; nt++)
        #pragma unroll
        for (int i = 0; i < 4; i++) {
            int row = mrow + (lane >> 2) + (i >> 1) * 8;
            int col = ncol + nt * 8 + (lane & 3) * 2 + (i & 1);
            att[row * HH + col] = g_h3[(a * BB + row) * HH + col] + acc[nt][i] + bo[col];
        }
    __syncthreads();

    if (tid < BB * OO) {
        int b = tid / OO, oo = tid % OO;
        float s = bout[a * OO + oo];
        #pragma unroll 4
        for (int k = 0; k < HH; k++)
            s = fmaf(att[b * HH + k], Wout[(a * HH + k) * OO + oo], s);
        out[(a * BB + b) * OO + oo] = s;
    }
}

// ---------------- host launcher ----------------
extern "C" void kernel_launch(void* const* d_in, const int* in_sizes, int n_in,
                              void* d_out, int out_size) {
    const float* x       = (const float*)d_in[0];
    const float* ln_in_g = (const float*)d_in[1];
    const float* ln_in_b = (const float*)d_in[2];
    const float* W1   = (const float*)d_in[3];
    const float* b1   = (const float*)d_in[4];
    const float* Ws1  = (const float*)d_in[5];
    const float* bs1  = (const float*)d_in[6];
    const float* W2   = (const float*)d_in[7];
    const float* b2   = (const float*)d_in[8];
    const float* Ws2  = (const float*)d_in[9];
    const float* bs2  = (const float*)d_in[10];
    const float* W3   = (const float*)d_in[11];
    const float* b3   = (const float*)d_in[12];
    const float* ln_h_g = (const float*)d_in[13];
    const float* ln_h_b = (const float*)d_in[14];
    const float* Wout = (const float*)d_in[15];
    const float* bout = (const float*)d_in[16];
    const float* aln_g = (const float*)d_in[17];
    const float* aln_b = (const float*)d_in[18];
    const float* Wq = (const float*)d_in[19];
    const float* bq = (const float*)d_in[20];
    const float* Wk = (const float*)d_in[21];
    const float* bk = (const float*)d_in[22];
    const float* Wv = (const float*)d_in[23];
    const float* bv = (const float*)d_in[24];
    const float* Wo = (const float*)d_in[25];
    const float* bo = (const float*)d_in[26];
    float* out = (float*)d_out;

    const int SM1 = (64 * 60 + 2 * 56 * 200) * 4;
    const int SM2 = (64 * 196 + 3 * 2 * 32 * 200) * 4;
    const int SM3 = (64 * 196 + 3 * 32 * 200) * 4;
    const int SM4 = (64 * 196 + 2 * 32 * 392) * 4;
    const int SM5 = (448 * 16 + 400 * 16 + 16 * 456) * 2;
    const int SM6 = (64 * 132 + 128 * 200 + 64 * 192) * 4;

    cudaFuncSetAttribute(k1_layer1, cudaFuncAttributeMaxDynamicSharedMemorySize, SM1);
    cudaFuncSetAttribute(k2_layer2, cudaFuncAttributeMaxDynamicSharedMemorySize, SM2);
    cudaFuncSetAttribute(k3_layer3, cudaFuncAttributeMaxDynamicSharedMemorySize, SM3);
    cudaFuncSetAttribute(k4_qkv,    cudaFuncAttributeMaxDynamicSharedMemorySize, SM4);
    cudaFuncSetAttribute(k5_attn,   cudaFuncAttributeMaxDynamicSharedMemorySize, SM5);
    cudaFuncSetAttribute(k6_out,    cudaFuncAttributeMaxDynamicSharedMemorySize, SM6);

    k0_xhat  <<<1, 64>>>(x);
    k1_layer1<<<AA, 512, SM1>>>(ln_in_g, ln_in_b, W1, b1, Ws1, bs1);
    k2_layer2<<<AA, 512, SM2>>>(W2, b2, Ws2, bs2);
    k3_layer3<<<AA, 512, SM3>>>(W3, b3, ln_h_g, ln_h_b, aln_g, aln_b);
    k4_qkv   <<<AA, 512, SM4>>>(Wq, bq, Wk, bk, Wv, bv);
    k5_attn  <<<BB * NHD, 128, SM5>>>();
    k6_out   <<<AA, 512, SM6>>>(Wo, bo, Wout, bout, out);
}

// round 8
// speedup vs baseline: 3.0311x; 1.0792x over previous
#include <cuda_runtime.h>
#include <cuda_fp16.h>
#include <math.h>
#include <stdint.h>

#define AA 400
#define BB 64
#define II 50
#define HH 192
#define OO 3
#define AD 128
#define NHD 8
#define HDD 16
#define EPSF 1e-5f

// ---------------- scratch (device globals) ----------------
__device__ __align__(16) float g_xhat[BB * II];
__device__ __align__(16) float g_h3[AA * BB * HH];
__device__ __align__(16) __half g_qh[BB * NHD * AA * HDD];   // [b, h, a, d], q pre-scaled by 0.25
__device__ __align__(16) __half g_kh[BB * NHD * AA * HDD];
__device__ __align__(16) __half g_vh[BB * NHD * AA * HDD];
__device__ __align__(16) float  g_o [BB * NHD * AA * HDD];

__device__ __forceinline__ float gelu_exact(float v) {
    return 0.5f * v * (1.0f + erff(v * 0.70710678118654752440f));
}
__device__ __forceinline__ float warp_sum(float v) {
    #pragma unroll
    for (int o = 16; o > 0; o >>= 1) v += __shfl_xor_sync(0xffffffffu, v, o);
    return v;
}
__device__ __forceinline__ uint32_t tfbits(float f) {
    uint32_t r;
    asm("cvt.rna.tf32.f32 %0, %1;" : "=r"(r) : "f"(f));
    return r;
}
__device__ __forceinline__ void cpa16(float* s, const float* g) {
    uint32_t sa = (uint32_t)__cvta_generic_to_shared(s);
    asm volatile("cp.async.cg.shared.global [%0], [%1], 16;" :: "r"(sa), "l"(g));
}
__device__ __forceinline__ void cpa_commit() { asm volatile("cp.async.commit_group;"); }
template<int N>
__device__ __forceinline__ void cpa_wait() { asm volatile("cp.async.wait_group %0;" :: "n"(N)); }

__device__ __forceinline__ void mma_tf32(float* c, uint32_t a0, uint32_t a1, uint32_t a2, uint32_t a3,
                                         uint32_t b0, uint32_t b1) {
    asm volatile("mma.sync.aligned.m16n8k8.row.col.f32.tf32.tf32.f32 "
                 "{%0,%1,%2,%3},{%4,%5,%6,%7},{%8,%9},{%0,%1,%2,%3};"
                 : "+f"(c[0]), "+f"(c[1]), "+f"(c[2]), "+f"(c[3])
                 : "r"(a0), "r"(a1), "r"(a2), "r"(a3), "r"(b0), "r"(b1));
}
__device__ __forceinline__ void mma_f16(float* c, uint32_t a0, uint32_t a1, uint32_t a2, uint32_t a3,
                                        uint32_t b0, uint32_t b1) {
    asm volatile("mma.sync.aligned.m16n8k16.row.col.f32.f16.f16.f32 "
                 "{%0,%1,%2,%3},{%4,%5,%6,%7},{%8,%9},{%0,%1,%2,%3};"
                 : "+f"(c[0]), "+f"(c[1]), "+f"(c[2]), "+f"(c[3])
                 : "r"(a0), "r"(a1), "r"(a2), "r"(a3), "r"(b0), "r"(b1));
}
__device__ __forceinline__ uint32_t pack2h(float x, float y) {
    __half2 h = __floats2half2_rn(x, y);
    return *reinterpret_cast<uint32_t*>(&h);
}

// ---------------- K0: shared input LN stats ----------------
__global__ void __launch_bounds__(64) k0_xhat(const float* __restrict__ x) {
    int b = threadIdx.x;
    if (b >= BB) return;
    float s = 0.f;
    #pragma unroll
    for (int i = 0; i < II; i++) s += x[b * II + i];
    float mu = s * (1.0f / II);
    float vv = 0.f;
    #pragma unroll
    for (int i = 0; i < II; i++) { float d = x[b * II + i] - mu; vv += d * d; }
    float rinv = rsqrtf(vv * (1.0f / II) + EPSF);
    #pragma unroll
    for (int i = 0; i < II; i++) g_xhat[b * II + i] = (x[b * II + i] - mu) * rinv;
}

// ================= Fused per-agent MLP + LN + QKV kernel =================
// smem layout (floats):
//   bufX = [0, 12544)        activation ping (stride 196; layer1 uses stride 60)
//   bufY = [12544, 25088)    activation pong
//   wst  = [25088, 50688)    weight stream, 2 stages x 12800
__global__ void __launch_bounds__(512) kf_mlp(
        const float* __restrict__ ling, const float* __restrict__ linb,
        const float* __restrict__ W1,  const float* __restrict__ b1,
        const float* __restrict__ Ws1, const float* __restrict__ bs1,
        const float* __restrict__ W2,  const float* __restrict__ b2,
        const float* __restrict__ Ws2, const float* __restrict__ bs2,
        const float* __restrict__ W3,  const float* __restrict__ b3v,
        const float* __restrict__ lhg,  const float* __restrict__ lhb,
        const float* __restrict__ alng, const float* __restrict__ alnb,
        const float* __restrict__ Wq, const float* __restrict__ bq,
        const float* __restrict__ Wk, const float* __restrict__ bk,
        const float* __restrict__ Wv, const float* __restrict__ bv) {
    int a = blockIdx.x;
    extern __shared__ float sm[];
    float* bufX = sm;
    float* bufY = sm + 12544;
    float* wst  = sm + 25088;
    float* st0  = wst;
    float* st1  = wst + 12800;
    int tid = threadIdx.x, lane = tid & 31, wid = tid >> 5;
    int mrow = (wid & 3) * 16, ncol = (wid >> 2) * 48;

    // ---------- Layer 1 ----------
    {
        const float* w1g = W1  + a * II * HH;
        const float* w2g = Ws1 + a * II * HH;
        for (int f = tid; f < 2400; f += 512) {
            int k = f / 48, n4 = (f % 48) * 4;
            cpa16(st0 + k * 200 + n4, w1g + f * 4);
            cpa16(st1 + k * 200 + n4, w2g + f * 4);
        }
        cpa_commit();
        // zero padding: rows 50..55 all cols; cols 192..199 rows 0..49
        for (int idx = tid; idx < 6 * 200; idx += 512) { st0[50 * 200 + idx] = 0.f; st1[50 * 200 + idx] = 0.f; }
        for (int idx = tid; idx < 50 * 8; idx += 512) {
            int k = idx / 8, c = 192 + (idx % 8);
            st0[k * 200 + c] = 0.f; st1[k * 200 + c] = 0.f;
        }
        // xn into bufX (stride 60)
        for (int idx = tid; idx < 64 * 60; idx += 512) {
            int r = idx / 60, c = idx % 60;
            float v = 0.f;
            if (c < II) v = g_xhat[r * II + c] * ling[a * II + c] + linb[a * II + c];
            bufX[idx] = v;
        }
        cpa_wait<0>();
        __syncthreads();

        float accA[6][4] = {}, accB[6][4] = {};
        #pragma unroll
        for (int ks = 0; ks < 7; ks++) {
            int k0 = ks * 8;
            int ar = mrow + (lane >> 2);
            int ac = k0 + (lane & 3);
            uint32_t a0 = tfbits(bufX[ar * 60 + ac]);
            uint32_t a1 = tfbits(bufX[(ar + 8) * 60 + ac]);
            uint32_t a2 = tfbits(bufX[ar * 60 + ac + 4]);
            uint32_t a3 = tfbits(bufX[(ar + 8) * 60 + ac + 4]);
            #pragma unroll
            for (int nt = 0; nt < 6; nt++) {
                int bo = (k0 + (lane & 3)) * 200 + ncol + nt * 8 + (lane >> 2);
                mma_tf32(accA[nt], a0, a1, a2, a3, tfbits(st0[bo]), tfbits(st0[bo + 4 * 200]));
                mma_tf32(accB[nt], a0, a1, a2, a3, tfbits(st1[bo]), tfbits(st1[bo + 4 * 200]));
            }
        }
        __syncthreads();   // done with bufX(xn) reads and weight stages
        #pragma unroll
        for (int nt = 0; nt < 6; nt++)
            #pragma unroll
            for (int j = 0; j < 2; j++) {
                int row = mrow + (lane >> 2) + j * 8;
                int col = ncol + nt * 8 + (lane & 3) * 2;
                float va0 = accA[nt][j*2]   + b1 [a * HH + col];
                float va1 = accA[nt][j*2+1] + b1 [a * HH + col + 1];
                float vb0 = accB[nt][j*2]   + bs1[a * HH + col];
                float vb1 = accB[nt][j*2+1] + bs1[a * HH + col + 1];
                bufY[row * 196 + col]     = gelu_exact(va0) + vb0;
                bufY[row * 196 + col + 1] = gelu_exact(va1) + vb1;
            }
        __syncthreads();
    }

    // ---------- Layer 2 (A = bufY, out -> bufX) ----------
    {
        const float* w1g = W2  + a * HH * HH;
        const float* w2g = Ws2 + a * HH * HH;
        // issue slab0 into stage0
        #pragma unroll
        for (int j = 0; j < 3; j++) {
            int f = tid + j * 512;
            int k = f / 48, n4 = (f % 48) * 4;
            cpa16(st0 + k * 200 + n4,        w1g + f * 4);
            cpa16(st0 + 6400 + k * 200 + n4, w2g + f * 4);
        }
        cpa_commit();

        float accA[6][4] = {}, accB[6][4] = {};
        #pragma unroll 1
        for (int slab = 0; slab < 6; slab++) {
            if (slab + 1 < 6) {
                float* ns = (slab & 1) ? st0 : st1;
                #pragma unroll
                for (int j = 0; j < 3; j++) {
                    int f = tid + j * 512;
                    int k = f / 48, n4 = (f % 48) * 4;
                    cpa16(ns + k * 200 + n4,        w1g + (slab + 1) * 6144 + f * 4);
                    cpa16(ns + 6400 + k * 200 + n4, w2g + (slab + 1) * 6144 + f * 4);
                }
            }
            cpa_commit();
            cpa_wait<1>();
            __syncthreads();
            float* cw1 = (slab & 1) ? st1 : st0;
            float* cw2 = cw1 + 6400;
            #pragma unroll
            for (int ks = 0; ks < 4; ks++) {
                int k0 = ks * 8;
                int ar = mrow + (lane >> 2);
                int ac = slab * 32 + k0 + (lane & 3);
                uint32_t a0 = tfbits(bufY[ar * 196 + ac]);
                uint32_t a1 = tfbits(bufY[(ar + 8) * 196 + ac]);
                uint32_t a2 = tfbits(bufY[ar * 196 + ac + 4]);
                uint32_t a3 = tfbits(bufY[(ar + 8) * 196 + ac + 4]);
                #pragma unroll
                for (int nt = 0; nt < 6; nt++) {
                    int bo = (k0 + (lane & 3)) * 200 + ncol + nt * 8 + (lane >> 2);
                    mma_tf32(accA[nt], a0, a1, a2, a3, tfbits(cw1[bo]), tfbits(cw1[bo + 4 * 200]));
                    mma_tf32(accB[nt], a0, a1, a2, a3, tfbits(cw2[bo]), tfbits(cw2[bo + 4 * 200]));
                }
            }
            __syncthreads();
        }
        #pragma unroll
        for (int nt = 0; nt < 6; nt++)
            #pragma unroll
            for (int j = 0; j < 2; j++) {
                int row = mrow + (lane >> 2) + j * 8;
                int col = ncol + nt * 8 + (lane & 3) * 2;
                float va0 = accA[nt][j*2]   + b2 [a * HH + col];
                float va1 = accA[nt][j*2+1] + b2 [a * HH + col + 1];
                float vb0 = accB[nt][j*2]   + bs2[a * HH + col];
                float vb1 = accB[nt][j*2+1] + bs2[a * HH + col + 1];
                bufX[row * 196 + col]     = gelu_exact(va0) + vb0;
                bufX[row * 196 + col + 1] = gelu_exact(va1) + vb1;
            }
        __syncthreads();
    }

    // ---------- Layer 3 (A = bufX = exact h2) + residual + LN + LN ----------
    {
        const float* wg = W3 + a * HH * HH;
        #pragma unroll
        for (int j = 0; j < 3; j++) {
            int f = tid + j * 512;
            int k = f / 48, n4 = (f % 48) * 4;
            cpa16(st0 + k * 200 + n4, wg + f * 4);
        }
        cpa_commit();

        float acc[6][4] = {};
        #pragma unroll 1
        for (int slab = 0; slab < 6; slab++) {
            if (slab + 1 < 6) {
                float* ns = (slab & 1) ? st0 : st1;
                #pragma unroll
                for (int j = 0; j < 3; j++) {
                    int f = tid + j * 512;
                    int k = f / 48, n4 = (f % 48) * 4;
                    cpa16(ns + k * 200 + n4, wg + (slab + 1) * 6144 + f * 4);
                }
            }
            cpa_commit();
            cpa_wait<1>();
            __syncthreads();
            float* cw = (slab & 1) ? st1 : st0;
            #pragma unroll
            for (int ks = 0; ks < 4; ks++) {
                int k0 = ks * 8;
                int ar = mrow + (lane >> 2);
                int ac = slab * 32 + k0 + (lane & 3);
                uint32_t a0 = tfbits(bufX[ar * 196 + ac]);
                uint32_t a1 = tfbits(bufX[(ar + 8) * 196 + ac]);
                uint32_t a2 = tfbits(bufX[ar * 196 + ac + 4]);
                uint32_t a3 = tfbits(bufX[(ar + 8) * 196 + ac + 4]);
                #pragma unroll
                for (int nt = 0; nt < 6; nt++) {
                    int bo = (k0 + (lane & 3)) * 200 + ncol + nt * 8 + (lane >> 2);
                    mma_tf32(acc[nt], a0, a1, a2, a3, tfbits(cw[bo]), tfbits(cw[bo + 4 * 200]));
                }
            }
            __syncthreads();
        }

        float* tbf = wst;   // 64 x 196, fits in stage region
        #pragma unroll
        for (int nt = 0; nt < 6; nt++)
            #pragma unroll
            for (int j = 0; j < 2; j++) {
                int row = mrow + (lane >> 2) + j * 8;
                int col = ncol + nt * 8 + (lane & 3) * 2;
                tbf[row * 196 + col]     = bufX[row * 196 + col]     + acc[nt][j*2]   + b3v[a * HH + col];
                tbf[row * 196 + col + 1] = bufX[row * 196 + col + 1] + acc[nt][j*2+1] + b3v[a * HH + col + 1];
            }
        __syncthreads();

        for (int r = wid; r < BB; r += 16) {
            float v[6];
            #pragma unroll
            for (int u = 0; u < 6; u++) v[u] = tbf[r * 196 + u * 32 + lane];
            float s = 0.f;
            #pragma unroll
            for (int u = 0; u < 6; u++) s += v[u];
            s = warp_sum(s);
            float mu = s * (1.0f / HH);
            float ss = 0.f;
            #pragma unroll
            for (int u = 0; u < 6; u++) { float d = v[u] - mu; ss += d * d; }
            ss = warp_sum(ss);
            float rinv = rsqrtf(ss * (1.0f / HH) + EPSF);

            float h3v[6]; float s2 = 0.f;
            #pragma unroll
            for (int u = 0; u < 6; u++) {
                int i = u * 32 + lane;
                h3v[u] = (v[u] - mu) * rinv * lhg[a * HH + i] + lhb[a * HH + i];
                g_h3[(a * BB + r) * HH + i] = h3v[u];
                s2 += h3v[u];
            }
            s2 = warp_sum(s2);
            float mu2 = s2 * (1.0f / HH);
            float ss2 = 0.f;
            #pragma unroll
            for (int u = 0; u < 6; u++) { float d = h3v[u] - mu2; ss2 += d * d; }
            ss2 = warp_sum(ss2);
            float rinv2 = rsqrtf(ss2 * (1.0f / HH) + EPSF);
            #pragma unroll
            for (int u = 0; u < 6; u++) {
                int i = u * 32 + lane;
                bufY[r * 196 + i] = (h3v[u] - mu2) * rinv2 * alng[i] + alnb[i];
            }
        }
        __syncthreads();
    }

    // ---------- QKV (A = bufY = y) ----------
    {
        int ncolq = (wid >> 2) * 96;
        // issue slab0 into stage0 (32 x 392)
        #pragma unroll
        for (int j = 0; j < 6; j++) {
            int f = tid + j * 512;
            int k = f / 96, n4g = f % 96;
            int mat = n4g / 32, c4 = (n4g % 32) * 4;
            const float* W = (mat == 0) ? Wq : (mat == 1) ? Wk : Wv;
            cpa16(st0 + k * 392 + n4g * 4, W + k * AD + c4);
        }
        cpa_commit();

        float acc[12][4] = {};
        #pragma unroll 1
        for (int slab = 0; slab < 6; slab++) {
            if (slab + 1 < 6) {
                float* ns = (slab & 1) ? st0 : st1;
                #pragma unroll
                for (int j = 0; j < 6; j++) {
                    int f = tid + j * 512;
                    int k = f / 96, n4g = f % 96;
                    int mat = n4g / 32, c4 = (n4g % 32) * 4;
                    const float* W = (mat == 0) ? Wq : (mat == 1) ? Wk : Wv;
                    cpa16(ns + k * 392 + n4g * 4, W + ((slab + 1) * 32 + k) * AD + c4);
                }
            }
            cpa_commit();
            cpa_wait<1>();
            __syncthreads();
            float* ws = (slab & 1) ? st1 : st0;
            #pragma unroll
            for (int ks = 0; ks < 4; ks++) {
                int k0 = ks * 8;
                int ar = mrow + (lane >> 2);
                int ac = slab * 32 + k0 + (lane & 3);
                uint32_t a0 = tfbits(bufY[ar * 196 + ac]);
                uint32_t a1 = tfbits(bufY[(ar + 8) * 196 + ac]);
                uint32_t a2 = tfbits(bufY[ar * 196 + ac + 4]);
                uint32_t a3 = tfbits(bufY[(ar + 8) * 196 + ac + 4]);
                #pragma unroll
                for (int nt = 0; nt < 12; nt++) {
                    int bo = (k0 + (lane & 3)) * 392 + ncolq + nt * 8 + (lane >> 2);
                    mma_tf32(acc[nt], a0, a1, a2, a3, tfbits(ws[bo]), tfbits(ws[bo + 4 * 392]));
                }
            }
            __syncthreads();
        }

        #pragma unroll
        for (int nt = 0; nt < 12; nt++)
            #pragma unroll
            for (int i = 0; i < 4; i++) {
                int row = mrow + (lane >> 2) + (i >> 1) * 8;
                int col = ncolq + nt * 8 + (lane & 3) * 2 + (i & 1);
                float val = acc[nt][i];
                __half* dst; int c;
                if (col < 128)      { val = (val + bq[col]) * 0.25f; c = col;       dst = g_qh; }
                else if (col < 256) { val = val + bk[col - 128];     c = col - 128; dst = g_kh; }
                else                { val = val + bv[col - 256];     c = col - 256; dst = g_vh; }
                dst[(((row * NHD) + (c >> 4)) * AA + a) * HDD + (c & 15)] = __float2half_rn(val);
            }
    }
}

// ---------------- K5: flash attention over agents, fp16 mma ----------------
template<int NTS>
__device__ __forceinline__ void attn_chunk(int jbase, const __half* ks, const __half* vt,
                                           uint32_t qa0, uint32_t qa1, uint32_t qa2, uint32_t qa3,
                                           float* m, float* l, float* o0, float* o1, int lane) {
    float sc[NTS][4];
    #pragma unroll
    for (int nt = 0; nt < NTS; nt++) { sc[nt][0] = sc[nt][1] = sc[nt][2] = sc[nt][3] = 0.f; }
    #pragma unroll
    for (int nt = 0; nt < NTS; nt++) {
        const __half* bp = ks + (jbase + nt * 8 + (lane >> 2)) * 16 + 2 * (lane & 3);
        uint32_t b0 = *(const uint32_t*)bp;
        uint32_t b1 = *(const uint32_t*)(bp + 8);
        mma_f16(sc[nt], qa0, qa1, qa2, qa3, b0, b1);
    }
    float mx0 = -1e30f, mx1 = -1e30f;
    #pragma unroll
    for (int nt = 0; nt < NTS; nt++) {
        mx0 = fmaxf(mx0, fmaxf(sc[nt][0], sc[nt][1]));
        mx1 = fmaxf(mx1, fmaxf(sc[nt][2], sc[nt][3]));
    }
    mx0 = fmaxf(mx0, __shfl_xor_sync(0xffffffffu, mx0, 1));
    mx0 = fmaxf(mx0, __shfl_xor_sync(0xffffffffu, mx0, 2));
    mx1 = fmaxf(mx1, __shfl_xor_sync(0xffffffffu, mx1, 1));
    mx1 = fmaxf(mx1, __shfl_xor_sync(0xffffffffu, mx1, 2));
    float mn0 = fmaxf(m[0], mx0), mn1 = fmaxf(m[1], mx1);
    float f0 = __expf(m[0] - mn0), f1 = __expf(m[1] - mn1);
    float p[NTS][4];
    float sum0 = 0.f, sum1 = 0.f;
    #pragma unroll
    for (int nt = 0; nt < NTS; nt++) {
        p[nt][0] = __expf(sc[nt][0] - mn0);
        p[nt][1] = __expf(sc[nt][1] - mn0);
        p[nt][2] = __expf(sc[nt][2] - mn1);
        p[nt][3] = __expf(sc[nt][3] - mn1);
        sum0 += p[nt][0] + p[nt][1];
        sum1 += p[nt][2] + p[nt][3];
    }
    sum0 += __shfl_xor_sync(0xffffffffu, sum0, 1);
    sum0 += __shfl_xor_sync(0xffffffffu, sum0, 2);
    sum1 += __shfl_xor_sync(0xffffffffu, sum1, 1);
    sum1 += __shfl_xor_sync(0xffffffffu, sum1, 2);
    l[0] = l[0] * f0 + sum0;
    l[1] = l[1] * f1 + sum1;
    o0[0] *= f0; o0[1] *= f0; o0[2] *= f1; o0[3] *= f1;
    o1[0] *= f0; o1[1] *= f0; o1[2] *= f1; o1[3] *= f1;
    m[0] = mn0; m[1] = mn1;
    #pragma unroll
    for (int s = 0; s < NTS / 2; s++) {
        uint32_t pa0 = pack2h(p[2*s][0],   p[2*s][1]);
        uint32_t pa1 = pack2h(p[2*s][2],   p[2*s][3]);
        uint32_t pa2 = pack2h(p[2*s+1][0], p[2*s+1][1]);
        uint32_t pa3 = pack2h(p[2*s+1][2], p[2*s+1][3]);
        #pragma unroll
        for (int d = 0; d < 2; d++) {
            const __half* bp = vt + (d * 8 + (lane >> 2)) * 456 + jbase + 16 * s + 2 * (lane & 3);
            uint32_t b0 = *(const uint32_t*)bp;
            uint32_t b1 = *(const uint32_t*)(bp + 8);
            mma_f16(d ? o1 : o0, pa0, pa1, pa2, pa3, b0, b1);
        }
    }
}

__global__ void __launch_bounds__(128) k5_attn() {
    int bh = blockIdx.x;
    int tid = threadIdx.x, lane = tid & 31, wid = tid >> 5;
    extern __shared__ __half smh[];
    __half* qs = smh;                 // 448 x 16
    __half* ks = smh + 448 * 16;      // 400 x 16
    __half* vt = ks + 400 * 16;       // 16 x 456 (transposed V)

    const __half* qg = g_qh + bh * AA * HDD;
    const __half* kg = g_kh + bh * AA * HDD;
    const __half* vg = g_vh + bh * AA * HDD;

    {
        uint4* qd = (uint4*)qs; const uint4* qsrc = (const uint4*)qg;
        for (int i = tid; i < 800; i += 128) qd[i] = qsrc[i];
        uint4 z; z.x = z.y = z.z = z.w = 0u;
        for (int i = tid; i < 96; i += 128) qd[800 + i] = z;
        uint4* kd = (uint4*)ks; const uint4* ksrc = (const uint4*)kg;
        for (int i = tid; i < 800; i += 128) kd[i] = ksrc[i];
        const __half2* vsrc = (const __half2*)vg;
        for (int i = tid; i < 3200; i += 128) {
            int ag = i >> 3, dd = i & 7;
            __half2 h = vsrc[i];
            vt[(2 * dd) * 456 + ag]     = __low2half(h);
            vt[(2 * dd + 1) * 456 + ag] = __high2half(h);
        }
    }
    __syncthreads();

    for (int p = 0; p < 7; p++) {
        int mrow = p * 64 + wid * 16;
        int r = mrow + (lane >> 2);
        const __half* qp = qs + r * 16 + 2 * (lane & 3);
        uint32_t qa0 = *(const uint32_t*)qp;
        uint32_t qa1 = *(const uint32_t*)(qp + 8 * 16);
        uint32_t qa2 = *(const uint32_t*)(qp + 8);
        uint32_t qa3 = *(const uint32_t*)(qp + 8 * 16 + 8);
        float m[2] = {-1e30f, -1e30f}, l[2] = {0.f, 0.f};
        float o0[4] = {0.f, 0.f, 0.f, 0.f}, o1[4] = {0.f, 0.f, 0.f, 0.f};
        #pragma unroll 1
        for (int c = 0; c < 6; c++)
            attn_chunk<8>(c * 64, ks, vt, qa0, qa1, qa2, qa3, m, l, o0, o1, lane);
        attn_chunk<2>(384, ks, vt, qa0, qa1, qa2, qa3, m, l, o0, o1, lane);

        float i0 = 1.0f / l[0], i1 = 1.0f / l[1];
        int row0 = mrow + (lane >> 2), row1 = row0 + 8;
        int colb = (lane & 3) * 2;
        if (row0 < AA) {
            float* op = g_o + (bh * AA + row0) * HDD;
            op[colb] = o0[0] * i0; op[colb + 1] = o0[1] * i0;
            op[8 + colb] = o1[0] * i0; op[8 + colb + 1] = o1[1] * i0;
        }
        if (row1 < AA) {
            float* op = g_o + (bh * AA + row1) * HDD;
            op[colb] = o0[2] * i1; op[colb + 1] = o0[3] * i1;
            op[8 + colb] = o1[2] * i1; op[8 + colb + 1] = o1[3] * i1;
        }
    }
}

// ---------------- K6: O-proj (tf32 mma) + residual + output head ----------------
__global__ void __launch_bounds__(512) k6_out(
        const float* __restrict__ Wo,   const float* __restrict__ bo,
        const float* __restrict__ Wout, const float* __restrict__ bout,
        float* __restrict__ out) {
    int a = blockIdx.x;
    extern __shared__ float sm[];
    float* smA = sm;                      // 64 x 132 (raw o)
    float* smW = sm + 64 * 132;           // 128 x 200 (raw Wo)
    float* att = smW + 128 * 200;         // 64 x 192
    int tid = threadIdx.x, lane = tid & 31, wid = tid >> 5;
    int mrow = (wid & 3) * 16, ncol = (wid >> 2) * 48;

    #pragma unroll
    for (int j = 0; j < 4; j++) {
        int f = tid + j * 512;
        int b = f >> 5, c4 = f & 31;
        int head = c4 >> 2, d4 = (c4 & 3) * 4;
        cpa16(smA + b * 132 + c4 * 4, g_o + (((b * NHD) + head) * AA + a) * HDD + d4);
    }
    #pragma unroll
    for (int j = 0; j < 12; j++) {
        int f = tid + j * 512;
        int k = f / 48, n4 = (f % 48) * 4;
        cpa16(smW + k * 200 + n4, Wo + f * 4);
    }
    cpa_commit();
    cpa_wait<0>();
    __syncthreads();

    float acc[6][4] = {};
    #pragma unroll
    for (int ks = 0; ks < 16; ks++) {
        int k0 = ks * 8;
        int ar = mrow + (lane >> 2);
        int ac = k0 + (lane & 3);
        uint32_t a0 = tfbits(smA[ar * 132 + ac]);
        uint32_t a1 = tfbits(smA[(ar + 8) * 132 + ac]);
        uint32_t a2 = tfbits(smA[ar * 132 + ac + 4]);
        uint32_t a3 = tfbits(smA[(ar + 8) * 132 + ac + 4]);
        #pragma unroll
        for (int nt = 0; nt < 6; nt++) {
            int bo2 = (k0 + (lane & 3)) * 200 + ncol + nt * 8 + (lane >> 2);
            mma_tf32(acc[nt], a0, a1, a2, a3, tfbits(smW[bo2]), tfbits(smW[bo2 + 4 * 200]));
        }
    }

    #pragma unroll
    for (int nt = 0; nt < 6; nt++)
        #pragma unroll
        for (int i = 0; i < 4; i++) {
            int row = mrow + (lane >> 2) + (i >> 1) * 8;
            int col = ncol + nt * 8 + (lane & 3) * 2 + (i & 1);
            att[row * HH + col] = g_h3[(a * BB + row) * HH + col] + acc[nt][i] + bo[col];
        }
    __syncthreads();

    if (tid < BB * OO) {
        int b = tid / OO, oo = tid % OO;
        float s = bout[a * OO + oo];
        #pragma unroll 4
        for (int k = 0; k < HH; k++)
            s = fmaf(att[b * HH + k], Wout[(a * HH + k) * OO + oo], s);
        out[(a * BB + b) * OO + oo] = s;
    }
}

// ---------------- host launcher ----------------
extern "C" void kernel_launch(void* const* d_in, const int* in_sizes, int n_in,
                              void* d_out, int out_size) {
    const float* x       = (const float*)d_in[0];
    const float* ln_in_g = (const float*)d_in[1];
    const float* ln_in_b = (const float*)d_in[2];
    const float* W1   = (const float*)d_in[3];
    const float* b1   = (const float*)d_in[4];
    const float* Ws1  = (const float*)d_in[5];
    const float* bs1  = (const float*)d_in[6];
    const float* W2   = (const float*)d_in[7];
    const float* b2   = (const float*)d_in[8];
    const float* Ws2  = (const float*)d_in[9];
    const float* bs2  = (const float*)d_in[10];
    const float* W3   = (const float*)d_in[11];
    const float* b3   = (const float*)d_in[12];
    const float* ln_h_g = (const float*)d_in[13];
    const float* ln_h_b = (const float*)d_in[14];
    const float* Wout = (const float*)d_in[15];
    const float* bout = (const float*)d_in[16];
    const float* aln_g = (const float*)d_in[17];
    const float* aln_b = (const float*)d_in[18];
    const float* Wq = (const float*)d_in[19];
    const float* bq = (const float*)d_in[20];
    const float* Wk = (const float*)d_in[21];
    const float* bk = (const float*)d_in[22];
    const float* Wv = (const float*)d_in[23];
    const float* bv = (const float*)d_in[24];
    const float* Wo = (const float*)d_in[25];
    const float* bo = (const float*)d_in[26];
    float* out = (float*)d_out;

    const int SMF = (12544 + 12544 + 2 * 12800) * 4;     // 202752 B
    const int SM5 = (448 * 16 + 400 * 16 + 16 * 456) * 2;
    const int SM6 = (64 * 132 + 128 * 200 + 64 * 192) * 4;

    cudaFuncSetAttribute(kf_mlp,  cudaFuncAttributeMaxDynamicSharedMemorySize, SMF);
    cudaFuncSetAttribute(k5_attn, cudaFuncAttributeMaxDynamicSharedMemorySize, SM5);
    cudaFuncSetAttribute(k6_out,  cudaFuncAttributeMaxDynamicSharedMemorySize, SM6);

    k0_xhat<<<1, 64>>>(x);
    kf_mlp <<<AA, 512, SMF>>>(ln_in_g, ln_in_b, W1, b1, Ws1, bs1,
                              W2, b2, Ws2, bs2, W3, b3,
                              ln_h_g, ln_h_b, aln_g, aln_b,
                              Wq, bq, Wk, bk, Wv, bv);
    k5_attn<<<BB * NHD, 128, SM5>>>();
    k6_out <<<AA, 512, SM6>>>(Wo, bo, Wout, bout, out);
}

// round 11
// speedup vs baseline: 3.5682x; 1.1772x over previous
#include <cuda_runtime.h>
#include <cuda_fp16.h>
#include <math.h>
#include <stdint.h>

#define AA 400
#define BB 64
#define II 50
#define HH 192
#define OO 3
#define AD 128
#define NHD 8
#define HDD 16
#define EPSF 1e-5f

// ---------------- scratch (device globals) ----------------
__device__ __align__(16) float g_xhat[BB * II];
__device__ __align__(16) float g_h3[AA * BB * HH];
__device__ __align__(16) __half g_qh[BB * NHD * AA * HDD];   // [b, h, a, d], q pre-scaled by 0.25
__device__ __align__(16) __half g_kh[BB * NHD * AA * HDD];
__device__ __align__(16) __half g_vh[BB * NHD * AA * HDD];
__device__ __align__(16) float  g_o [BB * NHD * AA * HDD];

__device__ __forceinline__ float gelu_exact(float v) {
    return 0.5f * v * (1.0f + erff(v * 0.70710678118654752440f));
}
__device__ __forceinline__ float warp_sum(float v) {
    #pragma unroll
    for (int o = 16; o > 0; o >>= 1) v += __shfl_xor_sync(0xffffffffu, v, o);
    return v;
}
__device__ __forceinline__ uint32_t tfbits(float f) {
    uint32_t r;
    asm("cvt.rna.tf32.f32 %0, %1;" : "=r"(r) : "f"(f));
    return r;
}
__device__ __forceinline__ void cpa16(float* s, const float* g) {
    uint32_t sa = (uint32_t)__cvta_generic_to_shared(s);
    asm volatile("cp.async.cg.shared.global [%0], [%1], 16;" :: "r"(sa), "l"(g));
}
__device__ __forceinline__ void cpa_commit() { asm volatile("cp.async.commit_group;"); }
template<int N>
__device__ __forceinline__ void cpa_wait() { asm volatile("cp.async.wait_group %0;" :: "n"(N)); }

__device__ __forceinline__ void mma_tf32(float* c, uint32_t a0, uint32_t a1, uint32_t a2, uint32_t a3,
                                         uint32_t b0, uint32_t b1) {
    asm volatile("mma.sync.aligned.m16n8k8.row.col.f32.tf32.tf32.f32 "
                 "{%0,%1,%2,%3},{%4,%5,%6,%7},{%8,%9},{%0,%1,%2,%3};"
                 : "+f"(c[0]), "+f"(c[1]), "+f"(c[2]), "+f"(c[3])
                 : "r"(a0), "r"(a1), "r"(a2), "r"(a3), "r"(b0), "r"(b1));
}
__device__ __forceinline__ void mma_f16(float* c, uint32_t a0, uint32_t a1, uint32_t a2, uint32_t a3,
                                        uint32_t b0, uint32_t b1) {
    asm volatile("mma.sync.aligned.m16n8k16.row.col.f32.f16.f16.f32 "
                 "{%0,%1,%2,%3},{%4,%5,%6,%7},{%8,%9},{%0,%1,%2,%3};"
                 : "+f"(c[0]), "+f"(c[1]), "+f"(c[2]), "+f"(c[3])
                 : "r"(a0), "r"(a1), "r"(a2), "r"(a3), "r"(b0), "r"(b1));
}
__device__ __forceinline__ uint32_t pack2h(float x, float y) {
    __half2 h = __floats2half2_rn(x, y);
    return *reinterpret_cast<uint32_t*>(&h);
}

// ---------------- K0: shared input LN stats ----------------
__global__ void __launch_bounds__(64) k0_xhat(const float* __restrict__ x) {
    int b = threadIdx.x;
    if (b >= BB) return;
    float s = 0.f;
    #pragma unroll
    for (int i = 0; i < II; i++) s += x[b * II + i];
    float mu = s * (1.0f / II);
    float vv = 0.f;
    #pragma unroll
    for (int i = 0; i < II; i++) { float d = x[b * II + i] - mu; vv += d * d; }
    float rinv = rsqrtf(vv * (1.0f / II) + EPSF);
    #pragma unroll
    for (int i = 0; i < II; i++) g_xhat[b * II + i] = (x[b * II + i] - mu) * rinv;
}

// ================= Fused per-agent MLP + LN + QKV kernel =================
__global__ void __launch_bounds__(512) kf_mlp(
        const float* __restrict__ ling, const float* __restrict__ linb,
        const float* __restrict__ W1,  const float* __restrict__ b1,
        const float* __restrict__ Ws1, const float* __restrict__ bs1,
        const float* __restrict__ W2,  const float* __restrict__ b2,
        const float* __restrict__ Ws2, const float* __restrict__ bs2,
        const float* __restrict__ W3,  const float* __restrict__ b3v,
        const float* __restrict__ lhg,  const float* __restrict__ lhb,
        const float* __restrict__ alng, const float* __restrict__ alnb,
        const float* __restrict__ Wq, const float* __restrict__ bq,
        const float* __restrict__ Wk, const float* __restrict__ bk,
        const float* __restrict__ Wv, const float* __restrict__ bv) {
    int a = blockIdx.x;
    extern __shared__ float sm[];
    float* bufX = sm;
    float* bufY = sm + 12544;
    float* wst  = sm + 25088;
    float* st0  = wst;
    float* st1  = wst + 12800;
    int tid = threadIdx.x, lane = tid & 31, wid = tid >> 5;
    int mrow = (wid & 3) * 16, ncol = (wid >> 2) * 48;

    // ---------- Layer 1 ----------
    {
        const float* w1g = W1  + a * II * HH;
        const float* w2g = Ws1 + a * II * HH;
        for (int f = tid; f < 2400; f += 512) {
            int k = f / 48, n4 = (f % 48) * 4;
            cpa16(st0 + k * 200 + n4, w1g + f * 4);
            cpa16(st1 + k * 200 + n4, w2g + f * 4);
        }
        cpa_commit();
        for (int idx = tid; idx < 6 * 200; idx += 512) { st0[50 * 200 + idx] = 0.f; st1[50 * 200 + idx] = 0.f; }
        for (int idx = tid; idx < 50 * 8; idx += 512) {
            int k = idx / 8, c = 192 + (idx % 8);
            st0[k * 200 + c] = 0.f; st1[k * 200 + c] = 0.f;
        }
        for (int idx = tid; idx < 64 * 60; idx += 512) {
            int r = idx / 60, c = idx % 60;
            float v = 0.f;
            if (c < II) v = g_xhat[r * II + c] * ling[a * II + c] + linb[a * II + c];
            bufX[idx] = v;
        }
        cpa_wait<0>();
        __syncthreads();

        float accA[6][4] = {}, accB[6][4] = {};
        #pragma unroll
        for (int ks = 0; ks < 7; ks++) {
            int k0 = ks * 8;
            int ar = mrow + (lane >> 2);
            int ac = k0 + (lane & 3);
            uint32_t a0 = tfbits(bufX[ar * 60 + ac]);
            uint32_t a1 = tfbits(bufX[(ar + 8) * 60 + ac]);
            uint32_t a2 = tfbits(bufX[ar * 60 + ac + 4]);
            uint32_t a3 = tfbits(bufX[(ar + 8) * 60 + ac + 4]);
            #pragma unroll
            for (int nt = 0; nt < 6; nt++) {
                int bo = (k0 + (lane & 3)) * 200 + ncol + nt * 8 + (lane >> 2);
                mma_tf32(accA[nt], a0, a1, a2, a3, tfbits(st0[bo]), tfbits(st0[bo + 4 * 200]));
                mma_tf32(accB[nt], a0, a1, a2, a3, tfbits(st1[bo]), tfbits(st1[bo + 4 * 200]));
            }
        }
        __syncthreads();
        #pragma unroll
        for (int nt = 0; nt < 6; nt++)
            #pragma unroll
            for (int j = 0; j < 2; j++) {
                int row = mrow + (lane >> 2) + j * 8;
                int col = ncol + nt * 8 + (lane & 3) * 2;
                float va0 = accA[nt][j*2]   + b1 [a * HH + col];
                float va1 = accA[nt][j*2+1] + b1 [a * HH + col + 1];
                float vb0 = accB[nt][j*2]   + bs1[a * HH + col];
                float vb1 = accB[nt][j*2+1] + bs1[a * HH + col + 1];
                bufY[row * 196 + col]     = gelu_exact(va0) + vb0;
                bufY[row * 196 + col + 1] = gelu_exact(va1) + vb1;
            }
        __syncthreads();
    }

    // ---------- Layer 2 (A = bufY, out -> bufX) ----------
    {
        const float* w1g = W2  + a * HH * HH;
        const float* w2g = Ws2 + a * HH * HH;
        #pragma unroll
        for (int j = 0; j < 3; j++) {
            int f = tid + j * 512;
            int k = f / 48, n4 = (f % 48) * 4;
            cpa16(st0 + k * 200 + n4,        w1g + f * 4);
            cpa16(st0 + 6400 + k * 200 + n4, w2g + f * 4);
        }
        cpa_commit();

        float accA[6][4] = {}, accB[6][4] = {};
        #pragma unroll 1
        for (int slab = 0; slab < 6; slab++) {
            if (slab + 1 < 6) {
                float* ns = (slab & 1) ? st0 : st1;
                #pragma unroll
                for (int j = 0; j < 3; j++) {
                    int f = tid + j * 512;
                    int k = f / 48, n4 = (f % 48) * 4;
                    cpa16(ns + k * 200 + n4,        w1g + (slab + 1) * 6144 + f * 4);
                    cpa16(ns + 6400 + k * 200 + n4, w2g + (slab + 1) * 6144 + f * 4);
                }
            }
            cpa_commit();
            cpa_wait<1>();
            __syncthreads();
            float* cw1 = (slab & 1) ? st1 : st0;
            float* cw2 = cw1 + 6400;
            #pragma unroll
            for (int ks = 0; ks < 4; ks++) {
                int k0 = ks * 8;
                int ar = mrow + (lane >> 2);
                int ac = slab * 32 + k0 + (lane & 3);
                uint32_t a0 = tfbits(bufY[ar * 196 + ac]);
                uint32_t a1 = tfbits(bufY[(ar + 8) * 196 + ac]);
                uint32_t a2 = tfbits(bufY[ar * 196 + ac + 4]);
                uint32_t a3 = tfbits(bufY[(ar + 8) * 196 + ac + 4]);
                #pragma unroll
                for (int nt = 0; nt < 6; nt++) {
                    int bo = (k0 + (lane & 3)) * 200 + ncol + nt * 8 + (lane >> 2);
                    mma_tf32(accA[nt], a0, a1, a2, a3, tfbits(cw1[bo]), tfbits(cw1[bo + 4 * 200]));
                    mma_tf32(accB[nt], a0, a1, a2, a3, tfbits(cw2[bo]), tfbits(cw2[bo + 4 * 200]));
                }
            }
            __syncthreads();
        }
        #pragma unroll
        for (int nt = 0; nt < 6; nt++)
            #pragma unroll
            for (int j = 0; j < 2; j++) {
                int row = mrow + (lane >> 2) + j * 8;
                int col = ncol + nt * 8 + (lane & 3) * 2;
                float va0 = accA[nt][j*2]   + b2 [a * HH + col];
                float va1 = accA[nt][j*2+1] + b2 [a * HH + col + 1];
                float vb0 = accB[nt][j*2]   + bs2[a * HH + col];
                float vb1 = accB[nt][j*2+1] + bs2[a * HH + col + 1];
                bufX[row * 196 + col]     = gelu_exact(va0) + vb0;
                bufX[row * 196 + col + 1] = gelu_exact(va1) + vb1;
            }
        __syncthreads();
    }

    // ---------- Layer 3 (A = bufX = exact h2) + residual + LN + LN ----------
    {
        const float* wg = W3 + a * HH * HH;
        #pragma unroll
        for (int j = 0; j < 3; j++) {
            int f = tid + j * 512;
            int k = f / 48, n4 = (f % 48) * 4;
            cpa16(st0 + k * 200 + n4, wg + f * 4);
        }
        cpa_commit();

        float acc[6][4] = {};
        #pragma unroll 1
        for (int slab = 0; slab < 6; slab++) {
            if (slab + 1 < 6) {
                float* ns = (slab & 1) ? st0 : st1;
                #pragma unroll
                for (int j = 0; j < 3; j++) {
                    int f = tid + j * 512;
                    int k = f / 48, n4 = (f % 48) * 4;
                    cpa16(ns + k * 200 + n4, wg + (slab + 1) * 6144 + f * 4);
                }
            }
            cpa_commit();
            cpa_wait<1>();
            __syncthreads();
            float* cw = (slab & 1) ? st1 : st0;
            #pragma unroll
            for (int ks = 0; ks < 4; ks++) {
                int k0 = ks * 8;
                int ar = mrow + (lane >> 2);
                int ac = slab * 32 + k0 + (lane & 3);
                uint32_t a0 = tfbits(bufX[ar * 196 + ac]);
                uint32_t a1 = tfbits(bufX[(ar + 8) * 196 + ac]);
                uint32_t a2 = tfbits(bufX[ar * 196 + ac + 4]);
                uint32_t a3 = tfbits(bufX[(ar + 8) * 196 + ac + 4]);
                #pragma unroll
                for (int nt = 0; nt < 6; nt++) {
                    int bo = (k0 + (lane & 3)) * 200 + ncol + nt * 8 + (lane >> 2);
                    mma_tf32(acc[nt], a0, a1, a2, a3, tfbits(cw[bo]), tfbits(cw[bo + 4 * 200]));
                }
            }
            __syncthreads();
        }

        float* tbf = wst;
        #pragma unroll
        for (int nt = 0; nt < 6; nt++)
            #pragma unroll
            for (int j = 0; j < 2; j++) {
                int row = mrow + (lane >> 2) + j * 8;
                int col = ncol + nt * 8 + (lane & 3) * 2;
                tbf[row * 196 + col]     = bufX[row * 196 + col]     + acc[nt][j*2]   + b3v[a * HH + col];
                tbf[row * 196 + col + 1] = bufX[row * 196 + col + 1] + acc[nt][j*2+1] + b3v[a * HH + col + 1];
            }
        __syncthreads();

        for (int r = wid; r < BB; r += 16) {
            float v[6];
            #pragma unroll
            for (int u = 0; u < 6; u++) v[u] = tbf[r * 196 + u * 32 + lane];
            float s = 0.f;
            #pragma unroll
            for (int u = 0; u < 6; u++) s += v[u];
            s = warp_sum(s);
            float mu = s * (1.0f / HH);
            float ss = 0.f;
            #pragma unroll
            for (int u = 0; u < 6; u++) { float d = v[u] - mu; ss += d * d; }
            ss = warp_sum(ss);
            float rinv = rsqrtf(ss * (1.0f / HH) + EPSF);

            float h3v[6]; float s2 = 0.f;
            #pragma unroll
            for (int u = 0; u < 6; u++) {
                int i = u * 32 + lane;
                h3v[u] = (v[u] - mu) * rinv * lhg[a * HH + i] + lhb[a * HH + i];
                g_h3[(a * BB + r) * HH + i] = h3v[u];
                s2 += h3v[u];
            }
            s2 = warp_sum(s2);
            float mu2 = s2 * (1.0f / HH);
            float ss2 = 0.f;
            #pragma unroll
            for (int u = 0; u < 6; u++) { float d = h3v[u] - mu2; ss2 += d * d; }
            ss2 = warp_sum(ss2);
            float rinv2 = rsqrtf(ss2 * (1.0f / HH) + EPSF);
            #pragma unroll
            for (int u = 0; u < 6; u++) {
                int i = u * 32 + lane;
                bufY[r * 196 + i] = (h3v[u] - mu2) * rinv2 * alng[i] + alnb[i];
            }
        }
        __syncthreads();
    }

    // ---------- QKV (A = bufY = y) ----------
    {
        int ncolq = (wid >> 2) * 96;
        #pragma unroll
        for (int j = 0; j < 6; j++) {
            int f = tid + j * 512;
            int k = f / 96, n4g = f % 96;
            int mat = n4g / 32, c4 = (n4g % 32) * 4;
            const float* W = (mat == 0) ? Wq : (mat == 1) ? Wk : Wv;
            cpa16(st0 + k * 392 + n4g * 4, W + k * AD + c4);
        }
        cpa_commit();

        float acc[12][4] = {};
        #pragma unroll 1
        for (int slab = 0; slab < 6; slab++) {
            if (slab + 1 < 6) {
                float* ns = (slab & 1) ? st0 : st1;
                #pragma unroll
                for (int j = 0; j < 6; j++) {
                    int f = tid + j * 512;
                    int k = f / 96, n4g = f % 96;
                    int mat = n4g / 32, c4 = (n4g % 32) * 4;
                    const float* W = (mat == 0) ? Wq : (mat == 1) ? Wk : Wv;
                    cpa16(ns + k * 392 + n4g * 4, W + ((slab + 1) * 32 + k) * AD + c4);
                }
            }
            cpa_commit();
            cpa_wait<1>();
            __syncthreads();
            float* ws = (slab & 1) ? st1 : st0;
            #pragma unroll
            for (int ks = 0; ks < 4; ks++) {
                int k0 = ks * 8;
                int ar = mrow + (lane >> 2);
                int ac = slab * 32 + k0 + (lane & 3);
                uint32_t a0 = tfbits(bufY[ar * 196 + ac]);
                uint32_t a1 = tfbits(bufY[(ar + 8) * 196 + ac]);
                uint32_t a2 = tfbits(bufY[ar * 196 + ac + 4]);
                uint32_t a3 = tfbits(bufY[(ar + 8) * 196 + ac + 4]);
                #pragma unroll
                for (int nt = 0; nt < 12; nt++) {
                    int bo = (k0 + (lane & 3)) * 392 + ncolq + nt * 8 + (lane >> 2);
                    mma_tf32(acc[nt], a0, a1, a2, a3, tfbits(ws[bo]), tfbits(ws[bo + 4 * 392]));
                }
            }
            __syncthreads();
        }

        #pragma unroll
        for (int nt = 0; nt < 12; nt++)
            #pragma unroll
            for (int i = 0; i < 4; i++) {
                int row = mrow + (lane >> 2) + (i >> 1) * 8;
                int col = ncolq + nt * 8 + (lane & 3) * 2 + (i & 1);
                float val = acc[nt][i];
                __half* dst; int c;
                if (col < 128)      { val = (val + bq[col]) * 0.25f; c = col;       dst = g_qh; }
                else if (col < 256) { val = val + bk[col - 128];     c = col - 128; dst = g_kh; }
                else                { val = val + bv[col - 256];     c = col - 256; dst = g_vh; }
                dst[(((row * NHD) + (c >> 4)) * AA + a) * HDD + (c & 15)] = __float2half_rn(val);
            }
    }
}

// ---------------- K5: flash attention over agents, fp16 mma ----------------
template<int NTS>
__device__ __forceinline__ void attn_chunk(int jbase, const __half* ks, const __half* vt,
                                           uint32_t qa0, uint32_t qa1, uint32_t qa2, uint32_t qa3,
                                           float* m, float* l, float* o0, float* o1, int lane) {
    float sc[NTS][4];
    #pragma unroll
    for (int nt = 0; nt < NTS; nt++) { sc[nt][0] = sc[nt][1] = sc[nt][2] = sc[nt][3] = 0.f; }
    #pragma unroll
    for (int nt = 0; nt < NTS; nt++) {
        const __half* bp = ks + (jbase + nt * 8 + (lane >> 2)) * 16 + 2 * (lane & 3);
        uint32_t b0 = *(const uint32_t*)bp;
        uint32_t b1 = *(const uint32_t*)(bp + 8);
        mma_f16(sc[nt], qa0, qa1, qa2, qa3, b0, b1);
    }
    float mx0 = -1e30f, mx1 = -1e30f;
    #pragma unroll
    for (int nt = 0; nt < NTS; nt++) {
        mx0 = fmaxf(mx0, fmaxf(sc[nt][0], sc[nt][1]));
        mx1 = fmaxf(mx1, fmaxf(sc[nt][2], sc[nt][3]));
    }
    mx0 = fmaxf(mx0, __shfl_xor_sync(0xffffffffu, mx0, 1));
    mx0 = fmaxf(mx0, __shfl_xor_sync(0xffffffffu, mx0, 2));
    mx1 = fmaxf(mx1, __shfl_xor_sync(0xffffffffu, mx1, 1));
    mx1 = fmaxf(mx1, __shfl_xor_sync(0xffffffffu, mx1, 2));
    float mn0 = fmaxf(m[0], mx0), mn1 = fmaxf(m[1], mx1);
    float f0 = __expf(m[0] - mn0), f1 = __expf(m[1] - mn1);
    float p[NTS][4];
    float sum0 = 0.f, sum1 = 0.f;
    #pragma unroll
    for (int nt = 0; nt < NTS; nt++) {
        p[nt][0] = __expf(sc[nt][0] - mn0);
        p[nt][1] = __expf(sc[nt][1] - mn0);
        p[nt][2] = __expf(sc[nt][2] - mn1);
        p[nt][3] = __expf(sc[nt][3] - mn1);
        sum0 += p[nt][0] + p[nt][1];
        sum1 += p[nt][2] + p[nt][3];
    }
    sum0 += __shfl_xor_sync(0xffffffffu, sum0, 1);
    sum0 += __shfl_xor_sync(0xffffffffu, sum0, 2);
    sum1 += __shfl_xor_sync(0xffffffffu, sum1, 1);
    sum1 += __shfl_xor_sync(0xffffffffu, sum1, 2);
    l[0] = l[0] * f0 + sum0;
    l[1] = l[1] * f1 + sum1;
    o0[0] *= f0; o0[1] *= f0; o0[2] *= f1; o0[3] *= f1;
    o1[0] *= f0; o1[1] *= f0; o1[2] *= f1; o1[3] *= f1;
    m[0] = mn0; m[1] = mn1;
    #pragma unroll
    for (int s = 0; s < NTS / 2; s++) {
        uint32_t pa0 = pack2h(p[2*s][0],   p[2*s][1]);
        uint32_t pa1 = pack2h(p[2*s][2],   p[2*s][3]);
        uint32_t pa2 = pack2h(p[2*s+1][0], p[2*s+1][1]);
        uint32_t pa3 = pack2h(p[2*s+1][2], p[2*s+1][3]);
        #pragma unroll
        for (int d = 0; d < 2; d++) {
            const __half* bp = vt + (d * 8 + (lane >> 2)) * 456 + jbase + 16 * s + 2 * (lane & 3);
            uint32_t b0 = *(const uint32_t*)bp;
            uint32_t b1 = *(const uint32_t*)(bp + 8);
            mma_f16(d ? o1 : o0, pa0, pa1, pa2, pa3, b0, b1);
        }
    }
}

__global__ void __launch_bounds__(128) k5_attn() {
    int bh = blockIdx.x;
    int tid = threadIdx.x, lane = tid & 31, wid = tid >> 5;
    extern __shared__ __half smh[];
    __half* qs = smh;                 // 448 x 16
    __half* ks = smh + 448 * 16;      // 400 x 16
    __half* vt = ks + 400 * 16;       // 16 x 456 (transposed V)

    const __half* qg = g_qh + bh * AA * HDD;
    const __half* kg = g_kh + bh * AA * HDD;
    const __half* vg = g_vh + bh * AA * HDD;

    {
        uint4* qd = (uint4*)qs; const uint4* qsrc = (const uint4*)qg;
        for (int i = tid; i < 800; i += 128) qd[i] = qsrc[i];
        uint4 z; z.x = z.y = z.z = z.w = 0u;
        for (int i = tid; i < 96; i += 128) qd[800 + i] = z;
        uint4* kd = (uint4*)ks; const uint4* ksrc = (const uint4*)kg;
        for (int i = tid; i < 800; i += 128) kd[i] = ksrc[i];
        const __half2* vsrc = (const __half2*)vg;
        for (int i = tid; i < 3200; i += 128) {
            int ag = i >> 3, dd = i & 7;
            __half2 h = vsrc[i];
            vt[(2 * dd) * 456 + ag]     = __low2half(h);
            vt[(2 * dd + 1) * 456 + ag] = __high2half(h);
        }
    }
    __syncthreads();

    for (int p = 0; p < 7; p++) {
        int mrow = p * 64 + wid * 16;
        int r = mrow + (lane >> 2);
        const __half* qp = qs + r * 16 + 2 * (lane & 3);
        uint32_t qa0 = *(const uint32_t*)qp;
        uint32_t qa1 = *(const uint32_t*)(qp + 8 * 16);
        uint32_t qa2 = *(const uint32_t*)(qp + 8);
        uint32_t qa3 = *(const uint32_t*)(qp + 8 * 16 + 8);
        float m[2] = {-1e30f, -1e30f}, l[2] = {0.f, 0.f};
        float o0[4] = {0.f, 0.f, 0.f, 0.f}, o1[4] = {0.f, 0.f, 0.f, 0.f};
        #pragma unroll 1
        for (int c = 0; c < 6; c++)
            attn_chunk<8>(c * 64, ks, vt, qa0, qa1, qa2, qa3, m, l, o0, o1, lane);
        attn_chunk<2>(384, ks, vt, qa0, qa1, qa2, qa3, m, l, o0, o1, lane);

        float i0 = 1.0f / l[0], i1 = 1.0f / l[1];
        int row0 = mrow + (lane >> 2), row1 = row0 + 8;
        int colb = (lane & 3) * 2;
        if (row0 < AA) {
            float* op = g_o + (bh * AA + row0) * HDD;
            op[colb] = o0[0] * i0; op[colb + 1] = o0[1] * i0;
            op[8 + colb] = o1[0] * i0; op[8 + colb + 1] = o1[1] * i0;
        }
        if (row1 < AA) {
            float* op = g_o + (bh * AA + row1) * HDD;
            op[colb] = o0[2] * i1; op[colb + 1] = o0[3] * i1;
            op[8 + colb] = o1[2] * i1; op[8 + colb + 1] = o1[3] * i1;
        }
    }
}

// ---------------- K6: O-proj (slab-pipelined Wo) + residual + output head ----------------
__global__ void __launch_bounds__(512) k6_out(
        const float* __restrict__ Wo,   const float* __restrict__ bo,
        const float* __restrict__ Wout, const float* __restrict__ bout,
        float* __restrict__ out) {
    int a = blockIdx.x;
    extern __shared__ float sm[];
    float* smA = sm;                      // 64 x 132 (raw o); reused for Wout copy
    float* wst = sm + 64 * 132;           // 2 stages x 32 x 200; reused as att 64x192
    float* st0 = wst;
    float* st1 = wst + 6400;
    int tid = threadIdx.x, lane = tid & 31, wid = tid >> 5;
    int mrow = (wid & 3) * 16, ncol = (wid >> 2) * 48;

    // o gather: 2048 f4 (16B chunks contiguous per (b,head))
    #pragma unroll
    for (int j = 0; j < 4; j++) {
        int f = tid + j * 512;
        int b = f >> 5, c4 = f & 31;
        int head = c4 >> 2, d4 = (c4 & 3) * 4;
        cpa16(smA + b * 132 + c4 * 4, g_o + (((b * NHD) + head) * AA + a) * HDD + d4);
    }
    // slab0 of Wo: 32 x 192 = 1536 f4
    #pragma unroll
    for (int j = 0; j < 3; j++) {
        int f = tid + j * 512;
        int k = f / 48, n4 = (f % 48) * 4;
        cpa16(st0 + k * 200 + n4, Wo + f * 4);
    }
    cpa_commit();

    float acc[6][4] = {};
    #pragma unroll 1
    for (int slab = 0; slab < 4; slab++) {
        if (slab + 1 < 4) {
            float* ns = (slab & 1) ? st0 : st1;
            #pragma unroll
            for (int j = 0; j < 3; j++) {
                int f = tid + j * 512;
                int k = f / 48, n4 = (f % 48) * 4;
                cpa16(ns + k * 200 + n4, Wo + (slab + 1) * 6144 + f * 4);
            }
        }
        cpa_commit();
        cpa_wait<1>();
        __syncthreads();
        float* cw = (slab & 1) ? st1 : st0;
        #pragma unroll
        for (int ks = 0; ks < 4; ks++) {
            int k0 = ks * 8;
            int ar = mrow + (lane >> 2);
            int ac = slab * 32 + k0 + (lane & 3);
            uint32_t a0 = tfbits(smA[ar * 132 + ac]);
            uint32_t a1 = tfbits(smA[(ar + 8) * 132 + ac]);
            uint32_t a2 = tfbits(smA[ar * 132 + ac + 4]);
            uint32_t a3 = tfbits(smA[(ar + 8) * 132 + ac + 4]);
            #pragma unroll
            for (int nt = 0; nt < 6; nt++) {
                int bo2 = (k0 + (lane & 3)) * 200 + ncol + nt * 8 + (lane >> 2);
                mma_tf32(acc[nt], a0, a1, a2, a3, tfbits(cw[bo2]), tfbits(cw[bo2 + 4 * 200]));
            }
        }
        __syncthreads();
    }

    // att = h3 + o@Wo + bo  -> reuse wst (64 x 192 = 12288 <= 12800)
    float* att = wst;
    #pragma unroll
    for (int nt = 0; nt < 6; nt++)
        #pragma unroll
        for (int j = 0; j < 2; j++) {
            int row = mrow + (lane >> 2) + j * 8;
            int col = ncol + nt * 8 + (lane & 3) * 2;
            float2 h3v = *(const float2*)(g_h3 + (a * BB + row) * HH + col);
            att[row * HH + col]     = h3v.x + acc[nt][j*2]   + bo[col];
            att[row * HH + col + 1] = h3v.y + acc[nt][j*2+1] + bo[col + 1];
        }
    // Wout[a]: 576 contiguous floats -> reuse smA
    float* wout = smA;
    if (tid < 144) {
        *(float4*)(wout + tid * 4) = *(const float4*)(Wout + a * HH * OO + tid * 4);
    }
    __syncthreads();

    // output head: warp per (b, oo) task; lane-parallel over K=192
    for (int t = wid; t < BB * OO; t += 16) {
        int b = t / OO, oo = t - b * OO;
        float partial = 0.f;
        #pragma unroll
        for (int u = 0; u < 6; u++) {
            int k = u * 32 + lane;
            partial = fmaf(att[b * HH + k], wout[k * OO + oo], partial);
        }
        partial = warp_sum(partial);
        if (lane == 0) out[(a * BB + b) * OO + oo] = partial + bout[a * OO + oo];
    }
}

// ---------------- host launcher ----------------
extern "C" void kernel_launch(void* const* d_in, const int* in_sizes, int n_in,
                              void* d_out, int out_size) {
    const float* x       = (const float*)d_in[0];
    const float* ln_in_g = (const float*)d_in[1];
    const float* ln_in_b = (const float*)d_in[2];
    const float* W1   = (const float*)d_in[3];
    const float* b1   = (const float*)d_in[4];
    const float* Ws1  = (const float*)d_in[5];
    const float* bs1  = (const float*)d_in[6];
    const float* W2   = (const float*)d_in[7];
    const float* b2   = (const float*)d_in[8];
    const float* Ws2  = (const float*)d_in[9];
    const float* bs2  = (const float*)d_in[10];
    const float* W3   = (const float*)d_in[11];
    const float* b3   = (const float*)d_in[12];
    const float* ln_h_g = (const float*)d_in[13];
    const float* ln_h_b = (const float*)d_in[14];
    const float* Wout = (const float*)d_in[15];
    const float* bout = (const float*)d_in[16];
    const float* aln_g = (const float*)d_in[17];
    const float* aln_b = (const float*)d_in[18];
    const float* Wq = (const float*)d_in[19];
    const float* bq = (const float*)d_in[20];
    const float* Wk = (const float*)d_in[21];
    const float* bk = (const float*)d_in[22];
    const float* Wv = (const float*)d_in[23];
    const float* bv = (const float*)d_in[24];
    const float* Wo = (const float*)d_in[25];
    const float* bo = (const float*)d_in[26];
    float* out = (float*)d_out;

    const int SMF = (12544 + 12544 + 2 * 12800) * 4;     // 202752 B
    const int SM5 = (448 * 16 + 400 * 16 + 16 * 456) * 2;
    const int SM6 = (64 * 132 + 2 * 32 * 200) * 4;       // 84992 B -> 2 CTAs/SM

    cudaFuncSetAttribute(kf_mlp,  cudaFuncAttributeMaxDynamicSharedMemorySize, SMF);
    cudaFuncSetAttribute(k5_attn, cudaFuncAttributeMaxDynamicSharedMemorySize, SM5);
    cudaFuncSetAttribute(k6_out,  cudaFuncAttributeMaxDynamicSharedMemorySize, SM6);

    k0_xhat<<<1, 64>>>(x);
    kf_mlp <<<AA, 512, SMF>>>(ln_in_g, ln_in_b, W1, b1, Ws1, bs1,
                              W2, b2, Ws2, bs2, W3, b3,
                              ln_h_g, ln_h_b, aln_g, aln_b,
                              Wq, bq, Wk, bk, Wv, bv);
    k5_attn<<<BB * NHD, 128, SM5>>>();
    k6_out <<<AA, 512, SM6>>>(Wo, bo, Wout, bout, out);
}

// round 13
// speedup vs baseline: 3.5967x; 1.0080x over previous
#include <cuda_runtime.h>
#include <cuda_fp16.h>
#include <math.h>
#include <stdint.h>

#define AA 400
#define BB 64
#define II 50
#define HH 192
#define OO 3
#define AD 128
#define NHD 8
#define HDD 16
#define EPSF 1e-5f

// ---------------- scratch (device globals) ----------------
__device__ __align__(16) float g_xhat[BB * II];
__device__ __align__(16) float g_h3[AA * BB * HH];
__device__ __align__(16) __half g_qh[BB * NHD * AA * HDD];   // [b, h, a, d], q pre-scaled by 0.25
__device__ __align__(16) __half g_kh[BB * NHD * AA * HDD];
__device__ __align__(16) __half g_vh[BB * NHD * AA * HDD];
__device__ __align__(16) float  g_o [BB * NHD * AA * HDD];

__device__ __forceinline__ float gelu_exact(float v) {
    return 0.5f * v * (1.0f + erff(v * 0.70710678118654752440f));
}
__device__ __forceinline__ float warp_sum(float v) {
    #pragma unroll
    for (int o = 16; o > 0; o >>= 1) v += __shfl_xor_sync(0xffffffffu, v, o);
    return v;
}
__device__ __forceinline__ uint32_t tfbits(float f) {
    uint32_t r;
    asm("cvt.rna.tf32.f32 %0, %1;" : "=r"(r) : "f"(f));
    return r;
}
__device__ __forceinline__ void cpa16(float* s, const float* g) {
    uint32_t sa = (uint32_t)__cvta_generic_to_shared(s);
    asm volatile("cp.async.cg.shared.global [%0], [%1], 16;" :: "r"(sa), "l"(g));
}
__device__ __forceinline__ void cpa_commit() { asm volatile("cp.async.commit_group;"); }
template<int N>
__device__ __forceinline__ void cpa_wait() { asm volatile("cp.async.wait_group %0;" :: "n"(N)); }

__device__ __forceinline__ void mma_tf32(float* c, uint32_t a0, uint32_t a1, uint32_t a2, uint32_t a3,
                                         uint32_t b0, uint32_t b1) {
    asm volatile("mma.sync.aligned.m16n8k8.row.col.f32.tf32.tf32.f32 "
                 "{%0,%1,%2,%3},{%4,%5,%6,%7},{%8,%9},{%0,%1,%2,%3};"
                 : "+f"(c[0]), "+f"(c[1]), "+f"(c[2]), "+f"(c[3])
                 : "r"(a0), "r"(a1), "r"(a2), "r"(a3), "r"(b0), "r"(b1));
}
__device__ __forceinline__ void mma_f16(float* c, uint32_t a0, uint32_t a1, uint32_t a2, uint32_t a3,
                                        uint32_t b0, uint32_t b1) {
    asm volatile("mma.sync.aligned.m16n8k16.row.col.f32.f16.f16.f32 "
                 "{%0,%1,%2,%3},{%4,%5,%6,%7},{%8,%9},{%0,%1,%2,%3};"
                 : "+f"(c[0]), "+f"(c[1]), "+f"(c[2]), "+f"(c[3])
                 : "r"(a0), "r"(a1), "r"(a2), "r"(a3), "r"(b0), "r"(b1));
}
__device__ __forceinline__ uint32_t pack2h(float x, float y) {
    __half2 h = __floats2half2_rn(x, y);
    return *reinterpret_cast<uint32_t*>(&h);
}

// ---------------- K0: shared input LN stats ----------------
__global__ void __launch_bounds__(64) k0_xhat(const float* __restrict__ x) {
    int b = threadIdx.x;
    if (b >= BB) return;
    float s = 0.f;
    #pragma unroll
    for (int i = 0; i < II; i++) s += x[b * II + i];
    float mu = s * (1.0f / II);
    float vv = 0.f;
    #pragma unroll
    for (int i = 0; i < II; i++) { float d = x[b * II + i] - mu; vv += d * d; }
    float rinv = rsqrtf(vv * (1.0f / II) + EPSF);
    #pragma unroll
    for (int i = 0; i < II; i++) g_xhat[b * II + i] = (x[b * II + i] - mu) * rinv;
}

// ================= Fused per-agent MLP + LN + QKV kernel (fp16 mma) =================
// smem (floats): bufX [0,12544) | bufY [12544,25088) | stages [25088, +2*12800)
// Weight tiles use row stride 196 floats (2m*196 mod 32 = 8m -> conflict-free B reads).
__global__ void __launch_bounds__(512) kf_mlp(
        const float* __restrict__ ling, const float* __restrict__ linb,
        const float* __restrict__ W1,  const float* __restrict__ b1,
        const float* __restrict__ Ws1, const float* __restrict__ bs1,
        const float* __restrict__ W2,  const float* __restrict__ b2,
        const float* __restrict__ Ws2, const float* __restrict__ bs2,
        const float* __restrict__ W3,  const float* __restrict__ b3v,
        const float* __restrict__ lhg,  const float* __restrict__ lhb,
        const float* __restrict__ alng, const float* __restrict__ alnb,
        const float* __restrict__ Wq, const float* __restrict__ bq,
        const float* __restrict__ Wk, const float* __restrict__ bk,
        const float* __restrict__ Wv, const float* __restrict__ bv) {
    int a = blockIdx.x;
    extern __shared__ float sm[];
    float* bufX = sm;
    float* bufY = sm + 12544;
    float* wst  = sm + 25088;
    float* st0  = wst;
    float* st1  = wst + 12800;
    int tid = threadIdx.x, lane = tid & 31, wid = tid >> 5;
    int mrow = (wid & 3) * 16, ncol = (wid >> 2) * 48;
    int q4 = lane >> 2, m2 = 2 * (lane & 3);
    int ar = mrow + q4;

    // ---------- Layer 1: K padded 50 -> 64, weights 64x196 in st0/st1 ----------
    {
        const float* w1g = W1  + a * II * HH;
        const float* w2g = Ws1 + a * II * HH;
        for (int f = tid; f < 2400; f += 512) {          // 50 rows x 192 cols
            int k = f / 48, n4 = (f % 48) * 4;
            cpa16(st0 + k * 196 + n4, w1g + f * 4);
            cpa16(st1 + k * 196 + n4, w2g + f * 4);
        }
        cpa_commit();
        // zero weight rows 50..63 (k padding)
        for (int idx = tid; idx < 14 * 196; idx += 512) {
            st0[50 * 196 + idx] = 0.f; st1[50 * 196 + idx] = 0.f;
        }
        // xn into bufX (stride 196), zero k-cols 50..63
        for (int idx = tid; idx < 64 * 64; idx += 512) {
            int r = idx >> 6, c = idx & 63;
            float v = 0.f;
            if (c < II) v = g_xhat[r * II + c] * ling[a * II + c] + linb[a * II + c];
            bufX[r * 196 + c] = v;
        }
        cpa_wait<0>();
        __syncthreads();

        float accA[6][4] = {}, accB[6][4] = {};
        #pragma unroll
        for (int hk = 0; hk < 4; hk++) {
            int k0 = hk * 16;
            float2 v00 = *(const float2*)(bufX + ar * 196 + k0 + m2);
            float2 v10 = *(const float2*)(bufX + (ar + 8) * 196 + k0 + m2);
            float2 v01 = *(const float2*)(bufX + ar * 196 + k0 + m2 + 8);
            float2 v11 = *(const float2*)(bufX + (ar + 8) * 196 + k0 + m2 + 8);
            uint32_t a0 = pack2h(v00.x, v00.y), a1 = pack2h(v10.x, v10.y);
            uint32_t a2 = pack2h(v01.x, v01.y), a3 = pack2h(v11.x, v11.y);
            int kb = k0 + m2;
            #pragma unroll
            for (int nt = 0; nt < 6; nt++) {
                int bn = ncol + nt * 8 + q4;
                uint32_t b0 = pack2h(st0[kb * 196 + bn],       st0[(kb + 1) * 196 + bn]);
                uint32_t b1 = pack2h(st0[(kb + 8) * 196 + bn], st0[(kb + 9) * 196 + bn]);
                mma_f16(accA[nt], a0, a1, a2, a3, b0, b1);
                uint32_t c0 = pack2h(st1[kb * 196 + bn],       st1[(kb + 1) * 196 + bn]);
                uint32_t c1 = pack2h(st1[(kb + 8) * 196 + bn], st1[(kb + 9) * 196 + bn]);
                mma_f16(accB[nt], a0, a1, a2, a3, c0, c1);
            }
        }
        __syncthreads();
        #pragma unroll
        for (int nt = 0; nt < 6; nt++)
            #pragma unroll
            for (int j = 0; j < 2; j++) {
                int row = ar + j * 8;
                int col = ncol + nt * 8 + m2;
                float va0 = accA[nt][j*2]   + b1 [a * HH + col];
                float va1 = accA[nt][j*2+1] + b1 [a * HH + col + 1];
                float vb0 = accB[nt][j*2]   + bs1[a * HH + col];
                float vb1 = accB[nt][j*2+1] + bs1[a * HH + col + 1];
                bufY[row * 196 + col]     = gelu_exact(va0) + vb0;
                bufY[row * 196 + col + 1] = gelu_exact(va1) + vb1;
            }
        __syncthreads();
    }

    // ---------- Layer 2 (A = bufY, out -> bufX); dual weights per stage ----------
    {
        const float* w1g = W2  + a * HH * HH;
        const float* w2g = Ws2 + a * HH * HH;
        #pragma unroll
        for (int j = 0; j < 3; j++) {
            int f = tid + j * 512;
            int k = f / 48, n4 = (f % 48) * 4;
            cpa16(st0 + k * 196 + n4,        w1g + f * 4);
            cpa16(st0 + 6272 + k * 196 + n4, w2g + f * 4);
        }
        cpa_commit();

        float accA[6][4] = {}, accB[6][4] = {};
        #pragma unroll 1
        for (int slab = 0; slab < 6; slab++) {
            if (slab + 1 < 6) {
                float* ns = (slab & 1) ? st0 : st1;
                #pragma unroll
                for (int j = 0; j < 3; j++) {
                    int f = tid + j * 512;
                    int k = f / 48, n4 = (f % 48) * 4;
                    cpa16(ns + k * 196 + n4,        w1g + (slab + 1) * 6144 + f * 4);
                    cpa16(ns + 6272 + k * 196 + n4, w2g + (slab + 1) * 6144 + f * 4);
                }
            }
            cpa_commit();
            cpa_wait<1>();
            __syncthreads();
            float* cw1 = (slab & 1) ? st1 : st0;
            float* cw2 = cw1 + 6272;
            #pragma unroll
            for (int hk = 0; hk < 2; hk++) {
                int k0 = slab * 32 + hk * 16;
                float2 v00 = *(const float2*)(bufY + ar * 196 + k0 + m2);
                float2 v10 = *(const float2*)(bufY + (ar + 8) * 196 + k0 + m2);
                float2 v01 = *(const float2*)(bufY + ar * 196 + k0 + m2 + 8);
                float2 v11 = *(const float2*)(bufY + (ar + 8) * 196 + k0 + m2 + 8);
                uint32_t a0 = pack2h(v00.x, v00.y), a1 = pack2h(v10.x, v10.y);
                uint32_t a2 = pack2h(v01.x, v01.y), a3 = pack2h(v11.x, v11.y);
                int kb = hk * 16 + m2;
                #pragma unroll
                for (int nt = 0; nt < 6; nt++) {
                    int bn = ncol + nt * 8 + q4;
                    uint32_t b0 = pack2h(cw1[kb * 196 + bn],       cw1[(kb + 1) * 196 + bn]);
                    uint32_t b1 = pack2h(cw1[(kb + 8) * 196 + bn], cw1[(kb + 9) * 196 + bn]);
                    mma_f16(accA[nt], a0, a1, a2, a3, b0, b1);
                    uint32_t c0 = pack2h(cw2[kb * 196 + bn],       cw2[(kb + 1) * 196 + bn]);
                    uint32_t c1 = pack2h(cw2[(kb + 8) * 196 + bn], cw2[(kb + 9) * 196 + bn]);
                    mma_f16(accB[nt], a0, a1, a2, a3, c0, c1);
                }
            }
            __syncthreads();
        }
        #pragma unroll
        for (int nt = 0; nt < 6; nt++)
            #pragma unroll
            for (int j = 0; j < 2; j++) {
                int row = ar + j * 8;
                int col = ncol + nt * 8 + m2;
                float va0 = accA[nt][j*2]   + b2 [a * HH + col];
                float va1 = accA[nt][j*2+1] + b2 [a * HH + col + 1];
                float vb0 = accB[nt][j*2]   + bs2[a * HH + col];
                float vb1 = accB[nt][j*2+1] + bs2[a * HH + col + 1];
                bufX[row * 196 + col]     = gelu_exact(va0) + vb0;
                bufX[row * 196 + col + 1] = gelu_exact(va1) + vb1;
            }
        __syncthreads();
    }

    // ---------- Layer 3 (A = bufX = exact h2) + residual + LN + LN ----------
    {
        const float* wg = W3 + a * HH * HH;
        #pragma unroll
        for (int j = 0; j < 3; j++) {
            int f = tid + j * 512;
            int k = f / 48, n4 = (f % 48) * 4;
            cpa16(st0 + k * 196 + n4, wg + f * 4);
        }
        cpa_commit();

        float acc[6][4] = {};
        #pragma unroll 1
        for (int slab = 0; slab < 6; slab++) {
            if (slab + 1 < 6) {
                float* ns = (slab & 1) ? st0 : st1;
                #pragma unroll
                for (int j = 0; j < 3; j++) {
                    int f = tid + j * 512;
                    int k = f / 48, n4 = (f % 48) * 4;
                    cpa16(ns + k * 196 + n4, wg + (slab + 1) * 6144 + f * 4);
                }
            }
            cpa_commit();
            cpa_wait<1>();
            __syncthreads();
            float* cw = (slab & 1) ? st1 : st0;
            #pragma unroll
            for (int hk = 0; hk < 2; hk++) {
                int k0 = slab * 32 + hk * 16;
                float2 v00 = *(const float2*)(bufX + ar * 196 + k0 + m2);
                float2 v10 = *(const float2*)(bufX + (ar + 8) * 196 + k0 + m2);
                float2 v01 = *(const float2*)(bufX + ar * 196 + k0 + m2 + 8);
                float2 v11 = *(const float2*)(bufX + (ar + 8) * 196 + k0 + m2 + 8);
                uint32_t a0 = pack2h(v00.x, v00.y), a1 = pack2h(v10.x, v10.y);
                uint32_t a2 = pack2h(v01.x, v01.y), a3 = pack2h(v11.x, v11.y);
                int kb = hk * 16 + m2;
                #pragma unroll
                for (int nt = 0; nt < 6; nt++) {
                    int bn = ncol + nt * 8 + q4;
                    uint32_t b0 = pack2h(cw[kb * 196 + bn],       cw[(kb + 1) * 196 + bn]);
                    uint32_t b1 = pack2h(cw[(kb + 8) * 196 + bn], cw[(kb + 9) * 196 + bn]);
                    mma_f16(acc[nt], a0, a1, a2, a3, b0, b1);
                }
            }
            __syncthreads();
        }

        float* tbf = wst;
        #pragma unroll
        for (int nt = 0; nt < 6; nt++)
            #pragma unroll
            for (int j = 0; j < 2; j++) {
                int row = ar + j * 8;
                int col = ncol + nt * 8 + m2;
                tbf[row * 196 + col]     = bufX[row * 196 + col]     + acc[nt][j*2]   + b3v[a * HH + col];
                tbf[row * 196 + col + 1] = bufX[row * 196 + col + 1] + acc[nt][j*2+1] + b3v[a * HH + col + 1];
            }
        __syncthreads();

        for (int r = wid; r < BB; r += 16) {
            float v[6];
            #pragma unroll
            for (int u = 0; u < 6; u++) v[u] = tbf[r * 196 + u * 32 + lane];
            float s = 0.f;
            #pragma unroll
            for (int u = 0; u < 6; u++) s += v[u];
            s = warp_sum(s);
            float mu = s * (1.0f / HH);
            float ss = 0.f;
            #pragma unroll
            for (int u = 0; u < 6; u++) { float d = v[u] - mu; ss += d * d; }
            ss = warp_sum(ss);
            float rinv = rsqrtf(ss * (1.0f / HH) + EPSF);

            float h3v[6]; float s2 = 0.f;
            #pragma unroll
            for (int u = 0; u < 6; u++) {
                int i = u * 32 + lane;
                h3v[u] = (v[u] - mu) * rinv * lhg[a * HH + i] + lhb[a * HH + i];
                g_h3[(a * BB + r) * HH + i] = h3v[u];
                s2 += h3v[u];
            }
            s2 = warp_sum(s2);
            float mu2 = s2 * (1.0f / HH);
            float ss2 = 0.f;
            #pragma unroll
            for (int u = 0; u < 6; u++) { float d = h3v[u] - mu2; ss2 += d * d; }
            ss2 = warp_sum(ss2);
            float rinv2 = rsqrtf(ss2 * (1.0f / HH) + EPSF);
            #pragma unroll
            for (int u = 0; u < 6; u++) {
                int i = u * 32 + lane;
                bufY[r * 196 + i] = (h3v[u] - mu2) * rinv2 * alng[i] + alnb[i];
            }
        }
        __syncthreads();
    }

    // ---------- QKV (A = bufY = y), weight tiles 32 x 388 ----------
    {
        int ncolq = (wid >> 2) * 96;
        #pragma unroll
        for (int j = 0; j < 6; j++) {
            int f = tid + j * 512;
            int k = f / 96, n4g = f % 96;
            int mat = n4g / 32, c4 = (n4g % 32) * 4;
            const float* W = (mat == 0) ? Wq : (mat == 1) ? Wk : Wv;
            cpa16(st0 + k * 388 + n4g * 4, W + k * AD + c4);
        }
        cpa_commit();

        float acc[12][4] = {};
        #pragma unroll 1
        for (int slab = 0; slab < 6; slab++) {
            if (slab + 1 < 6) {
                float* ns = (slab & 1) ? st0 : st1;
                #pragma unroll
                for (int j = 0; j < 6; j++) {
                    int f = tid + j * 512;
                    int k = f / 96, n4g = f % 96;
                    int mat = n4g / 32, c4 = (n4g % 32) * 4;
                    const float* W = (mat == 0) ? Wq : (mat == 1) ? Wk : Wv;
                    cpa16(ns + k * 388 + n4g * 4, W + ((slab + 1) * 32 + k) * AD + c4);
                }
            }
            cpa_commit();
            cpa_wait<1>();
            __syncthreads();
            float* ws = (slab & 1) ? st1 : st0;
            #pragma unroll
            for (int hk = 0; hk < 2; hk++) {
                int k0 = slab * 32 + hk * 16;
                float2 v00 = *(const float2*)(bufY + ar * 196 + k0 + m2);
                float2 v10 = *(const float2*)(bufY + (ar + 8) * 196 + k0 + m2);
                float2 v01 = *(const float2*)(bufY + ar * 196 + k0 + m2 + 8);
                float2 v11 = *(const float2*)(bufY + (ar + 8) * 196 + k0 + m2 + 8);
                uint32_t a0 = pack2h(v00.x, v00.y), a1 = pack2h(v10.x, v10.y);
                uint32_t a2 = pack2h(v01.x, v01.y), a3 = pack2h(v11.x, v11.y);
                int kb = hk * 16 + m2;
                #pragma unroll
                for (int nt = 0; nt < 12; nt++) {
                    int bn = ncolq + nt * 8 + q4;
                    uint32_t b0 = pack2h(ws[kb * 388 + bn],       ws[(kb + 1) * 388 + bn]);
                    uint32_t b1 = pack2h(ws[(kb + 8) * 388 + bn], ws[(kb + 9) * 388 + bn]);
                    mma_f16(acc[nt], a0, a1, a2, a3, b0, b1);
                }
            }
            __syncthreads();
        }

        #pragma unroll
        for (int nt = 0; nt < 12; nt++)
            #pragma unroll
            for (int i = 0; i < 4; i++) {
                int row = ar + (i >> 1) * 8;
                int col = ncolq + nt * 8 + m2 + (i & 1);
                float val = acc[nt][i];
                __half* dst; int c;
                if (col < 128)      { val = (val + bq[col]) * 0.25f; c = col;       dst = g_qh; }
                else if (col < 256) { val = val + bk[col - 128];     c = col - 128; dst = g_kh; }
                else                { val = val + bv[col - 256];     c = col - 256; dst = g_vh; }
                dst[(((row * NHD) + (c >> 4)) * AA + a) * HDD + (c & 15)] = __float2half_rn(val);
            }
    }
}

// ---------------- K5: flash attention over agents, fp16 mma ----------------
template<int NTS>
__device__ __forceinline__ void attn_chunk(int jbase, const __half* ks, const __half* vt,
                                           uint32_t qa0, uint32_t qa1, uint32_t qa2, uint32_t qa3,
                                           float* m, float* l, float* o0, float* o1, int lane) {
    float sc[NTS][4];
    #pragma unroll
    for (int nt = 0; nt < NTS; nt++) { sc[nt][0] = sc[nt][1] = sc[nt][2] = sc[nt][3] = 0.f; }
    #pragma unroll
    for (int nt = 0; nt < NTS; nt++) {
        const __half* bp = ks + (jbase + nt * 8 + (lane >> 2)) * 16 + 2 * (lane & 3);
        uint32_t b0 = *(const uint32_t*)bp;
        uint32_t b1 = *(const uint32_t*)(bp + 8);
        mma_f16(sc[nt], qa0, qa1, qa2, qa3, b0, b1);
    }
    float mx0 = -1e30f, mx1 = -1e30f;
    #pragma unroll
    for (int nt = 0; nt < NTS; nt++) {
        mx0 = fmaxf(mx0, fmaxf(sc[nt][0], sc[nt][1]));
        mx1 = fmaxf(mx1, fmaxf(sc[nt][2], sc[nt][3]));
    }
    mx0 = fmaxf(mx0, __shfl_xor_sync(0xffffffffu, mx0, 1));
    mx0 = fmaxf(mx0, __shfl_xor_sync(0xffffffffu, mx0, 2));
    mx1 = fmaxf(mx1, __shfl_xor_sync(0xffffffffu, mx1, 1));
    mx1 = fmaxf(mx1, __shfl_xor_sync(0xffffffffu, mx1, 2));
    float mn0 = fmaxf(m[0], mx0), mn1 = fmaxf(m[1], mx1);
    float f0 = __expf(m[0] - mn0), f1 = __expf(m[1] - mn1);
    float p[NTS][4];
    float sum0 = 0.f, sum1 = 0.f;
    #pragma unroll
    for (int nt = 0; nt < NTS; nt++) {
        p[nt][0] = __expf(sc[nt][0] - mn0);
        p[nt][1] = __expf(sc[nt][1] - mn0);
        p[nt][2] = __expf(sc[nt][2] - mn1);
        p[nt][3] = __expf(sc[nt][3] - mn1);
        sum0 += p[nt][0] + p[nt][1];
        sum1 += p[nt][2] + p[nt][3];
    }
    sum0 += __shfl_xor_sync(0xffffffffu, sum0, 1);
    sum0 += __shfl_xor_sync(0xffffffffu, sum0, 2);
    sum1 += __shfl_xor_sync(0xffffffffu, sum1, 1);
    sum1 += __shfl_xor_sync(0xffffffffu, sum1, 2);
    l[0] = l[0] * f0 + sum0;
    l[1] = l[1] * f1 + sum1;
    o0[0] *= f0; o0[1] *= f0; o0[2] *= f1; o0[3] *= f1;
    o1[0] *= f0; o1[1] *= f0; o1[2] *= f1; o1[3] *= f1;
    m[0] = mn0; m[1] = mn1;
    #pragma unroll
    for (int s = 0; s < NTS / 2; s++) {
        uint32_t pa0 = pack2h(p[2*s][0],   p[2*s][1]);
        uint32_t pa1 = pack2h(p[2*s][2],   p[2*s][3]);
        uint32_t pa2 = pack2h(p[2*s+1][0], p[2*s+1][1]);
        uint32_t pa3 = pack2h(p[2*s+1][2], p[2*s+1][3]);
        #pragma unroll
        for (int d = 0; d < 2; d++) {
            const __half* bp = vt + (d * 8 + (lane >> 2)) * 456 + jbase + 16 * s + 2 * (lane & 3);
            uint32_t b0 = *(const uint32_t*)bp;
            uint32_t b1 = *(const uint32_t*)(bp + 8);
            mma_f16(d ? o1 : o0, pa0, pa1, pa2, pa3, b0, b1);
        }
    }
}

__global__ void __launch_bounds__(128) k5_attn() {
    int bh = blockIdx.x;
    int tid = threadIdx.x, lane = tid & 31, wid = tid >> 5;
    extern __shared__ __half smh[];
    __half* qs = smh;                 // 448 x 16
    __half* ks = smh + 448 * 16;      // 400 x 16
    __half* vt = ks + 400 * 16;       // 16 x 456 (transposed V)

    const __half* qg = g_qh + bh * AA * HDD;
    const __half* kg = g_kh + bh * AA * HDD;
    const __half* vg = g_vh + bh * AA * HDD;

    {
        uint4* qd = (uint4*)qs; const uint4* qsrc = (const uint4*)qg;
        for (int i = tid; i < 800; i += 128) qd[i] = qsrc[i];
        uint4 z; z.x = z.y = z.z = z.w = 0u;
        for (int i = tid; i < 96; i += 128) qd[800 + i] = z;
        uint4* kd = (uint4*)ks; const uint4* ksrc = (const uint4*)kg;
        for (int i = tid; i < 800; i += 128) kd[i] = ksrc[i];
        const __half2* vsrc = (const __half2*)vg;
        for (int i = tid; i < 3200; i += 128) {
            int ag = i >> 3, dd = i & 7;
            __half2 h = vsrc[i];
            vt[(2 * dd) * 456 + ag]     = __low2half(h);
            vt[(2 * dd + 1) * 456 + ag] = __high2half(h);
        }
    }
    __syncthreads();

    for (int p = 0; p < 7; p++) {
        int mrow = p * 64 + wid * 16;
        int r = mrow + (lane >> 2);
        const __half* qp = qs + r * 16 + 2 * (lane & 3);
        uint32_t qa0 = *(const uint32_t*)qp;
        uint32_t qa1 = *(const uint32_t*)(qp + 8 * 16);
        uint32_t qa2 = *(const uint32_t*)(qp + 8);
        uint32_t qa3 = *(const uint32_t*)(qp + 8 * 16 + 8);
        float m[2] = {-1e30f, -1e30f}, l[2] = {0.f, 0.f};
        float o0[4] = {0.f, 0.f, 0.f, 0.f}, o1[4] = {0.f, 0.f, 0.f, 0.f};
        #pragma unroll 1
        for (int c = 0; c < 6; c++)
            attn_chunk<8>(c * 64, ks, vt, qa0, qa1, qa2, qa3, m, l, o0, o1, lane);
        attn_chunk<2>(384, ks, vt, qa0, qa1, qa2, qa3, m, l, o0, o1, lane);

        float i0 = 1.0f / l[0], i1 = 1.0f / l[1];
        int row0 = mrow + (lane >> 2), row1 = row0 + 8;
        int colb = (lane & 3) * 2;
        if (row0 < AA) {
            float* op = g_o + (bh * AA + row0) * HDD;
            op[colb] = o0[0] * i0; op[colb + 1] = o0[1] * i0;
            op[8 + colb] = o1[0] * i0; op[8 + colb + 1] = o1[1] * i0;
        }
        if (row1 < AA) {
            float* op = g_o + (bh * AA + row1) * HDD;
            op[colb] = o0[2] * i1; op[colb + 1] = o0[3] * i1;
            op[8 + colb] = o1[2] * i1; op[8 + colb + 1] = o1[3] * i1;
        }
    }
}

// ---------------- K6: O-proj (slab-pipelined Wo) + residual + output head ----------------
__global__ void __launch_bounds__(512) k6_out(
        const float* __restrict__ Wo,   const float* __restrict__ bo,
        const float* __restrict__ Wout, const float* __restrict__ bout,
        float* __restrict__ out) {
    int a = blockIdx.x;
    extern __shared__ float sm[];
    float* smA = sm;                      // 64 x 132 (raw o); reused for Wout copy
    float* wst = sm + 64 * 132;           // 2 stages x 32 x 200; reused as att 64x192
    float* st0 = wst;
    float* st1 = wst + 6400;
    int tid = threadIdx.x, lane = tid & 31, wid = tid >> 5;
    int mrow = (wid & 3) * 16, ncol = (wid >> 2) * 48;

    #pragma unroll
    for (int j = 0; j < 4; j++) {
        int f = tid + j * 512;
        int b = f >> 5, c4 = f & 31;
        int head = c4 >> 2, d4 = (c4 & 3) * 4;
        cpa16(smA + b * 132 + c4 * 4, g_o + (((b * NHD) + head) * AA + a) * HDD + d4);
    }
    #pragma unroll
    for (int j = 0; j < 3; j++) {
        int f = tid + j * 512;
        int k = f / 48, n4 = (f % 48) * 4;
        cpa16(st0 + k * 200 + n4, Wo + f * 4);
    }
    cpa_commit();

    float acc[6][4] = {};
    #pragma unroll 1
    for (int slab = 0; slab < 4; slab++) {
        if (slab + 1 < 4) {
            float* ns = (slab & 1) ? st0 : st1;
            #pragma unroll
            for (int j = 0; j < 3; j++) {
                int f = tid + j * 512;
                int k = f / 48, n4 = (f % 48) * 4;
                cpa16(ns + k * 200 + n4, Wo + (slab + 1) * 6144 + f * 4);
            }
        }
        cpa_commit();
        cpa_wait<1>();
        __syncthreads();
        float* cw = (slab & 1) ? st1 : st0;
        #pragma unroll
        for (int ks = 0; ks < 4; ks++) {
            int k0 = ks * 8;
            int ar = mrow + (lane >> 2);
            int ac = slab * 32 + k0 + (lane & 3);
            uint32_t a0 = tfbits(smA[ar * 132 + ac]);
            uint32_t a1 = tfbits(smA[(ar + 8) * 132 + ac]);
            uint32_t a2 = tfbits(smA[ar * 132 + ac + 4]);
            uint32_t a3 = tfbits(smA[(ar + 8) * 132 + ac + 4]);
            #pragma unroll
            for (int nt = 0; nt < 6; nt++) {
                int bo2 = (k0 + (lane & 3)) * 200 + ncol + nt * 8 + (lane >> 2);
                mma_tf32(acc[nt], a0, a1, a2, a3, tfbits(cw[bo2]), tfbits(cw[bo2 + 4 * 200]));
            }
        }
        __syncthreads();
    }

    float* att = wst;
    #pragma unroll
    for (int nt = 0; nt < 6; nt++)
        #pragma unroll
        for (int j = 0; j < 2; j++) {
            int row = mrow + (lane >> 2) + j * 8;
            int col = ncol + nt * 8 + (lane & 3) * 2;
            float2 h3v = *(const float2*)(g_h3 + (a * BB + row) * HH + col);
            att[row * HH + col]     = h3v.x + acc[nt][j*2]   + bo[col];
            att[row * HH + col + 1] = h3v.y + acc[nt][j*2+1] + bo[col + 1];
        }
    float* wout = smA;
    if (tid < 144) {
        *(float4*)(wout + tid * 4) = *(const float4*)(Wout + a * HH * OO + tid * 4);
    }
    __syncthreads();

    for (int t = wid; t < BB * OO; t += 16) {
        int b = t / OO, oo = t - b * OO;
        float partial = 0.f;
        #pragma unroll
        for (int u = 0; u < 6; u++) {
            int k = u * 32 + lane;
            partial = fmaf(att[b * HH + k], wout[k * OO + oo], partial);
        }
        partial = warp_sum(partial);
        if (lane == 0) out[(a * BB + b) * OO + oo] = partial + bout[a * OO + oo];
    }
}

// ---------------- host launcher ----------------
extern "C" void kernel_launch(void* const* d_in, const int* in_sizes, int n_in,
                              void* d_out, int out_size) {
    const float* x       = (const float*)d_in[0];
    const float* ln_in_g = (const float*)d_in[1];
    const float* ln_in_b = (const float*)d_in[2];
    const float* W1   = (const float*)d_in[3];
    const float* b1   = (const float*)d_in[4];
    const float* Ws1  = (const float*)d_in[5];
    const float* bs1  = (const float*)d_in[6];
    const float* W2   = (const float*)d_in[7];
    const float* b2   = (const float*)d_in[8];
    const float* Ws2  = (const float*)d_in[9];
    const float* bs2  = (const float*)d_in[10];
    const float* W3   = (const float*)d_in[11];
    const float* b3   = (const float*)d_in[12];
    const float* ln_h_g = (const float*)d_in[13];
    const float* ln_h_b = (const float*)d_in[14];
    const float* Wout = (const float*)d_in[15];
    const float* bout = (const float*)d_in[16];
    const float* aln_g = (const float*)d_in[17];
    const float* aln_b = (const float*)d_in[18];
    const float* Wq = (const float*)d_in[19];
    const float* bq = (const float*)d_in[20];
    const float* Wk = (const float*)d_in[21];
    const float* bk = (const float*)d_in[22];
    const float* Wv = (const float*)d_in[23];
    const float* bv = (const float*)d_in[24];
    const float* Wo = (const float*)d_in[25];
    const float* bo = (const float*)d_in[26];
    float* out = (float*)d_out;

    const int SMF = (12544 + 12544 + 2 * 12800) * 4;     // 202752 B
    const int SM5 = (448 * 16 + 400 * 16 + 16 * 456) * 2;
    const int SM6 = (64 * 132 + 2 * 32 * 200) * 4;       // 84992 B -> 2 CTAs/SM

    cudaFuncSetAttribute(kf_mlp,  cudaFuncAttributeMaxDynamicSharedMemorySize, SMF);
    cudaFuncSetAttribute(k5_attn, cudaFuncAttributeMaxDynamicSharedMemorySize, SM5);
    cudaFuncSetAttribute(k6_out,  cudaFuncAttributeMaxDynamicSharedMemorySize, SM6);

    k0_xhat<<<1, 64>>>(x);
    kf_mlp <<<AA, 512, SMF>>>(ln_in_g, ln_in_b, W1, b1, Ws1, bs1,
                              W2, b2, Ws2, bs2, W3, b3,
                              ln_h_g, ln_h_b, aln_g, aln_b,
                              Wq, bq, Wk, bk, Wv, bv);
    k5_attn<<<BB * NHD, 128, SM5>>>();
    k6_out <<<AA, 512, SM6>>>(Wo, bo, Wout, bout, out);
}